// round 2
// baseline (speedup 1.0000x reference)
#include <cuda_runtime.h>
#include <math.h>

#define IMG   128
#define NPIX  16384      // 128*128
#define NIMG  40         // B*T images per camera
#define BB    4
#define TT    10
#define SS    6
#define AA    6
#define HID   512
#define LL    6
#define NCH   16

// ---------------- scratch (static device allocations; no cudaMalloc) ----------------
__device__ float g_bufA[(size_t)NIMG * 128 * NPIX];   // up to 128 channels
__device__ float g_bufB[(size_t)NIMG * 64  * NPIX];   // up to 64 channels
__device__ float g_img [BB * TT * 64];                // fused image features
__device__ float g_h0[LL * BB * HID];
__device__ float g_h1[LL * BB * HID];
__device__ float g_c0[LL * BB * HID];
__device__ float g_c1[LL * BB * HID];

// ---------------- 3x3 SAME conv + bias + relu ----------------
// block = 128 threads (4 warps). warp handles one image row (32 lanes x 4 px).
// each thread: 8 output channels x 4 pixels.
// grid = (32 row-groups, Cout/8, N)
__global__ void conv3x3_relu_kernel(const float* __restrict__ in,
                                    const float* __restrict__ w,
                                    const float* __restrict__ bias,
                                    float* __restrict__ out,
                                    int Cin, int Cout) {
    extern __shared__ float sw[];   // [Cin*9][8] -> (ic*9+k)*8 + o
    const int tid  = threadIdx.x;
    const int lane = tid & 31;
    const int warp = tid >> 5;
    const int ocg  = blockIdx.y;
    const int n    = blockIdx.z;

    // stage weights for this oc-group into smem
    const int nw = Cin * 72;
    const float* wbase = w + (size_t)ocg * 8 * Cin * 9;
    for (int i = tid; i < nw; i += blockDim.x) {
        int o = i & 7, rest = i >> 3;            // rest = ic*9 + k
        sw[i] = wbase[(size_t)o * Cin * 9 + rest];
    }
    __syncthreads();

    const int y  = blockIdx.x * 4 + warp;
    const int x0 = lane * 4;

    float acc[8][4];
    #pragma unroll
    for (int o = 0; o < 8; o++) {
        float bv = bias[ocg * 8 + o];
        #pragma unroll
        for (int p = 0; p < 4; p++) acc[o][p] = bv;
    }

    for (int ic = 0; ic < Cin; ic++) {
        const float* ip = in + (size_t)(n * Cin + ic) * NPIX;
        float v[3][6];
        #pragma unroll
        for (int r = 0; r < 3; r++) {
            int yy = y - 1 + r;
            float4 m = make_float4(0.f, 0.f, 0.f, 0.f);
            if (yy >= 0 && yy < IMG)
                m = *reinterpret_cast<const float4*>(ip + yy * IMG + x0);
            float left  = __shfl_up_sync(0xffffffffu, m.w, 1);
            float right = __shfl_down_sync(0xffffffffu, m.x, 1);
            if (lane == 0)  left  = 0.f;
            if (lane == 31) right = 0.f;
            v[r][0] = left; v[r][1] = m.x; v[r][2] = m.y;
            v[r][3] = m.z;  v[r][4] = m.w; v[r][5] = right;
        }
        const float* wp = sw + ic * 72;
        #pragma unroll
        for (int ky = 0; ky < 3; ky++)
        #pragma unroll
        for (int kx = 0; kx < 3; kx++) {
            const float* wq = wp + (ky * 3 + kx) * 8;
            #pragma unroll
            for (int o = 0; o < 8; o++) {
                float wv = wq[o];
                #pragma unroll
                for (int p = 0; p < 4; p++)
                    acc[o][p] = fmaf(v[ky][kx + p], wv, acc[o][p]);
            }
        }
    }

    #pragma unroll
    for (int o = 0; o < 8; o++) {
        float4 r;
        r.x = fmaxf(acc[o][0], 0.f);
        r.y = fmaxf(acc[o][1], 0.f);
        r.z = fmaxf(acc[o][2], 0.f);
        r.w = fmaxf(acc[o][3], 0.f);
        *reinterpret_cast<float4*>(
            out + (size_t)(n * Cout + ocg * 8 + o) * NPIX + y * IMG + x0) = r;
    }
}

// ---------------- spatial softmax: (N,16,128,128) -> 2 expectations per channel ----------------
// grid = (16, N), block = 256
__global__ void spatial_softmax_kernel(const float* __restrict__ x,
                                       float* __restrict__ img, int base) {
    const int ch = blockIdx.x;
    const int n  = blockIdx.y;
    const float* p = x + (size_t)(n * NCH + ch) * NPIX;
    __shared__ float r1[256], r2[256], r3[256];
    const int tid = threadIdx.x;

    float m = -1e30f;
    for (int i = tid; i < NPIX; i += 256) m = fmaxf(m, p[i]);
    r1[tid] = m; __syncthreads();
    for (int s = 128; s > 0; s >>= 1) {
        if (tid < s) r1[tid] = fmaxf(r1[tid], r1[tid + s]);
        __syncthreads();
    }
    m = r1[0];
    __syncthreads();

    float s = 0.f, sx = 0.f, sy = 0.f;
    for (int i = tid; i < NPIX; i += 256) {
        float e = expf(p[i] - m);
        int yy = i >> 7, xx = i & 127;
        float px = -1.f + (2.f / 127.f) * (float)xx;
        float py = -1.f + (2.f / 127.f) * (float)yy;
        s += e; sx += e * px; sy += e * py;
    }
    r1[tid] = s; r2[tid] = sx; r3[tid] = sy; __syncthreads();
    for (int st = 128; st > 0; st >>= 1) {
        if (tid < st) {
            r1[tid] += r1[tid + st];
            r2[tid] += r2[tid + st];
            r3[tid] += r3[tid + st];
        }
        __syncthreads();
    }
    if (tid == 0) {
        float inv = 1.f / r1[0];
        img[n * 64 + base + 2 * ch]     = r2[0] * inv;
        img[n * 64 + base + 2 * ch + 1] = r3[0] * inv;
    }
}

// ---------------- fused LSTM cell: gates GEMV + nonlinearity + state update ----------------
// grid = 64 blocks, block = 256 (8 warps). warp -> hidden unit j, all 4 gates x 4 batches.
__global__ void lstm_cell_kernel(const float* __restrict__ x1, int d1, int x1_bs,
                                 const float* __restrict__ x2, int d2, int x2_bs,
                                 const float* __restrict__ hprev,
                                 const float* __restrict__ cprev,
                                 const float* __restrict__ wih,
                                 const float* __restrict__ whh,
                                 const float* __restrict__ bih,
                                 const float* __restrict__ bhh,
                                 float* __restrict__ hout,
                                 float* __restrict__ cout) {
    __shared__ float sx[BB * 576];
    __shared__ float sh[BB * HID];
    const int d   = d1 + d2;
    const int tid = threadIdx.x;

    for (int i = tid; i < BB * d; i += blockDim.x) {
        int b = i / d, k = i - b * d;
        sx[i] = (k < d1) ? x1[b * x1_bs + k] : x2[b * x2_bs + (k - d1)];
    }
    for (int i = tid; i < BB * HID; i += blockDim.x) sh[i] = hprev[i];
    __syncthreads();

    const int lane = tid & 31;
    const int j    = blockIdx.x * 8 + (tid >> 5);

    float acc[4][4];
    #pragma unroll
    for (int G = 0; G < 4; G++)
        #pragma unroll
        for (int b = 0; b < 4; b++) acc[G][b] = 0.f;

    #pragma unroll
    for (int G = 0; G < 4; G++) {
        const float* wr = wih + (size_t)(G * HID + j) * d;
        for (int k = lane; k < d; k += 32) {
            float wv = wr[k];
            #pragma unroll
            for (int b = 0; b < 4; b++)
                acc[G][b] = fmaf(sx[b * d + k], wv, acc[G][b]);
        }
        const float* w2 = whh + (size_t)(G * HID + j) * HID;
        for (int k = lane; k < HID; k += 32) {
            float wv = w2[k];
            #pragma unroll
            for (int b = 0; b < 4; b++)
                acc[G][b] = fmaf(sh[b * HID + k], wv, acc[G][b]);
        }
    }
    #pragma unroll
    for (int G = 0; G < 4; G++)
        #pragma unroll
        for (int b = 0; b < 4; b++) {
            #pragma unroll
            for (int off = 16; off > 0; off >>= 1)
                acc[G][b] += __shfl_xor_sync(0xffffffffu, acc[G][b], off);
        }

    if (lane < 4) {
        int b = lane;
        float gi = acc[0][b] + bih[j]           + bhh[j];
        float gf = acc[1][b] + bih[HID + j]     + bhh[HID + j];
        float gg = acc[2][b] + bih[2 * HID + j] + bhh[2 * HID + j];
        float go = acc[3][b] + bih[3 * HID + j] + bhh[3 * HID + j];
        float si = 1.f / (1.f + expf(-gi));
        float sf = 1.f / (1.f + expf(-gf));
        float tg = tanhf(gg);
        float so = 1.f / (1.f + expf(-go));
        float c2 = sf * cprev[b * HID + j] + si * tg;
        float h2 = so * tanhf(c2);
        hout[b * HID + j] = h2;
        cout[b * HID + j] = c2;
    }
}

// ---------------- output projection: out[b,t,:] = [h5, img] @ out_w.T + out_b ----------------
// 1 block, 768 threads = 24 warps = (b,a) pairs
__global__ void out_proj_kernel(const float* __restrict__ h,
                                const float* __restrict__ imgf,
                                const float* __restrict__ out_w,
                                const float* __restrict__ out_b,
                                float* __restrict__ out, int t) {
    const int wid  = threadIdx.x >> 5;
    const int lane = threadIdx.x & 31;
    if (wid >= BB * AA) return;
    const int b = wid / AA, a = wid % AA;
    const float* row = out_w + a * 576;
    float acc = 0.f;
    for (int k = lane; k < 576; k += 32) {
        float x = (k < HID) ? h[b * HID + k] : imgf[(b * TT + t) * 64 + (k - HID)];
        acc = fmaf(row[k], x, acc);
    }
    #pragma unroll
    for (int off = 16; off > 0; off >>= 1)
        acc += __shfl_xor_sync(0xffffffffu, acc, off);
    if (lane == 0) out[(b * TT + t) * AA + a] = acc + out_b[a];
}

// ---------------- host orchestration ----------------
extern "C" void kernel_launch(void* const* d_in, const int* in_sizes, int n_in,
                              void* d_out, int out_size) {
    (void)in_sizes; (void)n_in; (void)out_size;

    const float* im_m   = (const float*)d_in[0];
    const float* im_s   = (const float*)d_in[1];
    const float* states = (const float*)d_in[2];
    const float* cw[2][4] = {
        {(const float*)d_in[3],  (const float*)d_in[5],  (const float*)d_in[7],  (const float*)d_in[9]},
        {(const float*)d_in[11], (const float*)d_in[13], (const float*)d_in[15], (const float*)d_in[17]}};
    const float* cb[2][4] = {
        {(const float*)d_in[4],  (const float*)d_in[6],  (const float*)d_in[8],  (const float*)d_in[10]},
        {(const float*)d_in[12], (const float*)d_in[14], (const float*)d_in[16], (const float*)d_in[18]}};
    const float* wih0  = (const float*)d_in[19];
    const float* whh0  = (const float*)d_in[20];
    const float* bih0  = (const float*)d_in[21];
    const float* bhh0  = (const float*)d_in[22];
    const float* wih_r = (const float*)d_in[23];
    const float* whh_r = (const float*)d_in[24];
    const float* bih_r = (const float*)d_in[25];
    const float* bhh_r = (const float*)d_in[26];
    const float* out_w = (const float*)d_in[27];
    const float* out_b = (const float*)d_in[28];
    float* out = (float*)d_out;

    float *bufA, *bufB, *imgf, *h0, *h1, *c0, *c1;
    cudaGetSymbolAddress((void**)&bufA, g_bufA);
    cudaGetSymbolAddress((void**)&bufB, g_bufB);
    cudaGetSymbolAddress((void**)&imgf, g_img);
    cudaGetSymbolAddress((void**)&h0,   g_h0);
    cudaGetSymbolAddress((void**)&h1,   g_h1);
    cudaGetSymbolAddress((void**)&c0,   g_c0);
    cudaGetSymbolAddress((void**)&c1,   g_c1);

    // ---- CNN towers + spatial softmax ----
    for (int cam = 0; cam < 2; cam++) {
        const float* src = cam ? im_s : im_m;
        conv3x3_relu_kernel<<<dim3(32, 4, NIMG),  128, 3   * 72 * 4>>>(src,  cw[cam][0], cb[cam][0], bufA, 3,   32);
        conv3x3_relu_kernel<<<dim3(32, 8, NIMG),  128, 32  * 72 * 4>>>(bufA, cw[cam][1], cb[cam][1], bufB, 32,  64);
        conv3x3_relu_kernel<<<dim3(32, 16, NIMG), 128, 64  * 72 * 4>>>(bufB, cw[cam][2], cb[cam][2], bufA, 64,  128);
        conv3x3_relu_kernel<<<dim3(32, 2, NIMG),  128, 128 * 72 * 4>>>(bufA, cw[cam][3], cb[cam][3], bufB, 128, 16);
        spatial_softmax_kernel<<<dim3(NCH, NIMG), 256>>>(bufB, imgf, cam ? 32 : 0);
    }

    // ---- LSTM ----
    cudaMemsetAsync(h0, 0, (size_t)LL * BB * HID * sizeof(float));
    cudaMemsetAsync(c0, 0, (size_t)LL * BB * HID * sizeof(float));

    for (int t = 0; t < TT; t++) {
        float* hp = (t & 1) ? h1 : h0;
        float* hc = (t & 1) ? h0 : h1;
        float* cp = (t & 1) ? c1 : c0;
        float* cc = (t & 1) ? c0 : c1;
        for (int l = 0; l < LL; l++) {
            const float *x1, *wi, *wh, *bi, *bh;
            int d1, bs1;
            if (l == 0) {
                x1 = states + t * SS; d1 = SS; bs1 = TT * SS;
                wi = wih0; wh = whh0; bi = bih0; bh = bhh0;
            } else {
                x1 = hc + (size_t)(l - 1) * BB * HID; d1 = HID; bs1 = HID;
                wi = wih_r + (size_t)(l - 1) * 4 * HID * 576;
                wh = whh_r + (size_t)(l - 1) * 4 * HID * HID;
                bi = bih_r + (size_t)(l - 1) * 4 * HID;
                bh = bhh_r + (size_t)(l - 1) * 4 * HID;
            }
            lstm_cell_kernel<<<64, 256>>>(
                x1, d1, bs1,
                imgf + t * 64, 64, TT * 64,
                hp + (size_t)l * BB * HID, cp + (size_t)l * BB * HID,
                wi, wh, bi, bh,
                hc + (size_t)l * BB * HID, cc + (size_t)l * BB * HID);
        }
        out_proj_kernel<<<1, 768>>>(hc + (size_t)5 * BB * HID, imgf, out_w, out_b, out, t);
    }
}

// round 3
// speedup vs baseline: 1.0017x; 1.0017x over previous
#include <cuda_runtime.h>
#include <math.h>

#define IMG   128
#define NPIX  16384      // 128*128
#define NIMG  40         // B*T images per camera
#define BB    4
#define TT    10
#define SS    6
#define AA    6
#define HID   512
#define LL    6
#define NCH   16

// ---------------- scratch (static device allocations; no cudaMalloc) ----------------
__device__ float g_bufA[(size_t)NIMG * 128 * NPIX];   // up to 128 channels
__device__ float g_bufB[(size_t)NIMG * 64  * NPIX];   // up to 64 channels
__device__ float g_img [BB * TT * 64];                // fused image features
__device__ float g_h0[LL * BB * HID];
__device__ float g_h1[LL * BB * HID];
__device__ float g_c0[LL * BB * HID];
__device__ float g_c1[LL * BB * HID];

// ---------------- 3x3 SAME conv + bias + relu ----------------
// block = 128 threads (4 warps). warp handles one image row (32 lanes x 4 px).
// each thread: 8 output channels x 4 pixels.
// grid = (32 row-groups, Cout/8, N)
__global__ void conv3x3_relu_kernel(const float* __restrict__ in,
                                    const float* __restrict__ w,
                                    const float* __restrict__ bias,
                                    float* __restrict__ out,
                                    int Cin, int Cout) {
    extern __shared__ float sw[];   // [Cin*9][8] -> (ic*9+k)*8 + o
    const int tid  = threadIdx.x;
    const int lane = tid & 31;
    const int warp = tid >> 5;
    const int ocg  = blockIdx.y;
    const int n    = blockIdx.z;

    // stage weights for this oc-group into smem
    const int nw = Cin * 72;
    const float* wbase = w + (size_t)ocg * 8 * Cin * 9;
    for (int i = tid; i < nw; i += blockDim.x) {
        int o = i & 7, rest = i >> 3;            // rest = ic*9 + k
        sw[i] = wbase[(size_t)o * Cin * 9 + rest];
    }
    __syncthreads();

    const int y  = blockIdx.x * 4 + warp;
    const int x0 = lane * 4;

    float acc[8][4];
    #pragma unroll
    for (int o = 0; o < 8; o++) {
        float bv = bias[ocg * 8 + o];
        #pragma unroll
        for (int p = 0; p < 4; p++) acc[o][p] = bv;
    }

    for (int ic = 0; ic < Cin; ic++) {
        const float* ip = in + (size_t)(n * Cin + ic) * NPIX;
        float v[3][6];
        #pragma unroll
        for (int r = 0; r < 3; r++) {
            int yy = y - 1 + r;
            float4 m = make_float4(0.f, 0.f, 0.f, 0.f);
            if (yy >= 0 && yy < IMG)
                m = *reinterpret_cast<const float4*>(ip + yy * IMG + x0);
            float left  = __shfl_up_sync(0xffffffffu, m.w, 1);
            float right = __shfl_down_sync(0xffffffffu, m.x, 1);
            if (lane == 0)  left  = 0.f;
            if (lane == 31) right = 0.f;
            v[r][0] = left; v[r][1] = m.x; v[r][2] = m.y;
            v[r][3] = m.z;  v[r][4] = m.w; v[r][5] = right;
        }
        const float* wp = sw + ic * 72;
        #pragma unroll
        for (int ky = 0; ky < 3; ky++)
        #pragma unroll
        for (int kx = 0; kx < 3; kx++) {
            const float* wq = wp + (ky * 3 + kx) * 8;
            #pragma unroll
            for (int o = 0; o < 8; o++) {
                float wv = wq[o];
                #pragma unroll
                for (int p = 0; p < 4; p++)
                    acc[o][p] = fmaf(v[ky][kx + p], wv, acc[o][p]);
            }
        }
    }

    #pragma unroll
    for (int o = 0; o < 8; o++) {
        float4 r;
        r.x = fmaxf(acc[o][0], 0.f);
        r.y = fmaxf(acc[o][1], 0.f);
        r.z = fmaxf(acc[o][2], 0.f);
        r.w = fmaxf(acc[o][3], 0.f);
        *reinterpret_cast<float4*>(
            out + (size_t)(n * Cout + ocg * 8 + o) * NPIX + y * IMG + x0) = r;
    }
}

// ---------------- spatial softmax: (N,16,128,128) -> 2 expectations per channel ----------------
// grid = (16, N), block = 256
__global__ void spatial_softmax_kernel(const float* __restrict__ x,
                                       float* __restrict__ img, int base) {
    const int ch = blockIdx.x;
    const int n  = blockIdx.y;
    const float* p = x + (size_t)(n * NCH + ch) * NPIX;
    __shared__ float r1[256], r2[256], r3[256];
    const int tid = threadIdx.x;

    float m = -1e30f;
    for (int i = tid; i < NPIX; i += 256) m = fmaxf(m, p[i]);
    r1[tid] = m; __syncthreads();
    for (int s = 128; s > 0; s >>= 1) {
        if (tid < s) r1[tid] = fmaxf(r1[tid], r1[tid + s]);
        __syncthreads();
    }
    m = r1[0];
    __syncthreads();

    float s = 0.f, sx = 0.f, sy = 0.f;
    for (int i = tid; i < NPIX; i += 256) {
        float e = expf(p[i] - m);
        int yy = i >> 7, xx = i & 127;
        float px = -1.f + (2.f / 127.f) * (float)xx;
        float py = -1.f + (2.f / 127.f) * (float)yy;
        s += e; sx += e * px; sy += e * py;
    }
    r1[tid] = s; r2[tid] = sx; r3[tid] = sy; __syncthreads();
    for (int st = 128; st > 0; st >>= 1) {
        if (tid < st) {
            r1[tid] += r1[tid + st];
            r2[tid] += r2[tid + st];
            r3[tid] += r3[tid + st];
        }
        __syncthreads();
    }
    if (tid == 0) {
        float inv = 1.f / r1[0];
        img[n * 64 + base + 2 * ch]     = r2[0] * inv;
        img[n * 64 + base + 2 * ch + 1] = r3[0] * inv;
    }
}

// ---------------- fused LSTM cell: gates GEMV + nonlinearity + state update ----------------
// grid = 64 blocks, block = 256 (8 warps). warp -> hidden unit j, all 4 gates x 4 batches.
__global__ void lstm_cell_kernel(const float* __restrict__ x1, int d1, int x1_bs,
                                 const float* __restrict__ x2, int d2, int x2_bs,
                                 const float* __restrict__ hprev,
                                 const float* __restrict__ cprev,
                                 const float* __restrict__ wih,
                                 const float* __restrict__ whh,
                                 const float* __restrict__ bih,
                                 const float* __restrict__ bhh,
                                 float* __restrict__ hout,
                                 float* __restrict__ cout) {
    __shared__ float sx[BB * 576];
    __shared__ float sh[BB * HID];
    const int d   = d1 + d2;
    const int tid = threadIdx.x;

    for (int i = tid; i < BB * d; i += blockDim.x) {
        int b = i / d, k = i - b * d;
        sx[i] = (k < d1) ? x1[b * x1_bs + k] : x2[b * x2_bs + (k - d1)];
    }
    for (int i = tid; i < BB * HID; i += blockDim.x) sh[i] = hprev[i];
    __syncthreads();

    const int lane = tid & 31;
    const int j    = blockIdx.x * 8 + (tid >> 5);

    float acc[4][4];
    #pragma unroll
    for (int G = 0; G < 4; G++)
        #pragma unroll
        for (int b = 0; b < 4; b++) acc[G][b] = 0.f;

    #pragma unroll
    for (int G = 0; G < 4; G++) {
        const float* wr = wih + (size_t)(G * HID + j) * d;
        for (int k = lane; k < d; k += 32) {
            float wv = wr[k];
            #pragma unroll
            for (int b = 0; b < 4; b++)
                acc[G][b] = fmaf(sx[b * d + k], wv, acc[G][b]);
        }
        const float* w2 = whh + (size_t)(G * HID + j) * HID;
        for (int k = lane; k < HID; k += 32) {
            float wv = w2[k];
            #pragma unroll
            for (int b = 0; b < 4; b++)
                acc[G][b] = fmaf(sh[b * HID + k], wv, acc[G][b]);
        }
    }
    #pragma unroll
    for (int G = 0; G < 4; G++)
        #pragma unroll
        for (int b = 0; b < 4; b++) {
            #pragma unroll
            for (int off = 16; off > 0; off >>= 1)
                acc[G][b] += __shfl_xor_sync(0xffffffffu, acc[G][b], off);
        }

    if (lane < 4) {
        int b = lane;
        float gi = acc[0][b] + bih[j]           + bhh[j];
        float gf = acc[1][b] + bih[HID + j]     + bhh[HID + j];
        float gg = acc[2][b] + bih[2 * HID + j] + bhh[2 * HID + j];
        float go = acc[3][b] + bih[3 * HID + j] + bhh[3 * HID + j];
        float si = 1.f / (1.f + expf(-gi));
        float sf = 1.f / (1.f + expf(-gf));
        float tg = tanhf(gg);
        float so = 1.f / (1.f + expf(-go));
        float c2 = sf * cprev[b * HID + j] + si * tg;
        float h2 = so * tanhf(c2);
        hout[b * HID + j] = h2;
        cout[b * HID + j] = c2;
    }
}

// ---------------- output projection: out[b,t,:] = [h5, img] @ out_w.T + out_b ----------------
// 1 block, 768 threads = 24 warps = (b,a) pairs
__global__ void out_proj_kernel(const float* __restrict__ h,
                                const float* __restrict__ imgf,
                                const float* __restrict__ out_w,
                                const float* __restrict__ out_b,
                                float* __restrict__ out, int t) {
    const int wid  = threadIdx.x >> 5;
    const int lane = threadIdx.x & 31;
    if (wid >= BB * AA) return;
    const int b = wid / AA, a = wid % AA;
    const float* row = out_w + a * 576;
    float acc = 0.f;
    for (int k = lane; k < 576; k += 32) {
        float x = (k < HID) ? h[b * HID + k] : imgf[(b * TT + t) * 64 + (k - HID)];
        acc = fmaf(row[k], x, acc);
    }
    #pragma unroll
    for (int off = 16; off > 0; off >>= 1)
        acc += __shfl_xor_sync(0xffffffffu, acc, off);
    if (lane == 0) out[(b * TT + t) * AA + a] = acc + out_b[a];
}

// ---------------- host orchestration ----------------
extern "C" void kernel_launch(void* const* d_in, const int* in_sizes, int n_in,
                              void* d_out, int out_size) {
    (void)in_sizes; (void)n_in; (void)out_size;

    const float* im_m   = (const float*)d_in[0];
    const float* im_s   = (const float*)d_in[1];
    const float* states = (const float*)d_in[2];
    const float* cw[2][4] = {
        {(const float*)d_in[3],  (const float*)d_in[5],  (const float*)d_in[7],  (const float*)d_in[9]},
        {(const float*)d_in[11], (const float*)d_in[13], (const float*)d_in[15], (const float*)d_in[17]}};
    const float* cb[2][4] = {
        {(const float*)d_in[4],  (const float*)d_in[6],  (const float*)d_in[8],  (const float*)d_in[10]},
        {(const float*)d_in[12], (const float*)d_in[14], (const float*)d_in[16], (const float*)d_in[18]}};
    const float* wih0  = (const float*)d_in[19];
    const float* whh0  = (const float*)d_in[20];
    const float* bih0  = (const float*)d_in[21];
    const float* bhh0  = (const float*)d_in[22];
    const float* wih_r = (const float*)d_in[23];
    const float* whh_r = (const float*)d_in[24];
    const float* bih_r = (const float*)d_in[25];
    const float* bhh_r = (const float*)d_in[26];
    const float* out_w = (const float*)d_in[27];
    const float* out_b = (const float*)d_in[28];
    float* out = (float*)d_out;

    float *bufA, *bufB, *imgf, *h0, *h1, *c0, *c1;
    cudaGetSymbolAddress((void**)&bufA, g_bufA);
    cudaGetSymbolAddress((void**)&bufB, g_bufB);
    cudaGetSymbolAddress((void**)&imgf, g_img);
    cudaGetSymbolAddress((void**)&h0,   g_h0);
    cudaGetSymbolAddress((void**)&h1,   g_h1);
    cudaGetSymbolAddress((void**)&c0,   g_c0);
    cudaGetSymbolAddress((void**)&c1,   g_c1);

    // ---- CNN towers + spatial softmax ----
    for (int cam = 0; cam < 2; cam++) {
        const float* src = cam ? im_s : im_m;
        conv3x3_relu_kernel<<<dim3(32, 4, NIMG),  128, 3   * 72 * 4>>>(src,  cw[cam][0], cb[cam][0], bufA, 3,   32);
        conv3x3_relu_kernel<<<dim3(32, 8, NIMG),  128, 32  * 72 * 4>>>(bufA, cw[cam][1], cb[cam][1], bufB, 32,  64);
        conv3x3_relu_kernel<<<dim3(32, 16, NIMG), 128, 64  * 72 * 4>>>(bufB, cw[cam][2], cb[cam][2], bufA, 64,  128);
        conv3x3_relu_kernel<<<dim3(32, 2, NIMG),  128, 128 * 72 * 4>>>(bufA, cw[cam][3], cb[cam][3], bufB, 128, 16);
        spatial_softmax_kernel<<<dim3(NCH, NIMG), 256>>>(bufB, imgf, cam ? 32 : 0);
    }

    // ---- LSTM ----
    cudaMemsetAsync(h0, 0, (size_t)LL * BB * HID * sizeof(float));
    cudaMemsetAsync(c0, 0, (size_t)LL * BB * HID * sizeof(float));

    for (int t = 0; t < TT; t++) {
        float* hp = (t & 1) ? h1 : h0;
        float* hc = (t & 1) ? h0 : h1;
        float* cp = (t & 1) ? c1 : c0;
        float* cc = (t & 1) ? c0 : c1;
        for (int l = 0; l < LL; l++) {
            const float *x1, *wi, *wh, *bi, *bh;
            int d1, bs1;
            if (l == 0) {
                x1 = states + t * SS; d1 = SS; bs1 = TT * SS;
                wi = wih0; wh = whh0; bi = bih0; bh = bhh0;
            } else {
                x1 = hc + (size_t)(l - 1) * BB * HID; d1 = HID; bs1 = HID;
                wi = wih_r + (size_t)(l - 1) * 4 * HID * 576;
                wh = whh_r + (size_t)(l - 1) * 4 * HID * HID;
                bi = bih_r + (size_t)(l - 1) * 4 * HID;
                bh = bhh_r + (size_t)(l - 1) * 4 * HID;
            }
            lstm_cell_kernel<<<64, 256>>>(
                x1, d1, bs1,
                imgf + t * 64, 64, TT * 64,
                hp + (size_t)l * BB * HID, cp + (size_t)l * BB * HID,
                wi, wh, bi, bh,
                hc + (size_t)l * BB * HID, cc + (size_t)l * BB * HID);
        }
        out_proj_kernel<<<1, 768>>>(hc + (size_t)5 * BB * HID, imgf, out_w, out_b, out, t);
    }
}

// round 5
// speedup vs baseline: 1.0611x; 1.0593x over previous
#include <cuda_runtime.h>
#include <math.h>
#include <stdint.h>

#define IMG   128
#define NPIX  16384
#define NIMG  40
#define BB    4
#define TT    10
#define SS    6
#define AA    6
#define HID   512
#define LL    6
#define NCH   16

// ---------------- scratch ----------------
__device__ float g_bufA[(size_t)NIMG * 128 * NPIX];
__device__ float g_bufB[(size_t)NIMG * 64  * NPIX];
__device__ float g_img [BB * TT * 64];
__device__ float g_h0[LL * BB * HID];
__device__ float g_h1[LL * BB * HID];
__device__ float g_c0[LL * BB * HID];
__device__ float g_c1[LL * BB * HID];
// k-major tf32 weights per cam: L2 288x64, L3 576x128, L4 1152x16
__device__ float g_wt[2 * (288 * 64 + 576 * 128 + 1152 * 16)];

__device__ __forceinline__ float tf32r(float x) {
    uint32_t u;
    asm("cvt.rna.tf32.f32 %0, %1;" : "=r"(u) : "f"(x));
    return __uint_as_float(u);
}

__device__ __forceinline__ void mma_tf32(float* d,
                                         uint32_t a0, uint32_t a1, uint32_t a2, uint32_t a3,
                                         uint32_t b0, uint32_t b1) {
    asm volatile(
        "mma.sync.aligned.m16n8k8.row.col.f32.tf32.tf32.f32 "
        "{%0,%1,%2,%3}, {%4,%5,%6,%7}, {%8,%9}, {%0,%1,%2,%3};"
        : "+f"(d[0]), "+f"(d[1]), "+f"(d[2]), "+f"(d[3])
        : "r"(a0), "r"(a1), "r"(a2), "r"(a3), "r"(b0), "r"(b1));
}

// ================ weight transform: [oc][ic][3][3] -> k-major Wt[k][oc], tf32 ================
// k = (ky*3+kx)*Cin + ic
__global__ void wt_transform_kernel(const float* __restrict__ w, float* __restrict__ wt,
                                    int Cin, int Cout) {
    int idx = blockIdx.x * 256 + threadIdx.x;
    int K = 9 * Cin;
    if (idx >= K * Cout) return;
    int k = idx / Cout, oc = idx - (idx / Cout) * Cout;
    int kykx = k / Cin, ic = k - kykx * Cin;
    wt[idx] = tf32r(w[(oc * Cin + ic) * 9 + kykx]);
}

// ================ tf32 mma.sync implicit-GEMM 3x3 SAME conv + bias + relu ================
// D[px, oc] = sum_k A[px,k] * Wt[k,oc]
// block = 256 (8 warps). warp tile: 64 px x 16 oc. CTA: (WPX*64) px x (8/WPX*16) oc.
// grid = (128/rows_per_cta, Cout/ocT, NIMG), rows_per_cta = WPX/2.
#define SLABX 130
#define SLABI 10

__global__ void __launch_bounds__(256)
conv_mma_kernel(const float* __restrict__ in, const float* __restrict__ wt,
                const float* __restrict__ bias, float* __restrict__ out,
                int Cin, int Cout, int ocT, int WPX) {
    extern __shared__ float sm[];
    const int tid  = threadIdx.x;
    const int lane = tid & 31;
    const int wid  = tid >> 5;

    const int rows  = WPX >> 1;           // image rows per CTA
    const int slabR = rows + 2;
    const int slabW = slabR * SLABX * SLABI;
    const int SBS   = ocT + 8;            // sB row stride
    float* slab = sm;
    float* sBuf[2] = { sm + slabW, sm + slabW + 8 * SBS };

    const int n   = blockIdx.z;
    const int y0  = blockIdx.x * rows;
    const int oc0 = blockIdx.y * ocT;

    const int wpx = wid % WPX;
    const int woc = wid / WPX;
    const int pxbase = wpx * 64;
    const int ocb    = woc * 16;

    const int kk = lane & 3;              // k-quarter within fragment
    const int qr = lane >> 2;             // row/col-quarter index (0..7)

    float d[4][2][4];
    #pragma unroll
    for (int mf = 0; mf < 4; mf++)
        #pragma unroll
        for (int nf = 0; nf < 2; nf++)
            #pragma unroll
            for (int r = 0; r < 4; r++) d[mf][nf][r] = 0.f;

    const float* inb = in + (size_t)n * Cin * NPIX;
    const int nicb = Cin >> 3;

    for (int icb = 0; icb < nicb; icb++) {
        __syncthreads();   // slab + sB reuse across icb

        // ---- load input slab: slab[r][xs][icpair-interleave], ic pairs (p, p+4) adjacent ----
        {
            const int tot = slabR * 4 * SLABX;
            const float* base = inb + (size_t)(icb * 8) * NPIX;
            for (int i = tid; i < tot; i += 256) {
                int xs = i % SLABX;
                int rp = i / SLABX;
                int r = rp >> 2, p = rp & 3;
                int y = y0 + r - 1;
                int x = xs - 1;
                float v0 = 0.f, v1 = 0.f;
                if (y >= 0 && y < IMG && x >= 0 && x < IMG) {
                    const float* q = base + (size_t)p * NPIX + y * IMG + x;
                    v0 = tf32r(q[0]);
                    v1 = tf32r(q[4 * NPIX]);
                }
                *reinterpret_cast<float2*>(slab + (r * SLABX + xs) * SLABI + 2 * p) =
                    make_float2(v0, v1);
            }
        }

        // ---- stage B chunk 0 of this icb ----
        {
            const float* src = wt + ((size_t)icb * 8) * Cout + oc0;  // kykx=0
            const int tot = 8 * (ocT >> 2);
            const int cpr = ocT >> 2;
            for (int i = tid; i < tot; i += 256) {
                int row = i / cpr, col = (i - row * cpr) * 4;
                float4 v = *reinterpret_cast<const float4*>(src + (size_t)row * Cout + col);
                *reinterpret_cast<float4*>(sBuf[0] + row * SBS + col) = v;
            }
        }
        __syncthreads();

        for (int c = 0; c < 9; c++) {
            // stage next chunk's B into the other buffer (overlaps with mma below)
            if (c < 8) {
                int kbase = (c + 1) * Cin + icb * 8;
                const float* src = wt + (size_t)kbase * Cout + oc0;
                float* buf = sBuf[(c + 1) & 1];
                const int cpr = ocT >> 2;
                const int tot = 8 * cpr;
                for (int i = tid; i < tot; i += 256) {
                    int row = i / cpr, col = (i - row * cpr) * 4;
                    float4 v = *reinterpret_cast<const float4*>(src + (size_t)row * Cout + col);
                    *reinterpret_cast<float4*>(buf + row * SBS + col) = v;
                }
            }

            const int ky = c / 3, kx = c - (c / 3) * 3;
            const float* sb = sBuf[c & 1];

            // B fragments (conflict-free: SBS % 32 == 8)
            const int nn = ocb + qr;
            uint32_t b00 = __float_as_uint(sb[kk * SBS + nn]);
            uint32_t b01 = __float_as_uint(sb[(kk + 4) * SBS + nn]);
            uint32_t b10 = __float_as_uint(sb[kk * SBS + nn + 8]);
            uint32_t b11 = __float_as_uint(sb[(kk + 4) * SBS + nn + 8]);

            #pragma unroll
            for (int mf = 0; mf < 4; mf++) {
                int px = pxbase + mf * 16 + qr;
                int pr = px >> 7, x = px & 127;
                const float* ab = slab + ((pr + ky) * SLABX + x + kx) * SLABI + 2 * kk;
                float2 A0 = *reinterpret_cast<const float2*>(ab);              // rows px
                float2 A1 = *reinterpret_cast<const float2*>(ab + 8 * SLABI);  // rows px+8
                uint32_t a0 = __float_as_uint(A0.x);
                uint32_t a2 = __float_as_uint(A0.y);
                uint32_t a1 = __float_as_uint(A1.x);
                uint32_t a3 = __float_as_uint(A1.y);
                mma_tf32(d[mf][0], a0, a1, a2, a3, b00, b01);
                mma_tf32(d[mf][1], a0, a1, a2, a3, b10, b11);
            }
            __syncthreads();
        }
    }

    // ---- epilogue: bias + relu + store ----
    #pragma unroll
    for (int nf = 0; nf < 2; nf++) {
        int oc = oc0 + ocb + nf * 8 + 2 * kk;
        float bv0 = bias[oc], bv1 = bias[oc + 1];
        #pragma unroll
        for (int mf = 0; mf < 4; mf++) {
            int px = pxbase + mf * 16 + qr;
            int pr = px >> 7, x = px & 127;
            float* o0 = out + ((size_t)(n * Cout + oc)) * NPIX + (y0 + pr) * IMG + x;
            o0[0]            = fmaxf(d[mf][nf][0] + bv0, 0.f);
            o0[NPIX]         = fmaxf(d[mf][nf][1] + bv1, 0.f);
            o0[8]            = fmaxf(d[mf][nf][2] + bv0, 0.f);
            o0[NPIX + 8]     = fmaxf(d[mf][nf][3] + bv1, 0.f);
        }
    }
}

// ---------------- fp32 direct conv (layer 1 only, Cin=3) ----------------
__global__ void conv3x3_relu_kernel(const float* __restrict__ in,
                                    const float* __restrict__ w,
                                    const float* __restrict__ bias,
                                    float* __restrict__ out,
                                    int Cin, int Cout) {
    extern __shared__ float sw[];
    const int tid  = threadIdx.x;
    const int lane = tid & 31;
    const int warp = tid >> 5;
    const int ocg  = blockIdx.y;
    const int n    = blockIdx.z;

    const int nw = Cin * 72;
    const float* wbase = w + (size_t)ocg * 8 * Cin * 9;
    for (int i = tid; i < nw; i += blockDim.x) {
        int o = i & 7, rest = i >> 3;
        sw[i] = wbase[(size_t)o * Cin * 9 + rest];
    }
    __syncthreads();

    const int y  = blockIdx.x * 4 + warp;
    const int x0 = lane * 4;

    float acc[8][4];
    #pragma unroll
    for (int o = 0; o < 8; o++) {
        float bv = bias[ocg * 8 + o];
        #pragma unroll
        for (int p = 0; p < 4; p++) acc[o][p] = bv;
    }

    for (int ic = 0; ic < Cin; ic++) {
        const float* ip = in + (size_t)(n * Cin + ic) * NPIX;
        float v[3][6];
        #pragma unroll
        for (int r = 0; r < 3; r++) {
            int yy = y - 1 + r;
            float4 m = make_float4(0.f, 0.f, 0.f, 0.f);
            if (yy >= 0 && yy < IMG)
                m = *reinterpret_cast<const float4*>(ip + yy * IMG + x0);
            float left  = __shfl_up_sync(0xffffffffu, m.w, 1);
            float right = __shfl_down_sync(0xffffffffu, m.x, 1);
            if (lane == 0)  left  = 0.f;
            if (lane == 31) right = 0.f;
            v[r][0] = left; v[r][1] = m.x; v[r][2] = m.y;
            v[r][3] = m.z;  v[r][4] = m.w; v[r][5] = right;
        }
        const float* wp = sw + ic * 72;
        #pragma unroll
        for (int ky = 0; ky < 3; ky++)
        #pragma unroll
        for (int kx = 0; kx < 3; kx++) {
            const float* wq = wp + (ky * 3 + kx) * 8;
            #pragma unroll
            for (int o = 0; o < 8; o++) {
                float wv = wq[o];
                #pragma unroll
                for (int p = 0; p < 4; p++)
                    acc[o][p] = fmaf(v[ky][kx + p], wv, acc[o][p]);
            }
        }
    }

    #pragma unroll
    for (int o = 0; o < 8; o++) {
        float4 r;
        r.x = fmaxf(acc[o][0], 0.f);
        r.y = fmaxf(acc[o][1], 0.f);
        r.z = fmaxf(acc[o][2], 0.f);
        r.w = fmaxf(acc[o][3], 0.f);
        *reinterpret_cast<float4*>(
            out + (size_t)(n * Cout + ocg * 8 + o) * NPIX + y * IMG + x0) = r;
    }
}

// ---------------- spatial softmax ----------------
__global__ void spatial_softmax_kernel(const float* __restrict__ x,
                                       float* __restrict__ img, int base) {
    const int ch = blockIdx.x;
    const int n  = blockIdx.y;
    const float* p = x + (size_t)(n * NCH + ch) * NPIX;
    __shared__ float r1[256], r2[256], r3[256];
    const int tid = threadIdx.x;

    float m = -1e30f;
    for (int i = tid; i < NPIX; i += 256) m = fmaxf(m, p[i]);
    r1[tid] = m; __syncthreads();
    for (int s = 128; s > 0; s >>= 1) {
        if (tid < s) r1[tid] = fmaxf(r1[tid], r1[tid + s]);
        __syncthreads();
    }
    m = r1[0];
    __syncthreads();

    float s = 0.f, sx = 0.f, sy = 0.f;
    for (int i = tid; i < NPIX; i += 256) {
        float e = expf(p[i] - m);
        int yy = i >> 7, xx = i & 127;
        float px = -1.f + (2.f / 127.f) * (float)xx;
        float py = -1.f + (2.f / 127.f) * (float)yy;
        s += e; sx += e * px; sy += e * py;
    }
    r1[tid] = s; r2[tid] = sx; r3[tid] = sy; __syncthreads();
    for (int st = 128; st > 0; st >>= 1) {
        if (tid < st) {
            r1[tid] += r1[tid + st];
            r2[tid] += r2[tid + st];
            r3[tid] += r3[tid + st];
        }
        __syncthreads();
    }
    if (tid == 0) {
        float inv = 1.f / r1[0];
        img[n * 64 + base + 2 * ch]     = r2[0] * inv;
        img[n * 64 + base + 2 * ch + 1] = r3[0] * inv;
    }
}

// ---------------- fused LSTM cell ----------------
__global__ void lstm_cell_kernel(const float* __restrict__ x1, int d1, int x1_bs,
                                 const float* __restrict__ x2, int d2, int x2_bs,
                                 const float* __restrict__ hprev,
                                 const float* __restrict__ cprev,
                                 const float* __restrict__ wih,
                                 const float* __restrict__ whh,
                                 const float* __restrict__ bih,
                                 const float* __restrict__ bhh,
                                 float* __restrict__ hout,
                                 float* __restrict__ cout) {
    __shared__ float sx[BB * 576];
    __shared__ float sh[BB * HID];
    const int d   = d1 + d2;
    const int tid = threadIdx.x;

    for (int i = tid; i < BB * d; i += blockDim.x) {
        int b = i / d, k = i - b * d;
        sx[i] = (k < d1) ? x1[b * x1_bs + k] : x2[b * x2_bs + (k - d1)];
    }
    for (int i = tid; i < BB * HID; i += blockDim.x) sh[i] = hprev[i];
    __syncthreads();

    const int lane = tid & 31;
    const int j    = blockIdx.x * 8 + (tid >> 5);

    float acc[4][4];
    #pragma unroll
    for (int G = 0; G < 4; G++)
        #pragma unroll
        for (int b = 0; b < 4; b++) acc[G][b] = 0.f;

    #pragma unroll
    for (int G = 0; G < 4; G++) {
        const float* wr = wih + (size_t)(G * HID + j) * d;
        for (int k = lane; k < d; k += 32) {
            float wv = wr[k];
            #pragma unroll
            for (int b = 0; b < 4; b++)
                acc[G][b] = fmaf(sx[b * d + k], wv, acc[G][b]);
        }
        const float* w2 = whh + (size_t)(G * HID + j) * HID;
        for (int k = lane; k < HID; k += 32) {
            float wv = w2[k];
            #pragma unroll
            for (int b = 0; b < 4; b++)
                acc[G][b] = fmaf(sh[b * HID + k], wv, acc[G][b]);
        }
    }
    #pragma unroll
    for (int G = 0; G < 4; G++)
        #pragma unroll
        for (int b = 0; b < 4; b++) {
            #pragma unroll
            for (int off = 16; off > 0; off >>= 1)
                acc[G][b] += __shfl_xor_sync(0xffffffffu, acc[G][b], off);
        }

    if (lane < 4) {
        int b = lane;
        float gi = acc[0][b] + bih[j]           + bhh[j];
        float gf = acc[1][b] + bih[HID + j]     + bhh[HID + j];
        float gg = acc[2][b] + bih[2 * HID + j] + bhh[2 * HID + j];
        float go = acc[3][b] + bih[3 * HID + j] + bhh[3 * HID + j];
        float si = 1.f / (1.f + expf(-gi));
        float sf = 1.f / (1.f + expf(-gf));
        float tg = tanhf(gg);
        float so = 1.f / (1.f + expf(-go));
        float c2 = sf * cprev[b * HID + j] + si * tg;
        float h2 = so * tanhf(c2);
        hout[b * HID + j] = h2;
        cout[b * HID + j] = c2;
    }
}

// ---------------- output projection ----------------
__global__ void out_proj_kernel(const float* __restrict__ h,
                                const float* __restrict__ imgf,
                                const float* __restrict__ out_w,
                                const float* __restrict__ out_b,
                                float* __restrict__ out, int t) {
    const int wid  = threadIdx.x >> 5;
    const int lane = threadIdx.x & 31;
    if (wid >= BB * AA) return;
    const int b = wid / AA, a = wid % AA;
    const float* row = out_w + a * 576;
    float acc = 0.f;
    for (int k = lane; k < 576; k += 32) {
        float x = (k < HID) ? h[b * HID + k] : imgf[(b * TT + t) * 64 + (k - HID)];
        acc = fmaf(row[k], x, acc);
    }
    #pragma unroll
    for (int off = 16; off > 0; off >>= 1)
        acc += __shfl_xor_sync(0xffffffffu, acc, off);
    if (lane == 0) out[(b * TT + t) * AA + a] = acc + out_b[a];
}

// ---------------- host orchestration ----------------
extern "C" void kernel_launch(void* const* d_in, const int* in_sizes, int n_in,
                              void* d_out, int out_size) {
    (void)in_sizes; (void)n_in; (void)out_size;

    const float* im_m   = (const float*)d_in[0];
    const float* im_s   = (const float*)d_in[1];
    const float* states = (const float*)d_in[2];
    const float* cw[2][4] = {
        {(const float*)d_in[3],  (const float*)d_in[5],  (const float*)d_in[7],  (const float*)d_in[9]},
        {(const float*)d_in[11], (const float*)d_in[13], (const float*)d_in[15], (const float*)d_in[17]}};
    const float* cb[2][4] = {
        {(const float*)d_in[4],  (const float*)d_in[6],  (const float*)d_in[8],  (const float*)d_in[10]},
        {(const float*)d_in[12], (const float*)d_in[14], (const float*)d_in[16], (const float*)d_in[18]}};
    const float* wih0  = (const float*)d_in[19];
    const float* whh0  = (const float*)d_in[20];
    const float* bih0  = (const float*)d_in[21];
    const float* bhh0  = (const float*)d_in[22];
    const float* wih_r = (const float*)d_in[23];
    const float* whh_r = (const float*)d_in[24];
    const float* bih_r = (const float*)d_in[25];
    const float* bhh_r = (const float*)d_in[26];
    const float* out_w = (const float*)d_in[27];
    const float* out_b = (const float*)d_in[28];
    float* out = (float*)d_out;

    float *bufA, *bufB, *imgf, *h0, *h1, *c0, *c1, *wt;
    cudaGetSymbolAddress((void**)&bufA, g_bufA);
    cudaGetSymbolAddress((void**)&bufB, g_bufB);
    cudaGetSymbolAddress((void**)&imgf, g_img);
    cudaGetSymbolAddress((void**)&h0,   g_h0);
    cudaGetSymbolAddress((void**)&h1,   g_h1);
    cudaGetSymbolAddress((void**)&c0,   g_c0);
    cudaGetSymbolAddress((void**)&c1,   g_c1);
    cudaGetSymbolAddress((void**)&wt,   g_wt);

    // per-cam transformed weights: L2 288*64, L3 576*128, L4 1152*16
    const size_t szL2 = 288 * 64, szL3 = 576 * 128, szL4 = 1152 * 16;
    const size_t camw = szL2 + szL3 + szL4;

    // dynamic smem: slab (rows+2)*130*10 + 2*8*(ocT+8) floats
    const int SMEM_L23 = (3 * SLABX * SLABI + 2 * 8 * (64 + 8)) * 4;   // 20208 B
    const int SMEM_L4  = (6 * SLABX * SLABI + 2 * 8 * (16 + 8)) * 4;   // 32736 B

    for (int cam = 0; cam < 2; cam++) {
        const float* src = cam ? im_s : im_m;
        float* wt2 = wt + cam * camw;
        float* wt3 = wt2 + szL2;
        float* wt4 = wt3 + szL3;

        wt_transform_kernel<<<(int)((szL2 + 255) / 256), 256>>>(cw[cam][1], wt2, 32,  64);
        wt_transform_kernel<<<(int)((szL3 + 255) / 256), 256>>>(cw[cam][2], wt3, 64,  128);
        wt_transform_kernel<<<(int)((szL4 + 255) / 256), 256>>>(cw[cam][3], wt4, 128, 16);

        conv3x3_relu_kernel<<<dim3(32, 4, NIMG), 128, 3 * 72 * 4>>>(src, cw[cam][0], cb[cam][0], bufA, 3, 32);

        // L2: Cin=32, Cout=64, ocT=64, WPX=2 -> CTA 128px x 64oc, 1 row
        conv_mma_kernel<<<dim3(128, 1, NIMG), 256, SMEM_L23>>>(bufA, wt2, cb[cam][1], bufB, 32, 64, 64, 2);
        // L3: Cin=64, Cout=128, ocT=64, WPX=2
        conv_mma_kernel<<<dim3(128, 2, NIMG), 256, SMEM_L23>>>(bufB, wt3, cb[cam][2], bufA, 64, 128, 64, 2);
        // L4: Cin=128, Cout=16, ocT=16, WPX=8 -> CTA 512px x 16oc, 4 rows
        conv_mma_kernel<<<dim3(32, 1, NIMG), 256, SMEM_L4>>>(bufA, wt4, cb[cam][3], bufB, 128, 16, 16, 8);

        spatial_softmax_kernel<<<dim3(NCH, NIMG), 256>>>(bufB, imgf, cam ? 32 : 0);
    }

    // ---- LSTM ----
    cudaMemsetAsync(h0, 0, (size_t)LL * BB * HID * sizeof(float));
    cudaMemsetAsync(c0, 0, (size_t)LL * BB * HID * sizeof(float));

    for (int t = 0; t < TT; t++) {
        float* hp = (t & 1) ? h1 : h0;
        float* hc = (t & 1) ? h0 : h1;
        float* cp = (t & 1) ? c1 : c0;
        float* cc = (t & 1) ? c0 : c1;
        for (int l = 0; l < LL; l++) {
            const float *x1, *wi, *wh, *bi, *bh;
            int d1, bs1;
            if (l == 0) {
                x1 = states + t * SS; d1 = SS; bs1 = TT * SS;
                wi = wih0; wh = whh0; bi = bih0; bh = bhh0;
            } else {
                x1 = hc + (size_t)(l - 1) * BB * HID; d1 = HID; bs1 = HID;
                wi = wih_r + (size_t)(l - 1) * 4 * HID * 576;
                wh = whh_r + (size_t)(l - 1) * 4 * HID * HID;
                bi = bih_r + (size_t)(l - 1) * 4 * HID;
                bh = bhh_r + (size_t)(l - 1) * 4 * HID;
            }
            lstm_cell_kernel<<<64, 256>>>(
                x1, d1, bs1,
                imgf + t * 64, 64, TT * 64,
                hp + (size_t)l * BB * HID, cp + (size_t)l * BB * HID,
                wi, wh, bi, bh,
                hc + (size_t)l * BB * HID, cc + (size_t)l * BB * HID);
        }
        out_proj_kernel<<<1, 768>>>(hc + (size_t)5 * BB * HID, imgf, out_w, out_b, out, t);
    }
}

// round 6
// speedup vs baseline: 1.5028x; 1.4163x over previous
#include <cuda_runtime.h>
#include <math.h>
#include <stdint.h>

#define IMG   128
#define NPIX  16384
#define NIMG  40
#define BB    4
#define TT    10
#define SS    6
#define AA    6
#define HID   512
#define LL    6
#define NCH   16

// ---------------- scratch ----------------
__device__ float g_bufA[(size_t)NIMG * 128 * NPIX];
__device__ float g_bufB[(size_t)NIMG * 64  * NPIX];
__device__ float g_img [BB * TT * 64];
__device__ float g_h0[LL * BB * HID];
__device__ float g_h1[LL * BB * HID];
__device__ float g_c0[LL * BB * HID];
__device__ float g_c1[LL * BB * HID];
// k-major tf32 weights per cam: L2 288x64, L3 576x128, L4 1152x16
__device__ float g_wt[2 * (288 * 64 + 576 * 128 + 1152 * 16)];

__device__ __forceinline__ float tf32r(float x) {
    uint32_t u;
    asm("cvt.rna.tf32.f32 %0, %1;" : "=r"(u) : "f"(x));
    return __uint_as_float(u);
}

__device__ __forceinline__ void mma_tf32(float* d,
                                         uint32_t a0, uint32_t a1, uint32_t a2, uint32_t a3,
                                         uint32_t b0, uint32_t b1) {
    asm volatile(
        "mma.sync.aligned.m16n8k8.row.col.f32.tf32.tf32.f32 "
        "{%0,%1,%2,%3}, {%4,%5,%6,%7}, {%8,%9}, {%0,%1,%2,%3};"
        : "+f"(d[0]), "+f"(d[1]), "+f"(d[2]), "+f"(d[3])
        : "r"(a0), "r"(a1), "r"(a2), "r"(a3), "r"(b0), "r"(b1));
}

// ================ weight transform: [oc][ic][3][3] -> k-major Wt[k][oc], tf32 ================
__global__ void wt_transform_kernel(const float* __restrict__ w, float* __restrict__ wt,
                                    int Cin, int Cout) {
    int idx = blockIdx.x * 256 + threadIdx.x;
    int K = 9 * Cin;
    if (idx >= K * Cout) return;
    int k = idx / Cout, oc = idx - (idx / Cout) * Cout;
    int kykx = k / Cin, ic = k - kykx * Cin;
    wt[idx] = tf32r(w[(oc * Cin + ic) * 9 + kykx]);
}

// ================ tf32 mma.sync implicit-GEMM 3x3 SAME conv + bias + relu ================
// D[px, oc] = sum_k A[px,k] * Wt[k,oc]
// block = 256 (8 warps). warp tile: 64 px x 16 oc.
// Per ic-block of 8 channels: stage input slab + ALL 9 (ky,kx) B chunks, then 72 k8-steps
// with no intervening barriers (2 syncthreads per ic-block total).
#define SLABX 130
#define SLABI 10

__global__ void __launch_bounds__(256)
conv_mma_kernel(const float* __restrict__ in, const float* __restrict__ wt,
                const float* __restrict__ bias, float* __restrict__ out,
                int Cin, int Cout, int ocT, int WPX) {
    extern __shared__ float sm[];
    const int tid  = threadIdx.x;
    const int lane = tid & 31;
    const int wid  = tid >> 5;

    const int rows  = WPX >> 1;           // image rows per CTA
    const int slabR = rows + 2;
    const int slabW = slabR * SLABX * SLABI;
    const int SBS   = ocT + 8;            // sB row stride (72 or 24)
    float* slab = sm;
    float* sB   = sm + slabW;             // [72][SBS] : row = c*8 + r

    const int n   = blockIdx.z;
    const int y0  = blockIdx.x * rows;
    const int oc0 = blockIdx.y * ocT;

    const int wpx = wid % WPX;
    const int woc = wid / WPX;
    const int pxbase = wpx * 64;
    const int ocb    = woc * 16;

    const int kk = lane & 3;
    const int qr = lane >> 2;

    float d[4][2][4];
    #pragma unroll
    for (int mf = 0; mf < 4; mf++)
        #pragma unroll
        for (int nf = 0; nf < 2; nf++)
            #pragma unroll
            for (int r = 0; r < 4; r++) d[mf][nf][r] = 0.f;

    const float* inb = in + (size_t)n * Cin * NPIX;
    const int nicb = Cin >> 3;
    const int cpr  = ocT >> 2;

    for (int icb = 0; icb < nicb; icb++) {
        __syncthreads();   // protect slab/sB from overwrite while prior mma reads pending

        // ---- input slab: slab[r][xs][ic-interleave], ic pairs (p, p+4) adjacent ----
        {
            const int tot = slabR * 4 * SLABX;
            const float* base = inb + (size_t)(icb * 8) * NPIX;
            for (int i = tid; i < tot; i += 256) {
                int xs = i % SLABX;
                int rp = i / SLABX;
                int r = rp >> 2, p = rp & 3;
                int y = y0 + r - 1;
                int x = xs - 1;
                float v0 = 0.f, v1 = 0.f;
                if (y >= 0 && y < IMG && x >= 0 && x < IMG) {
                    const float* q = base + (size_t)p * NPIX + y * IMG + x;
                    v0 = tf32r(q[0]);
                    v1 = tf32r(q[4 * NPIX]);
                }
                *reinterpret_cast<float2*>(slab + (r * SLABX + xs) * SLABI + 2 * p) =
                    make_float2(v0, v1);
            }
        }

        // ---- stage all 9 B chunks: sB[c*8 + r][oc], k = c*Cin + icb*8 + r ----
        {
            const int tot = 72 * cpr;
            for (int i = tid; i < tot; i += 256) {
                int rowg = i / cpr, col = (i - rowg * cpr) * 4;
                int c = rowg >> 3, r = rowg & 7;
                int k = c * Cin + icb * 8 + r;
                float4 v = *reinterpret_cast<const float4*>(wt + (size_t)k * Cout + oc0 + col);
                *reinterpret_cast<float4*>(sB + rowg * SBS + col) = v;
            }
        }
        __syncthreads();

        #pragma unroll
        for (int c = 0; c < 9; c++) {
            const int ky = c / 3, kx = c - (c / 3) * 3;
            const float* sb = sB + (c * 8) * SBS;

            const int nn = ocb + qr;
            uint32_t b00 = __float_as_uint(sb[kk * SBS + nn]);
            uint32_t b01 = __float_as_uint(sb[(kk + 4) * SBS + nn]);
            uint32_t b10 = __float_as_uint(sb[kk * SBS + nn + 8]);
            uint32_t b11 = __float_as_uint(sb[(kk + 4) * SBS + nn + 8]);

            #pragma unroll
            for (int mf = 0; mf < 4; mf++) {
                int px = pxbase + mf * 16 + qr;
                int pr = px >> 7, x = px & 127;
                const float* ab = slab + ((pr + ky) * SLABX + x + kx) * SLABI + 2 * kk;
                float2 A0 = *reinterpret_cast<const float2*>(ab);
                float2 A1 = *reinterpret_cast<const float2*>(ab + 8 * SLABI);
                uint32_t a0 = __float_as_uint(A0.x);
                uint32_t a2 = __float_as_uint(A0.y);
                uint32_t a1 = __float_as_uint(A1.x);
                uint32_t a3 = __float_as_uint(A1.y);
                mma_tf32(d[mf][0], a0, a1, a2, a3, b00, b01);
                mma_tf32(d[mf][1], a0, a1, a2, a3, b10, b11);
            }
        }
    }

    // ---- epilogue: bias + relu + store ----
    #pragma unroll
    for (int nf = 0; nf < 2; nf++) {
        int oc = oc0 + ocb + nf * 8 + 2 * kk;
        float bv0 = bias[oc], bv1 = bias[oc + 1];
        #pragma unroll
        for (int mf = 0; mf < 4; mf++) {
            int px = pxbase + mf * 16 + qr;
            int pr = px >> 7, x = px & 127;
            float* o0 = out + ((size_t)(n * Cout + oc)) * NPIX + (y0 + pr) * IMG + x;
            o0[0]        = fmaxf(d[mf][nf][0] + bv0, 0.f);
            o0[NPIX]     = fmaxf(d[mf][nf][1] + bv1, 0.f);
            o0[8]        = fmaxf(d[mf][nf][2] + bv0, 0.f);
            o0[NPIX + 8] = fmaxf(d[mf][nf][3] + bv1, 0.f);
        }
    }
}

// ---------------- fp32 direct conv (layer 1 only, Cin=3) ----------------
__global__ void conv3x3_relu_kernel(const float* __restrict__ in,
                                    const float* __restrict__ w,
                                    const float* __restrict__ bias,
                                    float* __restrict__ out,
                                    int Cin, int Cout) {
    extern __shared__ float sw[];
    const int tid  = threadIdx.x;
    const int lane = tid & 31;
    const int warp = tid >> 5;
    const int ocg  = blockIdx.y;
    const int n    = blockIdx.z;

    const int nw = Cin * 72;
    const float* wbase = w + (size_t)ocg * 8 * Cin * 9;
    for (int i = tid; i < nw; i += blockDim.x) {
        int o = i & 7, rest = i >> 3;
        sw[i] = wbase[(size_t)o * Cin * 9 + rest];
    }
    __syncthreads();

    const int y  = blockIdx.x * 4 + warp;
    const int x0 = lane * 4;

    float acc[8][4];
    #pragma unroll
    for (int o = 0; o < 8; o++) {
        float bv = bias[ocg * 8 + o];
        #pragma unroll
        for (int p = 0; p < 4; p++) acc[o][p] = bv;
    }

    for (int ic = 0; ic < Cin; ic++) {
        const float* ip = in + (size_t)(n * Cin + ic) * NPIX;
        float v[3][6];
        #pragma unroll
        for (int r = 0; r < 3; r++) {
            int yy = y - 1 + r;
            float4 m = make_float4(0.f, 0.f, 0.f, 0.f);
            if (yy >= 0 && yy < IMG)
                m = *reinterpret_cast<const float4*>(ip + yy * IMG + x0);
            float left  = __shfl_up_sync(0xffffffffu, m.w, 1);
            float right = __shfl_down_sync(0xffffffffu, m.x, 1);
            if (lane == 0)  left  = 0.f;
            if (lane == 31) right = 0.f;
            v[r][0] = left; v[r][1] = m.x; v[r][2] = m.y;
            v[r][3] = m.z;  v[r][4] = m.w; v[r][5] = right;
        }
        const float* wp = sw + ic * 72;
        #pragma unroll
        for (int ky = 0; ky < 3; ky++)
        #pragma unroll
        for (int kx = 0; kx < 3; kx++) {
            const float* wq = wp + (ky * 3 + kx) * 8;
            #pragma unroll
            for (int o = 0; o < 8; o++) {
                float wv = wq[o];
                #pragma unroll
                for (int p = 0; p < 4; p++)
                    acc[o][p] = fmaf(v[ky][kx + p], wv, acc[o][p]);
            }
        }
    }

    #pragma unroll
    for (int o = 0; o < 8; o++) {
        float4 r;
        r.x = fmaxf(acc[o][0], 0.f);
        r.y = fmaxf(acc[o][1], 0.f);
        r.z = fmaxf(acc[o][2], 0.f);
        r.w = fmaxf(acc[o][3], 0.f);
        *reinterpret_cast<float4*>(
            out + (size_t)(n * Cout + ocg * 8 + o) * NPIX + y * IMG + x0) = r;
    }
}

// ---------------- spatial softmax ----------------
__global__ void spatial_softmax_kernel(const float* __restrict__ x,
                                       float* __restrict__ img, int base) {
    const int ch = blockIdx.x;
    const int n  = blockIdx.y;
    const float* p = x + (size_t)(n * NCH + ch) * NPIX;
    __shared__ float r1[256], r2[256], r3[256];
    const int tid = threadIdx.x;

    float m = -1e30f;
    for (int i = tid; i < NPIX; i += 256) m = fmaxf(m, p[i]);
    r1[tid] = m; __syncthreads();
    for (int s = 128; s > 0; s >>= 1) {
        if (tid < s) r1[tid] = fmaxf(r1[tid], r1[tid + s]);
        __syncthreads();
    }
    m = r1[0];
    __syncthreads();

    float s = 0.f, sx = 0.f, sy = 0.f;
    for (int i = tid; i < NPIX; i += 256) {
        float e = expf(p[i] - m);
        int yy = i >> 7, xx = i & 127;
        float px = -1.f + (2.f / 127.f) * (float)xx;
        float py = -1.f + (2.f / 127.f) * (float)yy;
        s += e; sx += e * px; sy += e * py;
    }
    r1[tid] = s; r2[tid] = sx; r3[tid] = sy; __syncthreads();
    for (int st = 128; st > 0; st >>= 1) {
        if (tid < st) {
            r1[tid] += r1[tid + st];
            r2[tid] += r2[tid + st];
            r3[tid] += r3[tid + st];
        }
        __syncthreads();
    }
    if (tid == 0) {
        float inv = 1.f / r1[0];
        img[n * 64 + base + 2 * ch]     = r2[0] * inv;
        img[n * 64 + base + 2 * ch + 1] = r3[0] * inv;
    }
}

// ---------------- fused LSTM cell (wide version) ----------------
// grid = 256 blocks, block = 256 (8 warps). block handles 2 hidden units,
// warp = (unit_local, gate): full 1088-wide dot product for all 4 batches, float4.
__global__ void __launch_bounds__(256)
lstm_cell_kernel(const float* __restrict__ x1, int d1, int x1_bs,
                 const float* __restrict__ x2, int d2, int x2_bs,
                 const float* __restrict__ hprev,
                 const float* __restrict__ cprev,
                 const float* __restrict__ wih,
                 const float* __restrict__ whh,
                 const float* __restrict__ bih,
                 const float* __restrict__ bhh,
                 float* __restrict__ hout,
                 float* __restrict__ cout) {
    __shared__ __align__(16) float sx[BB * 576];
    __shared__ __align__(16) float sh[BB * HID];
    __shared__ float gate[8][4];
    const int d   = d1 + d2;
    const int tid = threadIdx.x;

    for (int i = tid; i < BB * d; i += 256) {
        int b = i / d, k = i - b * d;
        sx[i] = (k < d1) ? x1[b * x1_bs + k] : x2[b * x2_bs + (k - d1)];
    }
    for (int i = tid; i < BB * HID; i += 256) sh[i] = hprev[i];
    __syncthreads();

    const int lane = tid & 31;
    const int w    = tid >> 5;
    const int jl   = w >> 2;              // 0..1 local unit
    const int g    = w & 3;               // gate
    const int j    = blockIdx.x * 2 + jl;

    float acc[4] = {0.f, 0.f, 0.f, 0.f};

    const float* wr = wih + (size_t)(g * HID + j) * d;
    if ((d & 3) == 0) {
        for (int k = lane * 4; k < d; k += 128) {
            float4 wv = *reinterpret_cast<const float4*>(wr + k);
            #pragma unroll
            for (int b = 0; b < 4; b++) {
                float4 xv = *reinterpret_cast<const float4*>(sx + b * d + k);
                acc[b] = fmaf(wv.x, xv.x, acc[b]);
                acc[b] = fmaf(wv.y, xv.y, acc[b]);
                acc[b] = fmaf(wv.z, xv.z, acc[b]);
                acc[b] = fmaf(wv.w, xv.w, acc[b]);
            }
        }
    } else {
        for (int k = lane; k < d; k += 32) {
            float wv = wr[k];
            #pragma unroll
            for (int b = 0; b < 4; b++)
                acc[b] = fmaf(sx[b * d + k], wv, acc[b]);
        }
    }

    const float* w2 = whh + (size_t)(g * HID + j) * HID;
    #pragma unroll
    for (int k4 = 0; k4 < 4; k4++) {
        int k = lane * 4 + k4 * 128;
        float4 wv = *reinterpret_cast<const float4*>(w2 + k);
        #pragma unroll
        for (int b = 0; b < 4; b++) {
            float4 hv = *reinterpret_cast<const float4*>(sh + b * HID + k);
            acc[b] = fmaf(wv.x, hv.x, acc[b]);
            acc[b] = fmaf(wv.y, hv.y, acc[b]);
            acc[b] = fmaf(wv.z, hv.z, acc[b]);
            acc[b] = fmaf(wv.w, hv.w, acc[b]);
        }
    }

    #pragma unroll
    for (int b = 0; b < 4; b++) {
        #pragma unroll
        for (int off = 16; off > 0; off >>= 1)
            acc[b] += __shfl_xor_sync(0xffffffffu, acc[b], off);
    }
    if (lane == 0) {
        gate[w][0] = acc[0]; gate[w][1] = acc[1];
        gate[w][2] = acc[2]; gate[w][3] = acc[3];
    }
    __syncthreads();

    if (tid < 8) {
        int jj = tid >> 2, b = tid & 3;
        int jg = blockIdx.x * 2 + jj;
        float gi = gate[jj * 4 + 0][b] + bih[jg]           + bhh[jg];
        float gf = gate[jj * 4 + 1][b] + bih[HID + jg]     + bhh[HID + jg];
        float gg = gate[jj * 4 + 2][b] + bih[2 * HID + jg] + bhh[2 * HID + jg];
        float go = gate[jj * 4 + 3][b] + bih[3 * HID + jg] + bhh[3 * HID + jg];
        float si = 1.f / (1.f + expf(-gi));
        float sf = 1.f / (1.f + expf(-gf));
        float tg = tanhf(gg);
        float so = 1.f / (1.f + expf(-go));
        float c2 = sf * cprev[b * HID + jg] + si * tg;
        float h2 = so * tanhf(c2);
        hout[b * HID + jg] = h2;
        cout[b * HID + jg] = c2;
    }
}

// ---------------- output projection ----------------
__global__ void out_proj_kernel(const float* __restrict__ h,
                                const float* __restrict__ imgf,
                                const float* __restrict__ out_w,
                                const float* __restrict__ out_b,
                                float* __restrict__ out, int t) {
    const int wid  = threadIdx.x >> 5;
    const int lane = threadIdx.x & 31;
    if (wid >= BB * AA) return;
    const int b = wid / AA, a = wid % AA;
    const float* row = out_w + a * 576;
    float acc = 0.f;
    for (int k = lane; k < 576; k += 32) {
        float x = (k < HID) ? h[b * HID + k] : imgf[(b * TT + t) * 64 + (k - HID)];
        acc = fmaf(row[k], x, acc);
    }
    #pragma unroll
    for (int off = 16; off > 0; off >>= 1)
        acc += __shfl_xor_sync(0xffffffffu, acc, off);
    if (lane == 0) out[(b * TT + t) * AA + a] = acc + out_b[a];
}

// ---------------- host orchestration ----------------
extern "C" void kernel_launch(void* const* d_in, const int* in_sizes, int n_in,
                              void* d_out, int out_size) {
    (void)in_sizes; (void)n_in; (void)out_size;

    const float* im_m   = (const float*)d_in[0];
    const float* im_s   = (const float*)d_in[1];
    const float* states = (const float*)d_in[2];
    const float* cw[2][4] = {
        {(const float*)d_in[3],  (const float*)d_in[5],  (const float*)d_in[7],  (const float*)d_in[9]},
        {(const float*)d_in[11], (const float*)d_in[13], (const float*)d_in[15], (const float*)d_in[17]}};
    const float* cb[2][4] = {
        {(const float*)d_in[4],  (const float*)d_in[6],  (const float*)d_in[8],  (const float*)d_in[10]},
        {(const float*)d_in[12], (const float*)d_in[14], (const float*)d_in[16], (const float*)d_in[18]}};
    const float* wih0  = (const float*)d_in[19];
    const float* whh0  = (const float*)d_in[20];
    const float* bih0  = (const float*)d_in[21];
    const float* bhh0  = (const float*)d_in[22];
    const float* wih_r = (const float*)d_in[23];
    const float* whh_r = (const float*)d_in[24];
    const float* bih_r = (const float*)d_in[25];
    const float* bhh_r = (const float*)d_in[26];
    const float* out_w = (const float*)d_in[27];
    const float* out_b = (const float*)d_in[28];
    float* out = (float*)d_out;

    float *bufA, *bufB, *imgf, *h0, *h1, *c0, *c1, *wt;
    cudaGetSymbolAddress((void**)&bufA, g_bufA);
    cudaGetSymbolAddress((void**)&bufB, g_bufB);
    cudaGetSymbolAddress((void**)&imgf, g_img);
    cudaGetSymbolAddress((void**)&h0,   g_h0);
    cudaGetSymbolAddress((void**)&h1,   g_h1);
    cudaGetSymbolAddress((void**)&c0,   g_c0);
    cudaGetSymbolAddress((void**)&c1,   g_c1);
    cudaGetSymbolAddress((void**)&wt,   g_wt);

    const size_t szL2 = 288 * 64, szL3 = 576 * 128, szL4 = 1152 * 16;
    const size_t camw = szL2 + szL3 + szL4;

    // dynamic smem: slab + sB[72][ocT+8]
    const int SMEM_L23 = (3 * SLABX * SLABI + 72 * (64 + 8)) * 4;   // 36336 B
    const int SMEM_L4  = (6 * SLABX * SLABI + 72 * (16 + 8)) * 4;   // 38112 B

    for (int cam = 0; cam < 2; cam++) {
        const float* src = cam ? im_s : im_m;
        float* wt2 = wt + cam * camw;
        float* wt3 = wt2 + szL2;
        float* wt4 = wt3 + szL3;

        wt_transform_kernel<<<(int)((szL2 + 255) / 256), 256>>>(cw[cam][1], wt2, 32,  64);
        wt_transform_kernel<<<(int)((szL3 + 255) / 256), 256>>>(cw[cam][2], wt3, 64,  128);
        wt_transform_kernel<<<(int)((szL4 + 255) / 256), 256>>>(cw[cam][3], wt4, 128, 16);

        conv3x3_relu_kernel<<<dim3(32, 4, NIMG), 128, 3 * 72 * 4>>>(src, cw[cam][0], cb[cam][0], bufA, 3, 32);

        // L2: Cin=32, Cout=64, ocT=64, WPX=2
        conv_mma_kernel<<<dim3(128, 1, NIMG), 256, SMEM_L23>>>(bufA, wt2, cb[cam][1], bufB, 32, 64, 64, 2);
        // L3: Cin=64, Cout=128, ocT=64, WPX=2
        conv_mma_kernel<<<dim3(128, 2, NIMG), 256, SMEM_L23>>>(bufB, wt3, cb[cam][2], bufA, 64, 128, 64, 2);
        // L4: Cin=128, Cout=16, ocT=16, WPX=8
        conv_mma_kernel<<<dim3(32, 1, NIMG), 256, SMEM_L4>>>(bufA, wt4, cb[cam][3], bufB, 128, 16, 16, 8);

        spatial_softmax_kernel<<<dim3(NCH, NIMG), 256>>>(bufB, imgf, cam ? 32 : 0);
    }

    // ---- LSTM ----
    cudaMemsetAsync(h0, 0, (size_t)LL * BB * HID * sizeof(float));
    cudaMemsetAsync(c0, 0, (size_t)LL * BB * HID * sizeof(float));

    for (int t = 0; t < TT; t++) {
        float* hp = (t & 1) ? h1 : h0;
        float* hc = (t & 1) ? h0 : h1;
        float* cp = (t & 1) ? c1 : c0;
        float* cc = (t & 1) ? c0 : c1;
        for (int l = 0; l < LL; l++) {
            const float *x1, *wi, *wh, *bi, *bh;
            int d1, bs1;
            if (l == 0) {
                x1 = states + t * SS; d1 = SS; bs1 = TT * SS;
                wi = wih0; wh = whh0; bi = bih0; bh = bhh0;
            } else {
                x1 = hc + (size_t)(l - 1) * BB * HID; d1 = HID; bs1 = HID;
                wi = wih_r + (size_t)(l - 1) * 4 * HID * 576;
                wh = whh_r + (size_t)(l - 1) * 4 * HID * HID;
                bi = bih_r + (size_t)(l - 1) * 4 * HID;
                bh = bhh_r + (size_t)(l - 1) * 4 * HID;
            }
            lstm_cell_kernel<<<256, 256>>>(
                x1, d1, bs1,
                imgf + t * 64, 64, TT * 64,
                hp + (size_t)l * BB * HID, cp + (size_t)l * BB * HID,
                wi, wh, bi, bh,
                hc + (size_t)l * BB * HID, cc + (size_t)l * BB * HID);
        }
        out_proj_kernel<<<1, 768>>>(hc + (size_t)5 * BB * HID, imgf, out_w, out_b, out, t);
    }
}

// round 7
// speedup vs baseline: 2.9276x; 1.9481x over previous
#include <cuda_runtime.h>
#include <cuda_fp16.h>
#include <math.h>
#include <stdint.h>

#define IMG   128
#define NPIX  16384
#define NIMG  40
#define BB    4
#define TT    10
#define SS    6
#define AA    6
#define HID   512
#define LL    6
#define NCH   16
#define SROW2 136   // half2 elements per slab row (data at [4..131], halo [3],[132])

// ---------------- scratch ----------------
__device__ __half2 g_bufA[(size_t)NIMG * 64 * NPIX];   // up to 128 ch (64 planes)
__device__ __half2 g_bufB[(size_t)NIMG * 32 * NPIX];   // up to 64 ch
__device__ float   g_img [BB * TT * 64];
__device__ float   g_h0[LL * BB * HID];
__device__ float   g_h1[LL * BB * HID];
__device__ float   g_c0[LL * BB * HID];
__device__ float   g_c1[LL * BB * HID];
// half2 k-pair-major weights per cam: L2 144x64, L3 288x128, L4 576x16 (half2 elems)
__device__ __half2 g_wt[2 * (144 * 64 + 288 * 128 + 576 * 16)];

__device__ __forceinline__ void mma_f16(float* d,
                                        uint32_t a0, uint32_t a1, uint32_t a2, uint32_t a3,
                                        uint32_t b0, uint32_t b1) {
    asm volatile(
        "mma.sync.aligned.m16n8k16.row.col.f32.f16.f16.f32 "
        "{%0,%1,%2,%3}, {%4,%5,%6,%7}, {%8,%9}, {%0,%1,%2,%3};"
        : "+f"(d[0]), "+f"(d[1]), "+f"(d[2]), "+f"(d[3])
        : "r"(a0), "r"(a1), "r"(a2), "r"(a3), "r"(b0), "r"(b1));
}

// ================ weight transform: [oc][ic][3][3] -> half2 pairs Wt2[k/2][Cout] ================
// k = (ky*3+kx)*Cin + ic ; pair (2m, 2m+1) = consecutive ic within same (ky,kx)
__global__ void wt_transform_kernel(const float* __restrict__ w, __half2* __restrict__ wt2,
                                    int Cin, int Cout) {
    int idx = blockIdx.x * 256 + threadIdx.x;
    int tot = (9 * Cin / 2) * Cout;
    if (idx >= tot) return;
    int m = idx / Cout, oc = idx - m * Cout;
    int k0 = 2 * m;
    int kykx = k0 / Cin, ic = k0 - kykx * Cin;
    float w0 = w[(oc * Cin + ic) * 9 + kykx];
    float w1 = w[(oc * Cin + ic + 1) * 9 + kykx];
    wt2[idx] = __floats2half2_rn(w0, w1);
}

// ================ fp16 mma.sync implicit-GEMM 3x3 SAME conv + bias + relu ================
// Activations: half2 channel-pair planar [n][Cin/2][128][128].
// block = 256 (8 warps). warp tile 64px x 16oc. ic-blocks of 16 channels (8 half2 planes).
// B fragments loaded gmem->regs (no smem staging). Slab: planar half2, conflict-free.
__global__ void __launch_bounds__(256)
conv_mma_kernel(const __half2* __restrict__ in, const __half2* __restrict__ wt2,
                const float* __restrict__ bias, __half2* __restrict__ out,
                int Cin, int Cout, int ocT, int WPX) {
    extern __shared__ __align__(16) uint32_t smu[];  // half2 slab [8][plane]
    const int tid  = threadIdx.x;
    const int lane = tid & 31;
    const int wid  = tid >> 5;

    const int rows  = WPX >> 1;
    const int slabR = rows + 2;
    int plane = slabR * SROW2;
    if ((plane & 31) == 16) plane += 8;     // keep plane % 32 == 24 (conflict-free kk strides)

    const int n   = blockIdx.z;
    const int y0  = blockIdx.x * rows;
    const int oc0 = blockIdx.y * ocT;

    const int wpx = wid % WPX;
    const int woc = wid / WPX;
    const int pxbase = wpx * 64;
    const int ocb    = woc * 16;

    const int kk = lane & 3;
    const int qr = lane >> 2;

    float d[4][2][4];
    #pragma unroll
    for (int mf = 0; mf < 4; mf++)
        #pragma unroll
        for (int nf = 0; nf < 2; nf++)
            #pragma unroll
            for (int r = 0; r < 4; r++) d[mf][nf][r] = 0.f;

    const int nicb = Cin >> 4;              // 16 channels per ic-block
    const int np   = Cin >> 1;              // half2 planes in input
    const uint32_t* wtb = (const uint32_t*)wt2;

    for (int icb = 0; icb < nicb; icb++) {
        __syncthreads();

        // ---- stage slab: 8 planes x slabR rows x 32 x (4 half2) ----
        {
            const int perp = slabR * 32;
            const int tot  = 8 * perp;
            for (int i = tid; i < tot; i += 256) {
                int q   = i / perp;
                int rem = i - q * perp;
                int r   = rem >> 5;
                int x0  = (rem & 31) << 2;
                int y   = y0 + r - 1;
                uint4 v = make_uint4(0u, 0u, 0u, 0u);
                if (y >= 0 && y < IMG)
                    v = *reinterpret_cast<const uint4*>(
                        in + ((size_t)(n * np + icb * 8 + q)) * NPIX + y * IMG + x0);
                *reinterpret_cast<uint4*>(smu + q * plane + r * SROW2 + 4 + x0) = v;
            }
            // halo zeros
            for (int i = tid; i < 8 * slabR; i += 256) {
                int q = i / slabR, r = i - q * slabR;
                smu[q * plane + r * SROW2 + 3]   = 0u;
                smu[q * plane + r * SROW2 + 132] = 0u;
            }
        }
        __syncthreads();

        #pragma unroll
        for (int c = 0; c < 9; c++) {
            const int ky = c / 3, kx = c - (c / 3) * 3;
            // B fragments: k-pairs (2kk,2kk+1) and (2kk+8,2kk+9), cols nn / nn+8
            const uint32_t* wb = wtb + ((size_t)((c * Cin) >> 1) + icb * 8) * Cout
                                 + oc0 + ocb + qr;
            uint32_t b0 = __ldg(wb + kk * Cout);
            uint32_t b1 = __ldg(wb + (kk + 4) * Cout);
            uint32_t b2 = __ldg(wb + kk * Cout + 8);
            uint32_t b3 = __ldg(wb + (kk + 4) * Cout + 8);

            #pragma unroll
            for (int mf = 0; mf < 4; mf++) {
                int px = pxbase + mf * 16 + qr;
                int pr = px >> 7, x = px & 127;
                int base = (pr + ky) * SROW2 + 3 + x + kx;
                uint32_t a0 = smu[kk * plane + base];
                uint32_t a1 = smu[kk * plane + base + 8];
                uint32_t a2 = smu[(kk + 4) * plane + base];
                uint32_t a3 = smu[(kk + 4) * plane + base + 8];
                mma_f16(d[mf][0], a0, a1, a2, a3, b0, b1);
                mma_f16(d[mf][1], a0, a1, a2, a3, b2, b3);
            }
        }
    }

    // ---- epilogue: bias + relu + half2 store ----
    #pragma unroll
    for (int nf = 0; nf < 2; nf++) {
        int oc = oc0 + ocb + nf * 8 + 2 * kk;
        float bv0 = bias[oc], bv1 = bias[oc + 1];
        #pragma unroll
        for (int mf = 0; mf < 4; mf++) {
            int px = pxbase + mf * 16 + qr;
            int pr = px >> 7, x = px & 127;
            __half2* o0 = out + ((size_t)(n * (Cout >> 1) + (oc >> 1))) * NPIX
                          + (y0 + pr) * IMG + x;
            o0[0] = __floats2half2_rn(fmaxf(d[mf][nf][0] + bv0, 0.f),
                                      fmaxf(d[mf][nf][1] + bv1, 0.f));
            o0[8] = __floats2half2_rn(fmaxf(d[mf][nf][2] + bv0, 0.f),
                                      fmaxf(d[mf][nf][3] + bv1, 0.f));
        }
    }
}

// ---------------- fp32 direct conv (layer 1, Cin=3) -> half2 output ----------------
__global__ void conv3x3_relu_kernel(const float* __restrict__ in,
                                    const float* __restrict__ w,
                                    const float* __restrict__ bias,
                                    __half2* __restrict__ out,
                                    int Cin, int Cout) {
    extern __shared__ float sw[];
    const int tid  = threadIdx.x;
    const int lane = tid & 31;
    const int warp = tid >> 5;
    const int ocg  = blockIdx.y;
    const int n    = blockIdx.z;

    const int nw = Cin * 72;
    const float* wbase = w + (size_t)ocg * 8 * Cin * 9;
    for (int i = tid; i < nw; i += blockDim.x) {
        int o = i & 7, rest = i >> 3;
        sw[i] = wbase[(size_t)o * Cin * 9 + rest];
    }
    __syncthreads();

    const int y  = blockIdx.x * 4 + warp;
    const int x0 = lane * 4;

    float acc[8][4];
    #pragma unroll
    for (int o = 0; o < 8; o++) {
        float bv = bias[ocg * 8 + o];
        #pragma unroll
        for (int p = 0; p < 4; p++) acc[o][p] = bv;
    }

    for (int ic = 0; ic < Cin; ic++) {
        const float* ip = in + (size_t)(n * Cin + ic) * NPIX;
        float v[3][6];
        #pragma unroll
        for (int r = 0; r < 3; r++) {
            int yy = y - 1 + r;
            float4 m = make_float4(0.f, 0.f, 0.f, 0.f);
            if (yy >= 0 && yy < IMG)
                m = *reinterpret_cast<const float4*>(ip + yy * IMG + x0);
            float left  = __shfl_up_sync(0xffffffffu, m.w, 1);
            float right = __shfl_down_sync(0xffffffffu, m.x, 1);
            if (lane == 0)  left  = 0.f;
            if (lane == 31) right = 0.f;
            v[r][0] = left; v[r][1] = m.x; v[r][2] = m.y;
            v[r][3] = m.z;  v[r][4] = m.w; v[r][5] = right;
        }
        const float* wp = sw + ic * 72;
        #pragma unroll
        for (int ky = 0; ky < 3; ky++)
        #pragma unroll
        for (int kx = 0; kx < 3; kx++) {
            const float* wq = wp + (ky * 3 + kx) * 8;
            #pragma unroll
            for (int o = 0; o < 8; o++) {
                float wv = wq[o];
                #pragma unroll
                for (int p = 0; p < 4; p++)
                    acc[o][p] = fmaf(v[ky][kx + p], wv, acc[o][p]);
            }
        }
    }

    #pragma unroll
    for (int o = 0; o < 8; o += 2) {
        __half2 h[4];
        #pragma unroll
        for (int p = 0; p < 4; p++)
            h[p] = __floats2half2_rn(fmaxf(acc[o][p], 0.f), fmaxf(acc[o + 1][p], 0.f));
        int pl = (ocg * 8 + o) >> 1;
        *reinterpret_cast<uint4*>(
            out + ((size_t)(n * (Cout >> 1) + pl)) * NPIX + y * IMG + x0) =
            *reinterpret_cast<uint4*>(h);
    }
}

// ---------------- spatial softmax (half2 input, __expf) ----------------
__global__ void spatial_softmax_kernel(const __half2* __restrict__ x,
                                       float* __restrict__ img, int base) {
    const int ch = blockIdx.x;
    const int n  = blockIdx.y;
    const int hi = ch & 1;
    const __half2* p = x + (size_t)(n * (NCH / 2) + (ch >> 1)) * NPIX;
    __shared__ float r1[256], r2[256], r3[256];
    const int tid = threadIdx.x;

    float m = -1e30f;
    for (int i = tid; i < NPIX; i += 256) {
        float v = hi ? __high2float(p[i]) : __low2float(p[i]);
        m = fmaxf(m, v);
    }
    r1[tid] = m; __syncthreads();
    for (int s = 128; s > 0; s >>= 1) {
        if (tid < s) r1[tid] = fmaxf(r1[tid], r1[tid + s]);
        __syncthreads();
    }
    m = r1[0];
    __syncthreads();

    float s = 0.f, sx = 0.f, sy = 0.f;
    for (int i = tid; i < NPIX; i += 256) {
        float v = hi ? __high2float(p[i]) : __low2float(p[i]);
        float e = __expf(v - m);
        int yy = i >> 7, xx = i & 127;
        float px = -1.f + (2.f / 127.f) * (float)xx;
        float py = -1.f + (2.f / 127.f) * (float)yy;
        s += e; sx += e * px; sy += e * py;
    }
    r1[tid] = s; r2[tid] = sx; r3[tid] = sy; __syncthreads();
    for (int st = 128; st > 0; st >>= 1) {
        if (tid < st) {
            r1[tid] += r1[tid + st];
            r2[tid] += r2[tid + st];
            r3[tid] += r3[tid + st];
        }
        __syncthreads();
    }
    if (tid == 0) {
        float inv = 1.f / r1[0];
        img[n * 64 + base + 2 * ch]     = r2[0] * inv;
        img[n * 64 + base + 2 * ch + 1] = r3[0] * inv;
    }
}

// ---------------- fused LSTM cell (wide) ----------------
__global__ void __launch_bounds__(256)
lstm_cell_kernel(const float* __restrict__ x1, int d1, int x1_bs,
                 const float* __restrict__ x2, int d2, int x2_bs,
                 const float* __restrict__ hprev,
                 const float* __restrict__ cprev,
                 const float* __restrict__ wih,
                 const float* __restrict__ whh,
                 const float* __restrict__ bih,
                 const float* __restrict__ bhh,
                 float* __restrict__ hout,
                 float* __restrict__ cout) {
    __shared__ __align__(16) float sx[BB * 576];
    __shared__ __align__(16) float sh[BB * HID];
    __shared__ float gate[8][4];
    const int d   = d1 + d2;
    const int tid = threadIdx.x;

    for (int i = tid; i < BB * d; i += 256) {
        int b = i / d, k = i - b * d;
        sx[i] = (k < d1) ? x1[b * x1_bs + k] : x2[b * x2_bs + (k - d1)];
    }
    for (int i = tid; i < BB * HID; i += 256) sh[i] = hprev[i];
    __syncthreads();

    const int lane = tid & 31;
    const int w    = tid >> 5;
    const int jl   = w >> 2;
    const int g    = w & 3;
    const int j    = blockIdx.x * 2 + jl;

    float acc[4] = {0.f, 0.f, 0.f, 0.f};

    const float* wr = wih + (size_t)(g * HID + j) * d;
    if ((d & 3) == 0) {
        for (int k = lane * 4; k < d; k += 128) {
            float4 wv = *reinterpret_cast<const float4*>(wr + k);
            #pragma unroll
            for (int b = 0; b < 4; b++) {
                float4 xv = *reinterpret_cast<const float4*>(sx + b * d + k);
                acc[b] = fmaf(wv.x, xv.x, acc[b]);
                acc[b] = fmaf(wv.y, xv.y, acc[b]);
                acc[b] = fmaf(wv.z, xv.z, acc[b]);
                acc[b] = fmaf(wv.w, xv.w, acc[b]);
            }
        }
    } else {
        for (int k = lane; k < d; k += 32) {
            float wv = wr[k];
            #pragma unroll
            for (int b = 0; b < 4; b++)
                acc[b] = fmaf(sx[b * d + k], wv, acc[b]);
        }
    }

    const float* w2 = whh + (size_t)(g * HID + j) * HID;
    #pragma unroll
    for (int k4 = 0; k4 < 4; k4++) {
        int k = lane * 4 + k4 * 128;
        float4 wv = *reinterpret_cast<const float4*>(w2 + k);
        #pragma unroll
        for (int b = 0; b < 4; b++) {
            float4 hv = *reinterpret_cast<const float4*>(sh + b * HID + k);
            acc[b] = fmaf(wv.x, hv.x, acc[b]);
            acc[b] = fmaf(wv.y, hv.y, acc[b]);
            acc[b] = fmaf(wv.z, hv.z, acc[b]);
            acc[b] = fmaf(wv.w, hv.w, acc[b]);
        }
    }

    #pragma unroll
    for (int b = 0; b < 4; b++) {
        #pragma unroll
        for (int off = 16; off > 0; off >>= 1)
            acc[b] += __shfl_xor_sync(0xffffffffu, acc[b], off);
    }
    if (lane == 0) {
        gate[w][0] = acc[0]; gate[w][1] = acc[1];
        gate[w][2] = acc[2]; gate[w][3] = acc[3];
    }
    __syncthreads();

    if (tid < 8) {
        int jj = tid >> 2, b = tid & 3;
        int jg = blockIdx.x * 2 + jj;
        float gi = gate[jj * 4 + 0][b] + bih[jg]           + bhh[jg];
        float gf = gate[jj * 4 + 1][b] + bih[HID + jg]     + bhh[HID + jg];
        float gg = gate[jj * 4 + 2][b] + bih[2 * HID + jg] + bhh[2 * HID + jg];
        float go = gate[jj * 4 + 3][b] + bih[3 * HID + jg] + bhh[3 * HID + jg];
        float si = 1.f / (1.f + expf(-gi));
        float sf = 1.f / (1.f + expf(-gf));
        float tg = tanhf(gg);
        float so = 1.f / (1.f + expf(-go));
        float c2 = sf * cprev[b * HID + jg] + si * tg;
        float h2 = so * tanhf(c2);
        hout[b * HID + jg] = h2;
        cout[b * HID + jg] = c2;
    }
}

// ---------------- output projection ----------------
__global__ void out_proj_kernel(const float* __restrict__ h,
                                const float* __restrict__ imgf,
                                const float* __restrict__ out_w,
                                const float* __restrict__ out_b,
                                float* __restrict__ out, int t) {
    const int wid  = threadIdx.x >> 5;
    const int lane = threadIdx.x & 31;
    if (wid >= BB * AA) return;
    const int b = wid / AA, a = wid % AA;
    const float* row = out_w + a * 576;
    float acc = 0.f;
    for (int k = lane; k < 576; k += 32) {
        float x = (k < HID) ? h[b * HID + k] : imgf[(b * TT + t) * 64 + (k - HID)];
        acc = fmaf(row[k], x, acc);
    }
    #pragma unroll
    for (int off = 16; off > 0; off >>= 1)
        acc += __shfl_xor_sync(0xffffffffu, acc, off);
    if (lane == 0) out[(b * TT + t) * AA + a] = acc + out_b[a];
}

// ---------------- host orchestration ----------------
extern "C" void kernel_launch(void* const* d_in, const int* in_sizes, int n_in,
                              void* d_out, int out_size) {
    (void)in_sizes; (void)n_in; (void)out_size;

    const float* im_m   = (const float*)d_in[0];
    const float* im_s   = (const float*)d_in[1];
    const float* states = (const float*)d_in[2];
    const float* cw[2][4] = {
        {(const float*)d_in[3],  (const float*)d_in[5],  (const float*)d_in[7],  (const float*)d_in[9]},
        {(const float*)d_in[11], (const float*)d_in[13], (const float*)d_in[15], (const float*)d_in[17]}};
    const float* cb[2][4] = {
        {(const float*)d_in[4],  (const float*)d_in[6],  (const float*)d_in[8],  (const float*)d_in[10]},
        {(const float*)d_in[12], (const float*)d_in[14], (const float*)d_in[16], (const float*)d_in[18]}};
    const float* wih0  = (const float*)d_in[19];
    const float* whh0  = (const float*)d_in[20];
    const float* bih0  = (const float*)d_in[21];
    const float* bhh0  = (const float*)d_in[22];
    const float* wih_r = (const float*)d_in[23];
    const float* whh_r = (const float*)d_in[24];
    const float* bih_r = (const float*)d_in[25];
    const float* bhh_r = (const float*)d_in[26];
    const float* out_w = (const float*)d_in[27];
    const float* out_b = (const float*)d_in[28];
    float* out = (float*)d_out;

    __half2 *bufA, *bufB, *wt;
    float *imgf, *h0, *h1, *c0, *c1;
    cudaGetSymbolAddress((void**)&bufA, g_bufA);
    cudaGetSymbolAddress((void**)&bufB, g_bufB);
    cudaGetSymbolAddress((void**)&imgf, g_img);
    cudaGetSymbolAddress((void**)&h0,   g_h0);
    cudaGetSymbolAddress((void**)&h1,   g_h1);
    cudaGetSymbolAddress((void**)&c0,   g_c0);
    cudaGetSymbolAddress((void**)&c1,   g_c1);
    cudaGetSymbolAddress((void**)&wt,   g_wt);

    // per-cam half2 weights: L2 144*64, L3 288*128, L4 576*16
    const size_t szL2 = 144 * 64, szL3 = 288 * 128, szL4 = 576 * 16;
    const size_t camw = szL2 + szL3 + szL4;

    const int SMEM_L23 = 8 * (3 * SROW2) * 4;        // 13056 B (plane 408)
    const int SMEM_L4  = 8 * (6 * SROW2 + 8) * 4;    // 26368 B (plane 824)

    for (int cam = 0; cam < 2; cam++) {
        const float* src = cam ? im_s : im_m;
        __half2* wt2 = wt + cam * camw;
        __half2* wt3 = wt2 + szL2;
        __half2* wt4 = wt3 + szL3;

        wt_transform_kernel<<<(int)((szL2 + 255) / 256), 256>>>(cw[cam][1], wt2, 32,  64);
        wt_transform_kernel<<<(int)((szL3 + 255) / 256), 256>>>(cw[cam][2], wt3, 64,  128);
        wt_transform_kernel<<<(int)((szL4 + 255) / 256), 256>>>(cw[cam][3], wt4, 128, 16);

        conv3x3_relu_kernel<<<dim3(32, 4, NIMG), 128, 3 * 72 * 4>>>(src, cw[cam][0], cb[cam][0], bufA, 3, 32);

        // L2: Cin=32 (16 planes in bufA), Cout=64 -> bufB
        conv_mma_kernel<<<dim3(128, 1, NIMG), 256, SMEM_L23>>>(bufA, wt2, cb[cam][1], bufB, 32, 64, 64, 2);
        // L3: Cin=64 (bufB), Cout=128 -> bufA
        conv_mma_kernel<<<dim3(128, 2, NIMG), 256, SMEM_L23>>>(bufB, wt3, cb[cam][2], bufA, 64, 128, 64, 2);
        // L4: Cin=128 (bufA), Cout=16 -> bufB
        conv_mma_kernel<<<dim3(32, 1, NIMG), 256, SMEM_L4>>>(bufA, wt4, cb[cam][3], bufB, 128, 16, 16, 8);

        spatial_softmax_kernel<<<dim3(NCH, NIMG), 256>>>(bufB, imgf, cam ? 32 : 0);
    }

    // ---- LSTM ----
    cudaMemsetAsync(h0, 0, (size_t)LL * BB * HID * sizeof(float));
    cudaMemsetAsync(c0, 0, (size_t)LL * BB * HID * sizeof(float));

    for (int t = 0; t < TT; t++) {
        float* hp = (t & 1) ? h1 : h0;
        float* hc = (t & 1) ? h0 : h1;
        float* cp = (t & 1) ? c1 : c0;
        float* cc = (t & 1) ? c0 : c1;
        for (int l = 0; l < LL; l++) {
            const float *x1, *wi, *wh, *bi, *bh;
            int d1, bs1;
            if (l == 0) {
                x1 = states + t * SS; d1 = SS; bs1 = TT * SS;
                wi = wih0; wh = whh0; bi = bih0; bh = bhh0;
            } else {
                x1 = hc + (size_t)(l - 1) * BB * HID; d1 = HID; bs1 = HID;
                wi = wih_r + (size_t)(l - 1) * 4 * HID * 576;
                wh = whh_r + (size_t)(l - 1) * 4 * HID * HID;
                bi = bih_r + (size_t)(l - 1) * 4 * HID;
                bh = bhh_r + (size_t)(l - 1) * 4 * HID;
            }
            lstm_cell_kernel<<<256, 256>>>(
                x1, d1, bs1,
                imgf + t * 64, 64, TT * 64,
                hp + (size_t)l * BB * HID, cp + (size_t)l * BB * HID,
                wi, wh, bi, bh,
                hc + (size_t)l * BB * HID, cc + (size_t)l * BB * HID);
        }
        out_proj_kernel<<<1, 768>>>(hc + (size_t)5 * BB * HID, imgf, out_w, out_b, out, t);
    }
}

// round 8
// speedup vs baseline: 2.9365x; 1.0030x over previous
#include <cuda_runtime.h>
#include <cuda_fp16.h>
#include <math.h>
#include <stdint.h>

#define IMG   128
#define NPIX  16384
#define NIMG  40
#define BB    4
#define TT    10
#define SS    6
#define AA    6
#define HID   512
#define LL    6
#define NCH   16
#define SROW2 136   // half2 elements per slab row (data at [4..131], halo [3],[132])

// ---------------- scratch ----------------
__device__ __half2 g_bufA[(size_t)NIMG * 64 * NPIX];   // up to 128 ch (64 planes)
__device__ __half2 g_bufB[(size_t)NIMG * 32 * NPIX];   // up to 64 ch
__device__ float   g_img [BB * TT * 64];
__device__ float   g_h0[LL * BB * HID];
__device__ float   g_h1[LL * BB * HID];
__device__ float   g_c0[LL * BB * HID];
__device__ float   g_c1[LL * BB * HID];
// half2 k-pair-major weights per cam: L2 144x64, L3 288x128, L4 576x16 (half2 elems)
__device__ __half2 g_wt[2 * (144 * 64 + 288 * 128 + 576 * 16)];

__device__ __forceinline__ void mma_f16(float* d,
                                        uint32_t a0, uint32_t a1, uint32_t a2, uint32_t a3,
                                        uint32_t b0, uint32_t b1) {
    asm volatile(
        "mma.sync.aligned.m16n8k16.row.col.f32.f16.f16.f32 "
        "{%0,%1,%2,%3}, {%4,%5,%6,%7}, {%8,%9}, {%0,%1,%2,%3};"
        : "+f"(d[0]), "+f"(d[1]), "+f"(d[2]), "+f"(d[3])
        : "r"(a0), "r"(a1), "r"(a2), "r"(a3), "r"(b0), "r"(b1));
}

// ================ weight transform: [oc][ic][3][3] -> half2 pairs Wt2[k/2][Cout] ================
__global__ void wt_transform_kernel(const float* __restrict__ w, __half2* __restrict__ wt2,
                                    int Cin, int Cout) {
    int idx = blockIdx.x * 256 + threadIdx.x;
    int tot = (9 * Cin / 2) * Cout;
    if (idx >= tot) return;
    int m = idx / Cout, oc = idx - m * Cout;
    int k0 = 2 * m;
    int kykx = k0 / Cin, ic = k0 - kykx * Cin;
    float w0 = w[(oc * Cin + ic) * 9 + kykx];
    float w1 = w[(oc * Cin + ic + 1) * 9 + kykx];
    wt2[idx] = __floats2half2_rn(w0, w1);
}

// ================ fp16 mma.sync implicit-GEMM 3x3 SAME conv + bias + relu ================
__global__ void __launch_bounds__(256)
conv_mma_kernel(const __half2* __restrict__ in, const __half2* __restrict__ wt2,
                const float* __restrict__ bias, __half2* __restrict__ out,
                int Cin, int Cout, int ocT, int WPX) {
    extern __shared__ __align__(16) uint32_t smu[];
    const int tid  = threadIdx.x;
    const int lane = tid & 31;
    const int wid  = tid >> 5;

    const int rows  = WPX >> 1;
    const int slabR = rows + 2;
    int plane = slabR * SROW2;
    if ((plane & 31) == 16) plane += 8;     // keep plane % 32 == 24 (conflict-free)

    const int n   = blockIdx.z;
    const int y0  = blockIdx.x * rows;
    const int oc0 = blockIdx.y * ocT;

    const int wpx = wid % WPX;
    const int woc = wid / WPX;
    const int pxbase = wpx * 64;
    const int ocb    = woc * 16;

    const int kk = lane & 3;
    const int qr = lane >> 2;

    float d[4][2][4];
    #pragma unroll
    for (int mf = 0; mf < 4; mf++)
        #pragma unroll
        for (int nf = 0; nf < 2; nf++)
            #pragma unroll
            for (int r = 0; r < 4; r++) d[mf][nf][r] = 0.f;

    const int nicb = Cin >> 4;
    const int np   = Cin >> 1;
    const uint32_t* wtb = (const uint32_t*)wt2;

    for (int icb = 0; icb < nicb; icb++) {
        __syncthreads();

        // ---- stage slab: 8 planes x slabR rows x 32 x (4 half2) ----
        {
            const int perp = slabR * 32;
            const int tot  = 8 * perp;
            for (int i = tid; i < tot; i += 256) {
                int q   = i / perp;
                int rem = i - q * perp;
                int r   = rem >> 5;
                int x0  = (rem & 31) << 2;
                int y   = y0 + r - 1;
                uint4 v = make_uint4(0u, 0u, 0u, 0u);
                if (y >= 0 && y < IMG)
                    v = *reinterpret_cast<const uint4*>(
                        in + ((size_t)(n * np + icb * 8 + q)) * NPIX + y * IMG + x0);
                *reinterpret_cast<uint4*>(smu + q * plane + r * SROW2 + 4 + x0) = v;
            }
            for (int i = tid; i < 8 * slabR; i += 256) {
                int q = i / slabR, r = i - q * slabR;
                smu[q * plane + r * SROW2 + 3]   = 0u;
                smu[q * plane + r * SROW2 + 132] = 0u;
            }
        }
        __syncthreads();

        #pragma unroll
        for (int c = 0; c < 9; c++) {
            const int ky = c / 3, kx = c - (c / 3) * 3;
            const uint32_t* wb = wtb + ((size_t)((c * Cin) >> 1) + icb * 8) * Cout
                                 + oc0 + ocb + qr;
            uint32_t b0 = __ldg(wb + kk * Cout);
            uint32_t b1 = __ldg(wb + (kk + 4) * Cout);
            uint32_t b2 = __ldg(wb + kk * Cout + 8);
            uint32_t b3 = __ldg(wb + (kk + 4) * Cout + 8);

            #pragma unroll
            for (int mf = 0; mf < 4; mf++) {
                int px = pxbase + mf * 16 + qr;
                int pr = px >> 7, x = px & 127;
                int base = (pr + ky) * SROW2 + 3 + x + kx;
                uint32_t a0 = smu[kk * plane + base];
                uint32_t a1 = smu[kk * plane + base + 8];
                uint32_t a2 = smu[(kk + 4) * plane + base];
                uint32_t a3 = smu[(kk + 4) * plane + base + 8];
                mma_f16(d[mf][0], a0, a1, a2, a3, b0, b1);
                mma_f16(d[mf][1], a0, a1, a2, a3, b2, b3);
            }
        }
    }

    // ---- epilogue: bias + relu + half2 store ----
    #pragma unroll
    for (int nf = 0; nf < 2; nf++) {
        int oc = oc0 + ocb + nf * 8 + 2 * kk;
        float bv0 = bias[oc], bv1 = bias[oc + 1];
        #pragma unroll
        for (int mf = 0; mf < 4; mf++) {
            int px = pxbase + mf * 16 + qr;
            int pr = px >> 7, x = px & 127;
            __half2* o0 = out + ((size_t)(n * (Cout >> 1) + (oc >> 1))) * NPIX
                          + (y0 + pr) * IMG + x;
            o0[0] = __floats2half2_rn(fmaxf(d[mf][nf][0] + bv0, 0.f),
                                      fmaxf(d[mf][nf][1] + bv1, 0.f));
            o0[8] = __floats2half2_rn(fmaxf(d[mf][nf][2] + bv0, 0.f),
                                      fmaxf(d[mf][nf][3] + bv1, 0.f));
        }
    }
}

// ---------------- fp32 direct conv (layer 1, Cin=3) -> half2 output ----------------
__global__ void conv3x3_relu_kernel(const float* __restrict__ in,
                                    const float* __restrict__ w,
                                    const float* __restrict__ bias,
                                    __half2* __restrict__ out,
                                    int Cin, int Cout) {
    extern __shared__ float sw[];
    const int tid  = threadIdx.x;
    const int lane = tid & 31;
    const int warp = tid >> 5;
    const int ocg  = blockIdx.y;
    const int n    = blockIdx.z;

    const int nw = Cin * 72;
    const float* wbase = w + (size_t)ocg * 8 * Cin * 9;
    for (int i = tid; i < nw; i += blockDim.x) {
        int o = i & 7, rest = i >> 3;
        sw[i] = wbase[(size_t)o * Cin * 9 + rest];
    }
    __syncthreads();

    const int y  = blockIdx.x * 4 + warp;
    const int x0 = lane * 4;

    float acc[8][4];
    #pragma unroll
    for (int o = 0; o < 8; o++) {
        float bv = bias[ocg * 8 + o];
        #pragma unroll
        for (int p = 0; p < 4; p++) acc[o][p] = bv;
    }

    for (int ic = 0; ic < Cin; ic++) {
        const float* ip = in + (size_t)(n * Cin + ic) * NPIX;
        float v[3][6];
        #pragma unroll
        for (int r = 0; r < 3; r++) {
            int yy = y - 1 + r;
            float4 m = make_float4(0.f, 0.f, 0.f, 0.f);
            if (yy >= 0 && yy < IMG)
                m = *reinterpret_cast<const float4*>(ip + yy * IMG + x0);
            float left  = __shfl_up_sync(0xffffffffu, m.w, 1);
            float right = __shfl_down_sync(0xffffffffu, m.x, 1);
            if (lane == 0)  left  = 0.f;
            if (lane == 31) right = 0.f;
            v[r][0] = left; v[r][1] = m.x; v[r][2] = m.y;
            v[r][3] = m.z;  v[r][4] = m.w; v[r][5] = right;
        }
        const float* wp = sw + ic * 72;
        #pragma unroll
        for (int ky = 0; ky < 3; ky++)
        #pragma unroll
        for (int kx = 0; kx < 3; kx++) {
            const float* wq = wp + (ky * 3 + kx) * 8;
            #pragma unroll
            for (int o = 0; o < 8; o++) {
                float wv = wq[o];
                #pragma unroll
                for (int p = 0; p < 4; p++)
                    acc[o][p] = fmaf(v[ky][kx + p], wv, acc[o][p]);
            }
        }
    }

    #pragma unroll
    for (int o = 0; o < 8; o += 2) {
        __half2 h[4];
        #pragma unroll
        for (int p = 0; p < 4; p++)
            h[p] = __floats2half2_rn(fmaxf(acc[o][p], 0.f), fmaxf(acc[o + 1][p], 0.f));
        int pl = (ocg * 8 + o) >> 1;
        *reinterpret_cast<uint4*>(
            out + ((size_t)(n * (Cout >> 1) + pl)) * NPIX + y * IMG + x0) =
            *reinterpret_cast<uint4*>(h);
    }
}

// ---------------- spatial softmax: one block per half2 plane (2 channels) ----------------
__global__ void spatial_softmax_kernel(const __half2* __restrict__ x,
                                       float* __restrict__ img, int base) {
    const int pl = blockIdx.x;                 // plane = channel pair
    const int n  = blockIdx.y;
    const __half2* p = x + (size_t)(n * (NCH / 2) + pl) * NPIX;
    __shared__ float rA[256], rB[256], rC[256], rD[256], rE[256], rF[256];
    const int tid = threadIdx.x;

    float m0 = -1e30f, m1 = -1e30f;
    for (int i = tid; i < NPIX; i += 256) {
        __half2 v = p[i];
        m0 = fmaxf(m0, __low2float(v));
        m1 = fmaxf(m1, __high2float(v));
    }
    rA[tid] = m0; rB[tid] = m1; __syncthreads();
    for (int s = 128; s > 0; s >>= 1) {
        if (tid < s) {
            rA[tid] = fmaxf(rA[tid], rA[tid + s]);
            rB[tid] = fmaxf(rB[tid], rB[tid + s]);
        }
        __syncthreads();
    }
    m0 = rA[0]; m1 = rB[0];
    __syncthreads();

    float s0 = 0.f, sx0 = 0.f, sy0 = 0.f;
    float s1 = 0.f, sx1 = 0.f, sy1 = 0.f;
    for (int i = tid; i < NPIX; i += 256) {
        __half2 v = p[i];
        float e0 = __expf(__low2float(v)  - m0);
        float e1 = __expf(__high2float(v) - m1);
        int yy = i >> 7, xx = i & 127;
        float px = -1.f + (2.f / 127.f) * (float)xx;
        float py = -1.f + (2.f / 127.f) * (float)yy;
        s0 += e0; sx0 += e0 * px; sy0 += e0 * py;
        s1 += e1; sx1 += e1 * px; sy1 += e1 * py;
    }
    rA[tid] = s0; rB[tid] = sx0; rC[tid] = sy0;
    rD[tid] = s1; rE[tid] = sx1; rF[tid] = sy1;
    __syncthreads();
    for (int st = 128; st > 0; st >>= 1) {
        if (tid < st) {
            rA[tid] += rA[tid + st]; rB[tid] += rB[tid + st]; rC[tid] += rC[tid + st];
            rD[tid] += rD[tid + st]; rE[tid] += rE[tid + st]; rF[tid] += rF[tid + st];
        }
        __syncthreads();
    }
    if (tid == 0) {
        float inv0 = 1.f / rA[0];
        float inv1 = 1.f / rD[0];
        int ch0 = 2 * pl, ch1 = 2 * pl + 1;
        img[n * 64 + base + 2 * ch0]     = rB[0] * inv0;
        img[n * 64 + base + 2 * ch0 + 1] = rC[0] * inv0;
        img[n * 64 + base + 2 * ch1]     = rE[0] * inv1;
        img[n * 64 + base + 2 * ch1 + 1] = rF[0] * inv1;
    }
}

// ---------------- fused LSTM cell (wide) ----------------
__global__ void __launch_bounds__(256)
lstm_cell_kernel(const float* __restrict__ x1, int d1, int x1_bs,
                 const float* __restrict__ x2, int d2, int x2_bs,
                 const float* __restrict__ hprev,
                 const float* __restrict__ cprev,
                 const float* __restrict__ wih,
                 const float* __restrict__ whh,
                 const float* __restrict__ bih,
                 const float* __restrict__ bhh,
                 float* __restrict__ hout,
                 float* __restrict__ cout) {
    __shared__ __align__(16) float sx[BB * 576];
    __shared__ __align__(16) float sh[BB * HID];
    __shared__ float gate[8][4];
    const int d   = d1 + d2;
    const int tid = threadIdx.x;

    for (int i = tid; i < BB * d; i += 256) {
        int b = i / d, k = i - b * d;
        sx[i] = (k < d1) ? x1[b * x1_bs + k] : x2[b * x2_bs + (k - d1)];
    }
    for (int i = tid; i < BB * HID; i += 256) sh[i] = hprev[i];
    __syncthreads();

    const int lane = tid & 31;
    const int w    = tid >> 5;
    const int jl   = w >> 2;
    const int g    = w & 3;
    const int j    = blockIdx.x * 2 + jl;

    float acc[4] = {0.f, 0.f, 0.f, 0.f};

    const float* wr = wih + (size_t)(g * HID + j) * d;
    if ((d & 3) == 0) {
        for (int k = lane * 4; k < d; k += 128) {
            float4 wv = *reinterpret_cast<const float4*>(wr + k);
            #pragma unroll
            for (int b = 0; b < 4; b++) {
                float4 xv = *reinterpret_cast<const float4*>(sx + b * d + k);
                acc[b] = fmaf(wv.x, xv.x, acc[b]);
                acc[b] = fmaf(wv.y, xv.y, acc[b]);
                acc[b] = fmaf(wv.z, xv.z, acc[b]);
                acc[b] = fmaf(wv.w, xv.w, acc[b]);
            }
        }
    } else {
        for (int k = lane; k < d; k += 32) {
            float wv = wr[k];
            #pragma unroll
            for (int b = 0; b < 4; b++)
                acc[b] = fmaf(sx[b * d + k], wv, acc[b]);
        }
    }

    const float* w2 = whh + (size_t)(g * HID + j) * HID;
    #pragma unroll
    for (int k4 = 0; k4 < 4; k4++) {
        int k = lane * 4 + k4 * 128;
        float4 wv = *reinterpret_cast<const float4*>(w2 + k);
        #pragma unroll
        for (int b = 0; b < 4; b++) {
            float4 hv = *reinterpret_cast<const float4*>(sh + b * HID + k);
            acc[b] = fmaf(wv.x, hv.x, acc[b]);
            acc[b] = fmaf(wv.y, hv.y, acc[b]);
            acc[b] = fmaf(wv.z, hv.z, acc[b]);
            acc[b] = fmaf(wv.w, hv.w, acc[b]);
        }
    }

    #pragma unroll
    for (int b = 0; b < 4; b++) {
        #pragma unroll
        for (int off = 16; off > 0; off >>= 1)
            acc[b] += __shfl_xor_sync(0xffffffffu, acc[b], off);
    }
    if (lane == 0) {
        gate[w][0] = acc[0]; gate[w][1] = acc[1];
        gate[w][2] = acc[2]; gate[w][3] = acc[3];
    }
    __syncthreads();

    if (tid < 8) {
        int jj = tid >> 2, b = tid & 3;
        int jg = blockIdx.x * 2 + jj;
        float gi = gate[jj * 4 + 0][b] + bih[jg]           + bhh[jg];
        float gf = gate[jj * 4 + 1][b] + bih[HID + jg]     + bhh[HID + jg];
        float gg = gate[jj * 4 + 2][b] + bih[2 * HID + jg] + bhh[2 * HID + jg];
        float go = gate[jj * 4 + 3][b] + bih[3 * HID + jg] + bhh[3 * HID + jg];
        float si = 1.f / (1.f + expf(-gi));
        float sf = 1.f / (1.f + expf(-gf));
        float tg = tanhf(gg);
        float so = 1.f / (1.f + expf(-go));
        float c2 = sf * cprev[b * HID + jg] + si * tg;
        float h2 = so * tanhf(c2);
        hout[b * HID + jg] = h2;
        cout[b * HID + jg] = c2;
    }
}

// ---------------- output projection ----------------
__global__ void out_proj_kernel(const float* __restrict__ h,
                                const float* __restrict__ imgf,
                                const float* __restrict__ out_w,
                                const float* __restrict__ out_b,
                                float* __restrict__ out, int t) {
    const int wid  = threadIdx.x >> 5;
    const int lane = threadIdx.x & 31;
    if (wid >= BB * AA) return;
    const int b = wid / AA, a = wid % AA;
    const float* row = out_w + a * 576;
    float acc = 0.f;
    for (int k = lane; k < 576; k += 32) {
        float x = (k < HID) ? h[b * HID + k] : imgf[(b * TT + t) * 64 + (k - HID)];
        acc = fmaf(row[k], x, acc);
    }
    #pragma unroll
    for (int off = 16; off > 0; off >>= 1)
        acc += __shfl_xor_sync(0xffffffffu, acc, off);
    if (lane == 0) out[(b * TT + t) * AA + a] = acc + out_b[a];
}

// ---------------- host orchestration ----------------
extern "C" void kernel_launch(void* const* d_in, const int* in_sizes, int n_in,
                              void* d_out, int out_size) {
    (void)in_sizes; (void)n_in; (void)out_size;

    const float* im_m   = (const float*)d_in[0];
    const float* im_s   = (const float*)d_in[1];
    const float* states = (const float*)d_in[2];
    const float* cw[2][4] = {
        {(const float*)d_in[3],  (const float*)d_in[5],  (const float*)d_in[7],  (const float*)d_in[9]},
        {(const float*)d_in[11], (const float*)d_in[13], (const float*)d_in[15], (const float*)d_in[17]}};
    const float* cb[2][4] = {
        {(const float*)d_in[4],  (const float*)d_in[6],  (const float*)d_in[8],  (const float*)d_in[10]},
        {(const float*)d_in[12], (const float*)d_in[14], (const float*)d_in[16], (const float*)d_in[18]}};
    const float* wih0  = (const float*)d_in[19];
    const float* whh0  = (const float*)d_in[20];
    const float* bih0  = (const float*)d_in[21];
    const float* bhh0  = (const float*)d_in[22];
    const float* wih_r = (const float*)d_in[23];
    const float* whh_r = (const float*)d_in[24];
    const float* bih_r = (const float*)d_in[25];
    const float* bhh_r = (const float*)d_in[26];
    const float* out_w = (const float*)d_in[27];
    const float* out_b = (const float*)d_in[28];
    float* out = (float*)d_out;

    __half2 *bufA, *bufB, *wt;
    float *imgf, *h0, *h1, *c0, *c1;
    cudaGetSymbolAddress((void**)&bufA, g_bufA);
    cudaGetSymbolAddress((void**)&bufB, g_bufB);
    cudaGetSymbolAddress((void**)&imgf, g_img);
    cudaGetSymbolAddress((void**)&h0,   g_h0);
    cudaGetSymbolAddress((void**)&h1,   g_h1);
    cudaGetSymbolAddress((void**)&c0,   g_c0);
    cudaGetSymbolAddress((void**)&c1,   g_c1);
    cudaGetSymbolAddress((void**)&wt,   g_wt);

    const size_t szL2 = 144 * 64, szL3 = 288 * 128, szL4 = 576 * 16;
    const size_t camw = szL2 + szL3 + szL4;

    const int SMEM_L23 = 8 * (3 * SROW2) * 4;        // 13056 B
    const int SMEM_L4  = 8 * (6 * SROW2 + 8) * 4;    // 26368 B

    for (int cam = 0; cam < 2; cam++) {
        const float* src = cam ? im_s : im_m;
        __half2* wt2 = wt + cam * camw;
        __half2* wt3 = wt2 + szL2;
        __half2* wt4 = wt3 + szL3;

        // Launch order chosen so the 4th kernel launch overall (cam 0) is
        // conv_mma_kernel (L2) — that is the launch ncu's fixed -s/-c window captures.
        conv3x3_relu_kernel<<<dim3(32, 4, NIMG), 128, 3 * 72 * 4>>>(src, cw[cam][0], cb[cam][0], bufA, 3, 32);
        wt_transform_kernel<<<(int)((szL2 + 255) / 256), 256>>>(cw[cam][1], wt2, 32,  64);
        wt_transform_kernel<<<(int)((szL3 + 255) / 256), 256>>>(cw[cam][2], wt3, 64,  128);

        // L2: Cin=32 (16 planes in bufA), Cout=64 -> bufB   [4th launch on cam 0]
        conv_mma_kernel<<<dim3(128, 1, NIMG), 256, SMEM_L23>>>(bufA, wt2, cb[cam][1], bufB, 32, 64, 64, 2);

        wt_transform_kernel<<<(int)((szL4 + 255) / 256), 256>>>(cw[cam][3], wt4, 128, 16);

        // L3: Cin=64 (bufB), Cout=128 -> bufA
        conv_mma_kernel<<<dim3(128, 2, NIMG), 256, SMEM_L23>>>(bufB, wt3, cb[cam][2], bufA, 64, 128, 64, 2);
        // L4: Cin=128 (bufA), Cout=16 -> bufB
        conv_mma_kernel<<<dim3(32, 1, NIMG), 256, SMEM_L4>>>(bufA, wt4, cb[cam][3], bufB, 128, 16, 16, 8);

        spatial_softmax_kernel<<<dim3(NCH / 2, NIMG), 256>>>(bufB, imgf, cam ? 32 : 0);
    }

    // ---- LSTM ----
    cudaMemsetAsync(h0, 0, (size_t)LL * BB * HID * sizeof(float));
    cudaMemsetAsync(c0, 0, (size_t)LL * BB * HID * sizeof(float));

    for (int t = 0; t < TT; t++) {
        float* hp = (t & 1) ? h1 : h0;
        float* hc = (t & 1) ? h0 : h1;
        float* cp = (t & 1) ? c1 : c0;
        float* cc = (t & 1) ? c0 : c1;
        for (int l = 0; l < LL; l++) {
            const float *x1, *wi, *wh, *bi, *bh;
            int d1, bs1;
            if (l == 0) {
                x1 = states + t * SS; d1 = SS; bs1 = TT * SS;
                wi = wih0; wh = whh0; bi = bih0; bh = bhh0;
            } else {
                x1 = hc + (size_t)(l - 1) * BB * HID; d1 = HID; bs1 = HID;
                wi = wih_r + (size_t)(l - 1) * 4 * HID * 576;
                wh = whh_r + (size_t)(l - 1) * 4 * HID * HID;
                bi = bih_r + (size_t)(l - 1) * 4 * HID;
                bh = bhh_r + (size_t)(l - 1) * 4 * HID;
            }
            lstm_cell_kernel<<<256, 256>>>(
                x1, d1, bs1,
                imgf + t * 64, 64, TT * 64,
                hp + (size_t)l * BB * HID, cp + (size_t)l * BB * HID,
                wi, wh, bi, bh,
                hc + (size_t)l * BB * HID, cc + (size_t)l * BB * HID);
        }
        out_proj_kernel<<<1, 768>>>(hc + (size_t)5 * BB * HID, imgf, out_w, out_b, out, t);
    }
}

// round 9
// speedup vs baseline: 3.0572x; 1.0411x over previous
#include <cuda_runtime.h>
#include <cuda_fp16.h>
#include <math.h>
#include <stdint.h>

#define IMG   128
#define NPIX  16384
#define NIMG  40
#define BB    4
#define TT    10
#define SS    6
#define AA    6
#define HID   512
#define LL    6
#define NCH   16
#define SROW2 136   // half2 elements per slab row (data at [4..131], halo [3],[132])

// ---------------- scratch ----------------
__device__ __half2 g_bufA[(size_t)NIMG * 64 * NPIX];   // up to 128 ch (64 planes)
__device__ __half2 g_bufB[(size_t)NIMG * 32 * NPIX];   // up to 64 ch
__device__ float   g_img [BB * TT * 64];
__device__ float   g_h0[LL * BB * HID];
__device__ float   g_h1[LL * BB * HID];
__device__ float   g_c0[LL * BB * HID];
__device__ float   g_c1[LL * BB * HID];
// paired-B half2 weights per cam: [c][icb][kk][oc][p], sizes L2 144x64, L3 288x128, L4 576x16
__device__ __half2 g_wt[2 * (144 * 64 + 288 * 128 + 576 * 16)];

__device__ __forceinline__ void mma_f16(float* d,
                                        uint32_t a0, uint32_t a1, uint32_t a2, uint32_t a3,
                                        uint32_t b0, uint32_t b1) {
    asm volatile(
        "mma.sync.aligned.m16n8k16.row.col.f32.f16.f16.f32 "
        "{%0,%1,%2,%3}, {%4,%5,%6,%7}, {%8,%9}, {%0,%1,%2,%3};"
        : "+f"(d[0]), "+f"(d[1]), "+f"(d[2]), "+f"(d[3])
        : "r"(a0), "r"(a1), "r"(a2), "r"(a3), "r"(b0), "r"(b1));
}

// ================ weight transform: [oc][ic][3][3] -> paired-B layout ================
// half2 element index: (((c*nicb + icb)*4 + kk)*Cout + oc)*2 + p
// channels of that half2: ic = icb*16 + 2*(kk + 4*p), ic+1
__global__ void wt_transform_kernel(const float* __restrict__ w, __half2* __restrict__ wt2,
                                    int Cin, int Cout) {
    int idx = blockIdx.x * 256 + threadIdx.x;
    int tot = (9 * Cin / 2) * Cout;
    if (idx >= tot) return;
    int nicb = Cin >> 4;
    int p  = idx & 1;
    int t  = idx >> 1;
    int oc = t % Cout;  t /= Cout;
    int kk = t & 3;     t >>= 2;
    int icb = t % nicb;
    int c   = t / nicb;
    int ic0 = icb * 16 + 2 * (kk + 4 * p);
    float w0 = w[(oc * Cin + ic0) * 9 + c];
    float w1 = w[(oc * Cin + ic0 + 1) * 9 + c];
    wt2[idx] = __floats2half2_rn(w0, w1);
}

// ================ fp16 mma.sync implicit-GEMM 3x3 SAME conv + bias + relu ================
// warp tile: (MF*16) px x (NF*8) oc. CTA: WPX px-warps x (8/WPX) oc-warps.
template<int MF, int NF, int WPX>
__global__ void __launch_bounds__(256)
conv_mma_kernel(const __half2* __restrict__ in, const __half2* __restrict__ wt2,
                const float* __restrict__ bias, __half2* __restrict__ out,
                int Cin, int Cout) {
    extern __shared__ __align__(16) uint32_t smu[];
    const int tid  = threadIdx.x;
    const int lane = tid & 31;
    const int wid  = tid >> 5;

    constexpr int rows  = (WPX * MF * 16) >> 7;   // image rows per CTA
    constexpr int slabR = rows + 2;
    constexpr int plane0 = slabR * SROW2;
    constexpr int plane  = ((plane0 & 31) == 16) ? plane0 + 8 : plane0;  // plane%32==24

    const int n   = blockIdx.z;
    const int y0  = blockIdx.x * rows;
    const int oc0 = blockIdx.y * ((8 / WPX) * NF * 8);

    const int wpx = wid % WPX;
    const int woc = wid / WPX;
    const int pxbase = wpx * (MF * 16);
    const int ocb    = woc * (NF * 8);

    const int kk = lane & 3;
    const int qr = lane >> 2;

    float d[MF][NF][4];
    #pragma unroll
    for (int mf = 0; mf < MF; mf++)
        #pragma unroll
        for (int j = 0; j < NF; j++)
            #pragma unroll
            for (int r = 0; r < 4; r++) d[mf][j][r] = 0.f;

    const int nicb = Cin >> 4;
    const int np   = Cin >> 1;

    for (int icb = 0; icb < nicb; icb++) {
        __syncthreads();

        // ---- stage slab: 8 planes x slabR rows x 32 x (4 half2) ----
        {
            const int perp = slabR * 32;
            const int tot  = 8 * perp;
            for (int i = tid; i < tot; i += 256) {
                int q   = i / perp;
                int rem = i - q * perp;
                int r   = rem >> 5;
                int x0  = (rem & 31) << 2;
                int y   = y0 + r - 1;
                uint4 v = make_uint4(0u, 0u, 0u, 0u);
                if (y >= 0 && y < IMG)
                    v = *reinterpret_cast<const uint4*>(
                        in + ((size_t)(n * np + icb * 8 + q)) * NPIX + y * IMG + x0);
                *reinterpret_cast<uint4*>(smu + q * plane + r * SROW2 + 4 + x0) = v;
            }
            for (int i = tid; i < 8 * slabR; i += 256) {
                int q = i / slabR, r = i - q * slabR;
                smu[q * plane + r * SROW2 + 3]   = 0u;
                smu[q * plane + r * SROW2 + 132] = 0u;
            }
        }
        __syncthreads();

        #pragma unroll
        for (int c = 0; c < 9; c++) {
            const int ky = c / 3, kx = c - (c / 3) * 3;

            // B fragments: one LDG.64 each (kpairs kk and kk+4 adjacent in layout)
            uint2 bf[NF];
            {
                const uint2* wb = reinterpret_cast<const uint2*>(wt2)
                                  + ((size_t)(c * nicb + icb) * 4 + kk) * Cout
                                  + oc0 + ocb + qr;
                #pragma unroll
                for (int j = 0; j < NF; j++) bf[j] = __ldg(wb + j * 8);
            }

            #pragma unroll
            for (int mf = 0; mf < MF; mf++) {
                int px = pxbase + mf * 16 + qr;
                int pr = px >> 7, x = px & 127;
                int base = (pr + ky) * SROW2 + 3 + x + kx;
                uint32_t a0 = smu[kk * plane + base];
                uint32_t a1 = smu[kk * plane + base + 8];
                uint32_t a2 = smu[(kk + 4) * plane + base];
                uint32_t a3 = smu[(kk + 4) * plane + base + 8];
                #pragma unroll
                for (int j = 0; j < NF; j++)
                    mma_f16(d[mf][j], a0, a1, a2, a3, bf[j].x, bf[j].y);
            }
        }
    }

    // ---- epilogue: bias + relu + half2 store ----
    #pragma unroll
    for (int j = 0; j < NF; j++) {
        int oc = oc0 + ocb + j * 8 + 2 * kk;
        float bv0 = bias[oc], bv1 = bias[oc + 1];
        #pragma unroll
        for (int mf = 0; mf < MF; mf++) {
            int px = pxbase + mf * 16 + qr;
            int pr = px >> 7, x = px & 127;
            __half2* o0 = out + ((size_t)(n * (Cout >> 1) + (oc >> 1))) * NPIX
                          + (y0 + pr) * IMG + x;
            o0[0] = __floats2half2_rn(fmaxf(d[mf][j][0] + bv0, 0.f),
                                      fmaxf(d[mf][j][1] + bv1, 0.f));
            o0[8] = __floats2half2_rn(fmaxf(d[mf][j][2] + bv0, 0.f),
                                      fmaxf(d[mf][j][3] + bv1, 0.f));
        }
    }
}

// ---------------- fp32 direct conv (layer 1, Cin=3) -> half2 output ----------------
__global__ void conv3x3_relu_kernel(const float* __restrict__ in,
                                    const float* __restrict__ w,
                                    const float* __restrict__ bias,
                                    __half2* __restrict__ out,
                                    int Cin, int Cout) {
    extern __shared__ float sw[];
    const int tid  = threadIdx.x;
    const int lane = tid & 31;
    const int warp = tid >> 5;
    const int ocg  = blockIdx.y;
    const int n    = blockIdx.z;

    const int nw = Cin * 72;
    const float* wbase = w + (size_t)ocg * 8 * Cin * 9;
    for (int i = tid; i < nw; i += blockDim.x) {
        int o = i & 7, rest = i >> 3;
        sw[i] = wbase[(size_t)o * Cin * 9 + rest];
    }
    __syncthreads();

    const int y  = blockIdx.x * 4 + warp;
    const int x0 = lane * 4;

    float acc[8][4];
    #pragma unroll
    for (int o = 0; o < 8; o++) {
        float bv = bias[ocg * 8 + o];
        #pragma unroll
        for (int p = 0; p < 4; p++) acc[o][p] = bv;
    }

    for (int ic = 0; ic < Cin; ic++) {
        const float* ip = in + (size_t)(n * Cin + ic) * NPIX;
        float v[3][6];
        #pragma unroll
        for (int r = 0; r < 3; r++) {
            int yy = y - 1 + r;
            float4 m = make_float4(0.f, 0.f, 0.f, 0.f);
            if (yy >= 0 && yy < IMG)
                m = *reinterpret_cast<const float4*>(ip + yy * IMG + x0);
            float left  = __shfl_up_sync(0xffffffffu, m.w, 1);
            float right = __shfl_down_sync(0xffffffffu, m.x, 1);
            if (lane == 0)  left  = 0.f;
            if (lane == 31) right = 0.f;
            v[r][0] = left; v[r][1] = m.x; v[r][2] = m.y;
            v[r][3] = m.z;  v[r][4] = m.w; v[r][5] = right;
        }
        const float* wp = sw + ic * 72;
        #pragma unroll
        for (int ky = 0; ky < 3; ky++)
        #pragma unroll
        for (int kx = 0; kx < 3; kx++) {
            const float* wq = wp + (ky * 3 + kx) * 8;
            #pragma unroll
            for (int o = 0; o < 8; o++) {
                float wv = wq[o];
                #pragma unroll
                for (int p = 0; p < 4; p++)
                    acc[o][p] = fmaf(v[ky][kx + p], wv, acc[o][p]);
            }
        }
    }

    #pragma unroll
    for (int o = 0; o < 8; o += 2) {
        __half2 h[4];
        #pragma unroll
        for (int p = 0; p < 4; p++)
            h[p] = __floats2half2_rn(fmaxf(acc[o][p], 0.f), fmaxf(acc[o + 1][p], 0.f));
        int pl = (ocg * 8 + o) >> 1;
        *reinterpret_cast<uint4*>(
            out + ((size_t)(n * (Cout >> 1) + pl)) * NPIX + y * IMG + x0) =
            *reinterpret_cast<uint4*>(h);
    }
}

// ---------------- spatial softmax: one block per half2 plane (2 channels) ----------------
__global__ void spatial_softmax_kernel(const __half2* __restrict__ x,
                                       float* __restrict__ img, int base) {
    const int pl = blockIdx.x;
    const int n  = blockIdx.y;
    const __half2* p = x + (size_t)(n * (NCH / 2) + pl) * NPIX;
    __shared__ float rA[256], rB[256], rC[256], rD[256], rE[256], rF[256];
    const int tid = threadIdx.x;

    float m0 = -1e30f, m1 = -1e30f;
    for (int i = tid; i < NPIX; i += 256) {
        __half2 v = p[i];
        m0 = fmaxf(m0, __low2float(v));
        m1 = fmaxf(m1, __high2float(v));
    }
    rA[tid] = m0; rB[tid] = m1; __syncthreads();
    for (int s = 128; s > 0; s >>= 1) {
        if (tid < s) {
            rA[tid] = fmaxf(rA[tid], rA[tid + s]);
            rB[tid] = fmaxf(rB[tid], rB[tid + s]);
        }
        __syncthreads();
    }
    m0 = rA[0]; m1 = rB[0];
    __syncthreads();

    float s0 = 0.f, sx0 = 0.f, sy0 = 0.f;
    float s1 = 0.f, sx1 = 0.f, sy1 = 0.f;
    for (int i = tid; i < NPIX; i += 256) {
        __half2 v = p[i];
        float e0 = __expf(__low2float(v)  - m0);
        float e1 = __expf(__high2float(v) - m1);
        int yy = i >> 7, xx = i & 127;
        float px = -1.f + (2.f / 127.f) * (float)xx;
        float py = -1.f + (2.f / 127.f) * (float)yy;
        s0 += e0; sx0 += e0 * px; sy0 += e0 * py;
        s1 += e1; sx1 += e1 * px; sy1 += e1 * py;
    }
    rA[tid] = s0; rB[tid] = sx0; rC[tid] = sy0;
    rD[tid] = s1; rE[tid] = sx1; rF[tid] = sy1;
    __syncthreads();
    for (int st = 128; st > 0; st >>= 1) {
        if (tid < st) {
            rA[tid] += rA[tid + st]; rB[tid] += rB[tid + st]; rC[tid] += rC[tid + st];
            rD[tid] += rD[tid + st]; rE[tid] += rE[tid + st]; rF[tid] += rF[tid + st];
        }
        __syncthreads();
    }
    if (tid == 0) {
        float inv0 = 1.f / rA[0];
        float inv1 = 1.f / rD[0];
        int ch0 = 2 * pl, ch1 = 2 * pl + 1;
        img[n * 64 + base + 2 * ch0]     = rB[0] * inv0;
        img[n * 64 + base + 2 * ch0 + 1] = rC[0] * inv0;
        img[n * 64 + base + 2 * ch1]     = rE[0] * inv1;
        img[n * 64 + base + 2 * ch1 + 1] = rF[0] * inv1;
    }
}

// ---------------- fused LSTM cell (wide) ----------------
__global__ void __launch_bounds__(256)
lstm_cell_kernel(const float* __restrict__ x1, int d1, int x1_bs,
                 const float* __restrict__ x2, int d2, int x2_bs,
                 const float* __restrict__ hprev,
                 const float* __restrict__ cprev,
                 const float* __restrict__ wih,
                 const float* __restrict__ whh,
                 const float* __restrict__ bih,
                 const float* __restrict__ bhh,
                 float* __restrict__ hout,
                 float* __restrict__ cout) {
    __shared__ __align__(16) float sx[BB * 576];
    __shared__ __align__(16) float sh[BB * HID];
    __shared__ float gate[8][4];
    const int d   = d1 + d2;
    const int tid = threadIdx.x;

    for (int i = tid; i < BB * d; i += 256) {
        int b = i / d, k = i - b * d;
        sx[i] = (k < d1) ? x1[b * x1_bs + k] : x2[b * x2_bs + (k - d1)];
    }
    for (int i = tid; i < BB * HID; i += 256) sh[i] = hprev[i];
    __syncthreads();

    const int lane = tid & 31;
    const int w    = tid >> 5;
    const int jl   = w >> 2;
    const int g    = w & 3;
    const int j    = blockIdx.x * 2 + jl;

    float acc[4] = {0.f, 0.f, 0.f, 0.f};

    const float* wr = wih + (size_t)(g * HID + j) * d;
    if ((d & 3) == 0) {
        for (int k = lane * 4; k < d; k += 128) {
            float4 wv = *reinterpret_cast<const float4*>(wr + k);
            #pragma unroll
            for (int b = 0; b < 4; b++) {
                float4 xv = *reinterpret_cast<const float4*>(sx + b * d + k);
                acc[b] = fmaf(wv.x, xv.x, acc[b]);
                acc[b] = fmaf(wv.y, xv.y, acc[b]);
                acc[b] = fmaf(wv.z, xv.z, acc[b]);
                acc[b] = fmaf(wv.w, xv.w, acc[b]);
            }
        }
    } else {
        for (int k = lane; k < d; k += 32) {
            float wv = wr[k];
            #pragma unroll
            for (int b = 0; b < 4; b++)
                acc[b] = fmaf(sx[b * d + k], wv, acc[b]);
        }
    }

    const float* w2 = whh + (size_t)(g * HID + j) * HID;
    #pragma unroll
    for (int k4 = 0; k4 < 4; k4++) {
        int k = lane * 4 + k4 * 128;
        float4 wv = *reinterpret_cast<const float4*>(w2 + k);
        #pragma unroll
        for (int b = 0; b < 4; b++) {
            float4 hv = *reinterpret_cast<const float4*>(sh + b * HID + k);
            acc[b] = fmaf(wv.x, hv.x, acc[b]);
            acc[b] = fmaf(wv.y, hv.y, acc[b]);
            acc[b] = fmaf(wv.z, hv.z, acc[b]);
            acc[b] = fmaf(wv.w, hv.w, acc[b]);
        }
    }

    #pragma unroll
    for (int b = 0; b < 4; b++) {
        #pragma unroll
        for (int off = 16; off > 0; off >>= 1)
            acc[b] += __shfl_xor_sync(0xffffffffu, acc[b], off);
    }
    if (lane == 0) {
        gate[w][0] = acc[0]; gate[w][1] = acc[1];
        gate[w][2] = acc[2]; gate[w][3] = acc[3];
    }
    __syncthreads();

    if (tid < 8) {
        int jj = tid >> 2, b = tid & 3;
        int jg = blockIdx.x * 2 + jj;
        float gi = gate[jj * 4 + 0][b] + bih[jg]           + bhh[jg];
        float gf = gate[jj * 4 + 1][b] + bih[HID + jg]     + bhh[HID + jg];
        float gg = gate[jj * 4 + 2][b] + bih[2 * HID + jg] + bhh[2 * HID + jg];
        float go = gate[jj * 4 + 3][b] + bih[3 * HID + jg] + bhh[3 * HID + jg];
        float si = 1.f / (1.f + expf(-gi));
        float sf = 1.f / (1.f + expf(-gf));
        float tg = tanhf(gg);
        float so = 1.f / (1.f + expf(-go));
        float c2 = sf * cprev[b * HID + jg] + si * tg;
        float h2 = so * tanhf(c2);
        hout[b * HID + jg] = h2;
        cout[b * HID + jg] = c2;
    }
}

// ---------------- output projection ----------------
__global__ void out_proj_kernel(const float* __restrict__ h,
                                const float* __restrict__ imgf,
                                const float* __restrict__ out_w,
                                const float* __restrict__ out_b,
                                float* __restrict__ out, int t) {
    const int wid  = threadIdx.x >> 5;
    const int lane = threadIdx.x & 31;
    if (wid >= BB * AA) return;
    const int b = wid / AA, a = wid % AA;
    const float* row = out_w + a * 576;
    float acc = 0.f;
    for (int k = lane; k < 576; k += 32) {
        float x = (k < HID) ? h[b * HID + k] : imgf[(b * TT + t) * 64 + (k - HID)];
        acc = fmaf(row[k], x, acc);
    }
    #pragma unroll
    for (int off = 16; off > 0; off >>= 1)
        acc += __shfl_xor_sync(0xffffffffu, acc, off);
    if (lane == 0) out[(b * TT + t) * AA + a] = acc + out_b[a];
}

// ---------------- host orchestration ----------------
extern "C" void kernel_launch(void* const* d_in, const int* in_sizes, int n_in,
                              void* d_out, int out_size) {
    (void)in_sizes; (void)n_in; (void)out_size;

    const float* im_m   = (const float*)d_in[0];
    const float* im_s   = (const float*)d_in[1];
    const float* states = (const float*)d_in[2];
    const float* cw[2][4] = {
        {(const float*)d_in[3],  (const float*)d_in[5],  (const float*)d_in[7],  (const float*)d_in[9]},
        {(const float*)d_in[11], (const float*)d_in[13], (const float*)d_in[15], (const float*)d_in[17]}};
    const float* cb[2][4] = {
        {(const float*)d_in[4],  (const float*)d_in[6],  (const float*)d_in[8],  (const float*)d_in[10]},
        {(const float*)d_in[12], (const float*)d_in[14], (const float*)d_in[16], (const float*)d_in[18]}};
    const float* wih0  = (const float*)d_in[19];
    const float* whh0  = (const float*)d_in[20];
    const float* bih0  = (const float*)d_in[21];
    const float* bhh0  = (const float*)d_in[22];
    const float* wih_r = (const float*)d_in[23];
    const float* whh_r = (const float*)d_in[24];
    const float* bih_r = (const float*)d_in[25];
    const float* bhh_r = (const float*)d_in[26];
    const float* out_w = (const float*)d_in[27];
    const float* out_b = (const float*)d_in[28];
    float* out = (float*)d_out;

    __half2 *bufA, *bufB, *wt;
    float *imgf, *h0, *h1, *c0, *c1;
    cudaGetSymbolAddress((void**)&bufA, g_bufA);
    cudaGetSymbolAddress((void**)&bufB, g_bufB);
    cudaGetSymbolAddress((void**)&imgf, g_img);
    cudaGetSymbolAddress((void**)&h0,   g_h0);
    cudaGetSymbolAddress((void**)&h1,   g_h1);
    cudaGetSymbolAddress((void**)&c0,   g_c0);
    cudaGetSymbolAddress((void**)&c1,   g_c1);
    cudaGetSymbolAddress((void**)&wt,   g_wt);

    const size_t szL2 = 144 * 64, szL3 = 288 * 128, szL4 = 576 * 16;
    const size_t camw = szL2 + szL3 + szL4;

    const int SMEM_L23 = 8 * (3 * SROW2) * 4;        // 13056 B (plane 408)
    const int SMEM_L4  = 8 * (6 * SROW2 + 8) * 4;    // 26368 B (plane 824)

    for (int cam = 0; cam < 2; cam++) {
        const float* src = cam ? im_s : im_m;
        __half2* wt2 = wt + cam * camw;
        __half2* wt3 = wt2 + szL2;
        __half2* wt4 = wt3 + szL3;

        // keep conv_mma (L2) as the 4th launch overall for ncu's capture slot
        conv3x3_relu_kernel<<<dim3(32, 4, NIMG), 128, 3 * 72 * 4>>>(src, cw[cam][0], cb[cam][0], bufA, 3, 32);
        wt_transform_kernel<<<(int)((szL2 + 255) / 256), 256>>>(cw[cam][1], wt2, 32,  64);
        wt_transform_kernel<<<(int)((szL3 + 255) / 256), 256>>>(cw[cam][2], wt3, 64,  128);

        // L2: Cin=32 -> Cout=64. MF=2,NF=4,WPX=4: CTA 128px x 64oc, 1 row
        conv_mma_kernel<2, 4, 4><<<dim3(128, 1, NIMG), 256, SMEM_L23>>>(bufA, wt2, cb[cam][1], bufB, 32, 64);

        wt_transform_kernel<<<(int)((szL4 + 255) / 256), 256>>>(cw[cam][3], wt4, 128, 16);

        // L3: Cin=64 -> Cout=128
        conv_mma_kernel<2, 4, 4><<<dim3(128, 2, NIMG), 256, SMEM_L23>>>(bufB, wt3, cb[cam][2], bufA, 64, 128);
        // L4: Cin=128 -> Cout=16. MF=4,NF=2,WPX=8: CTA 512px x 16oc, 4 rows
        conv_mma_kernel<4, 2, 8><<<dim3(32, 1, NIMG), 256, SMEM_L4>>>(bufA, wt4, cb[cam][3], bufB, 128, 16);

        spatial_softmax_kernel<<<dim3(NCH / 2, NIMG), 256>>>(bufB, imgf, cam ? 32 : 0);
    }

    // ---- LSTM ----
    cudaMemsetAsync(h0, 0, (size_t)LL * BB * HID * sizeof(float));
    cudaMemsetAsync(c0, 0, (size_t)LL * BB * HID * sizeof(float));

    for (int t = 0; t < TT; t++) {
        float* hp = (t & 1) ? h1 : h0;
        float* hc = (t & 1) ? h0 : h1;
        float* cp = (t & 1) ? c1 : c0;
        float* cc = (t & 1) ? c0 : c1;
        for (int l = 0; l < LL; l++) {
            const float *x1, *wi, *wh, *bi, *bh;
            int d1, bs1;
            if (l == 0) {
                x1 = states + t * SS; d1 = SS; bs1 = TT * SS;
                wi = wih0; wh = whh0; bi = bih0; bh = bhh0;
            } else {
                x1 = hc + (size_t)(l - 1) * BB * HID; d1 = HID; bs1 = HID;
                wi = wih_r + (size_t)(l - 1) * 4 * HID * 576;
                wh = whh_r + (size_t)(l - 1) * 4 * HID * HID;
                bi = bih_r + (size_t)(l - 1) * 4 * HID;
                bh = bhh_r + (size_t)(l - 1) * 4 * HID;
            }
            lstm_cell_kernel<<<256, 256>>>(
                x1, d1, bs1,
                imgf + t * 64, 64, TT * 64,
                hp + (size_t)l * BB * HID, cp + (size_t)l * BB * HID,
                wi, wh, bi, bh,
                hc + (size_t)l * BB * HID, cc + (size_t)l * BB * HID);
        }
        out_proj_kernel<<<1, 768>>>(hc + (size_t)5 * BB * HID, imgf, out_w, out_b, out, t);
    }
}

// round 10
// speedup vs baseline: 3.7581x; 1.2293x over previous
#include <cuda_runtime.h>
#include <cuda_fp16.h>
#include <math.h>
#include <stdint.h>

#define IMG   128
#define NPIX  16384
#define NIMG  40
#define BB    4
#define TT    10
#define SS    6
#define AA    6
#define HID   512
#define LL    6
#define NCH   16
#define SROW2 136   // half2 elements per slab row (data at [4..131], halo [3],[132])

// ---------------- scratch ----------------
__device__ __half2 g_bufA[(size_t)NIMG * 64 * NPIX];
__device__ __half2 g_bufB[(size_t)NIMG * 32 * NPIX];
__device__ float   g_img [BB * TT * 64];
__device__ float   g_h0[LL * BB * HID];
__device__ float   g_h1[LL * BB * HID];
__device__ float   g_c0[LL * BB * HID];
__device__ float   g_c1[LL * BB * HID];
// paired-B half2 weights per cam: [c][icb][kk][oc][p]
__device__ __half2 g_wt[2 * (144 * 64 + 288 * 128 + 576 * 16)];

__device__ __forceinline__ void mma_f16(float* d,
                                        uint32_t a0, uint32_t a1, uint32_t a2, uint32_t a3,
                                        uint32_t b0, uint32_t b1) {
    asm volatile(
        "mma.sync.aligned.m16n8k16.row.col.f32.f16.f16.f32 "
        "{%0,%1,%2,%3}, {%4,%5,%6,%7}, {%8,%9}, {%0,%1,%2,%3};"
        : "+f"(d[0]), "+f"(d[1]), "+f"(d[2]), "+f"(d[3])
        : "r"(a0), "r"(a1), "r"(a2), "r"(a3), "r"(b0), "r"(b1));
}

// ================ weight transform: [oc][ic][3][3] -> paired-B layout ================
// half2 element index: (((c*nicb + icb)*4 + kk)*Cout + oc)*2 + p
__global__ void wt_transform_kernel(const float* __restrict__ w, __half2* __restrict__ wt2,
                                    int Cin, int Cout) {
    int idx = blockIdx.x * 256 + threadIdx.x;
    int tot = (9 * Cin / 2) * Cout;
    if (idx >= tot) return;
    int nicb = Cin >> 4;
    int p  = idx & 1;
    int t  = idx >> 1;
    int oc = t % Cout;  t /= Cout;
    int kk = t & 3;     t >>= 2;
    int icb = t % nicb;
    int c   = t / nicb;
    int ic0 = icb * 16 + 2 * (kk + 4 * p);
    float w0 = w[(oc * Cin + ic0) * 9 + c];
    float w1 = w[(oc * Cin + ic0 + 1) * 9 + c];
    wt2[idx] = __floats2half2_rn(w0, w1);
}

// ================ fp16 mma.sync implicit-GEMM 3x3 SAME conv + bias + relu ================
// 8 warps, all sharing ONE oc tile of NF*8 columns (no cross-warp A or B duplication).
// warp tile: (MF*16) px x (NF*8) oc. CTA: 128*MF px = MF image rows.
// B is staged into padded smem once per ic-block (coalesced), then read as LDS.64.
template<int MF, int NF>
__global__ void __launch_bounds__(256)
conv_mma_kernel(const __half2* __restrict__ in, const __half2* __restrict__ wt2,
                const float* __restrict__ bias, __half2* __restrict__ out,
                int Cin, int Cout) {
    extern __shared__ __align__(16) uint32_t smu[];
    const int tid  = threadIdx.x;
    const int lane = tid & 31;
    const int wid  = tid >> 5;

    constexpr int rows   = MF;               // 8 warps * MF*16 px / 128
    constexpr int slabR  = rows + 2;
    constexpr int plane0 = slabR * SROW2;
    constexpr int plane  = plane0 + ((24 - (plane0 & 31)) & 31);  // plane%32==24
    constexpr int ocT    = NF * 8;
    constexpr int strideB = ocT + 4;         // uint2 units; (ocT+4)%16==4 -> conflict-free
    constexpr int sboff32 = 8 * plane;       // plane%32==24 -> even, uint2-aligned

    uint2* sB = reinterpret_cast<uint2*>(smu + sboff32);

    const int n   = blockIdx.z;
    const int y0  = blockIdx.x * rows;
    const int oc0 = blockIdx.y * ocT;

    const int pxbase = wid * (MF * 16);
    const int kk = lane & 3;
    const int qr = lane >> 2;

    float d[MF][NF][4];
    #pragma unroll
    for (int mf = 0; mf < MF; mf++)
        #pragma unroll
        for (int j = 0; j < NF; j++)
            #pragma unroll
            for (int r = 0; r < 4; r++) d[mf][j][r] = 0.f;

    const int nicb = Cin >> 4;
    const int np   = Cin >> 1;

    for (int icb = 0; icb < nicb; icb++) {
        __syncthreads();

        // ---- stage input slab: 8 planes x slabR rows ----
        {
            constexpr int perp = slabR * 32;
            constexpr int tot  = 8 * perp;
            for (int i = tid; i < tot; i += 256) {
                int q   = i / perp;
                int rem = i - q * perp;
                int r   = rem >> 5;
                int x0  = (rem & 31) << 2;
                int y   = y0 + r - 1;
                uint4 v = make_uint4(0u, 0u, 0u, 0u);
                if (y >= 0 && y < IMG)
                    v = *reinterpret_cast<const uint4*>(
                        in + ((size_t)(n * np + icb * 8 + q)) * NPIX + y * IMG + x0);
                *reinterpret_cast<uint4*>(smu + q * plane + r * SROW2 + 4 + x0) = v;
            }
            for (int i = tid; i < 8 * slabR; i += 256) {
                int q = i / slabR, r = i - q * slabR;
                smu[q * plane + r * SROW2 + 3]   = 0u;
                smu[q * plane + r * SROW2 + 132] = 0u;
            }
        }

        // ---- stage B slice (this CTA's ocT columns, all 9 c, 4 kk): coalesced ----
        {
            const uint2* gB = reinterpret_cast<const uint2*>(wt2)
                              + (size_t)icb * 4 * Cout + oc0;
            const size_t gcs = (size_t)nicb * 4 * Cout;
            for (int i = tid; i < 36 * ocT; i += 256) {
                int c   = i / (4 * ocT);
                int r   = i - c * 4 * ocT;
                int kkr = r / ocT, oc = r - kkr * ocT;
                sB[(c * 4 + kkr) * strideB + oc] = __ldg(gB + c * gcs + kkr * Cout + oc);
            }
        }
        __syncthreads();

        #pragma unroll
        for (int c = 0; c < 9; c++) {
            const int ky = c / 3, kx = c - (c / 3) * 3;

            uint2 bf[NF];
            #pragma unroll
            for (int j = 0; j < NF; j++)
                bf[j] = sB[(c * 4 + kk) * strideB + j * 8 + qr];

            #pragma unroll
            for (int mf = 0; mf < MF; mf++) {
                int px = pxbase + mf * 16 + qr;
                int pr = px >> 7, x = px & 127;
                int base = (pr + ky) * SROW2 + 3 + x + kx;
                uint32_t a0 = smu[kk * plane + base];
                uint32_t a1 = smu[kk * plane + base + 8];
                uint32_t a2 = smu[(kk + 4) * plane + base];
                uint32_t a3 = smu[(kk + 4) * plane + base + 8];
                #pragma unroll
                for (int j = 0; j < NF; j++)
                    mma_f16(d[mf][j], a0, a1, a2, a3, bf[j].x, bf[j].y);
            }
        }
    }

    // ---- epilogue: bias + relu + half2 store ----
    #pragma unroll
    for (int j = 0; j < NF; j++) {
        int oc = oc0 + j * 8 + 2 * kk;
        float bv0 = bias[oc], bv1 = bias[oc + 1];
        #pragma unroll
        for (int mf = 0; mf < MF; mf++) {
            int px = pxbase + mf * 16 + qr;
            int pr = px >> 7, x = px & 127;
            __half2* o0 = out + ((size_t)(n * (Cout >> 1) + (oc >> 1))) * NPIX
                          + (y0 + pr) * IMG + x;
            o0[0] = __floats2half2_rn(fmaxf(d[mf][j][0] + bv0, 0.f),
                                      fmaxf(d[mf][j][1] + bv1, 0.f));
            o0[8] = __floats2half2_rn(fmaxf(d[mf][j][2] + bv0, 0.f),
                                      fmaxf(d[mf][j][3] + bv1, 0.f));
        }
    }
}

// ---------------- fp32 direct conv (layer 1, Cin=3) -> half2 output ----------------
__global__ void conv3x3_relu_kernel(const float* __restrict__ in,
                                    const float* __restrict__ w,
                                    const float* __restrict__ bias,
                                    __half2* __restrict__ out,
                                    int Cin, int Cout) {
    extern __shared__ float sw[];
    const int tid  = threadIdx.x;
    const int lane = tid & 31;
    const int warp = tid >> 5;
    const int ocg  = blockIdx.y;
    const int n    = blockIdx.z;

    const int nw = Cin * 72;
    const float* wbase = w + (size_t)ocg * 8 * Cin * 9;
    for (int i = tid; i < nw; i += blockDim.x) {
        int o = i & 7, rest = i >> 3;
        sw[i] = wbase[(size_t)o * Cin * 9 + rest];
    }
    __syncthreads();

    const int y  = blockIdx.x * 4 + warp;
    const int x0 = lane * 4;

    float acc[8][4];
    #pragma unroll
    for (int o = 0; o < 8; o++) {
        float bv = bias[ocg * 8 + o];
        #pragma unroll
        for (int p = 0; p < 4; p++) acc[o][p] = bv;
    }

    for (int ic = 0; ic < Cin; ic++) {
        const float* ip = in + (size_t)(n * Cin + ic) * NPIX;
        float v[3][6];
        #pragma unroll
        for (int r = 0; r < 3; r++) {
            int yy = y - 1 + r;
            float4 m = make_float4(0.f, 0.f, 0.f, 0.f);
            if (yy >= 0 && yy < IMG)
                m = *reinterpret_cast<const float4*>(ip + yy * IMG + x0);
            float left  = __shfl_up_sync(0xffffffffu, m.w, 1);
            float right = __shfl_down_sync(0xffffffffu, m.x, 1);
            if (lane == 0)  left  = 0.f;
            if (lane == 31) right = 0.f;
            v[r][0] = left; v[r][1] = m.x; v[r][2] = m.y;
            v[r][3] = m.z;  v[r][4] = m.w; v[r][5] = right;
        }
        const float* wp = sw + ic * 72;
        #pragma unroll
        for (int ky = 0; ky < 3; ky++)
        #pragma unroll
        for (int kx = 0; kx < 3; kx++) {
            const float* wq = wp + (ky * 3 + kx) * 8;
            #pragma unroll
            for (int o = 0; o < 8; o++) {
                float wv = wq[o];
                #pragma unroll
                for (int p = 0; p < 4; p++)
                    acc[o][p] = fmaf(v[ky][kx + p], wv, acc[o][p]);
            }
        }
    }

    #pragma unroll
    for (int o = 0; o < 8; o += 2) {
        __half2 h[4];
        #pragma unroll
        for (int p = 0; p < 4; p++)
            h[p] = __floats2half2_rn(fmaxf(acc[o][p], 0.f), fmaxf(acc[o + 1][p], 0.f));
        int pl = (ocg * 8 + o) >> 1;
        *reinterpret_cast<uint4*>(
            out + ((size_t)(n * (Cout >> 1) + pl)) * NPIX + y * IMG + x0) =
            *reinterpret_cast<uint4*>(h);
    }
}

// ---------------- spatial softmax: one block per half2 plane (2 channels) ----------------
__global__ void spatial_softmax_kernel(const __half2* __restrict__ x,
                                       float* __restrict__ img, int base) {
    const int pl = blockIdx.x;
    const int n  = blockIdx.y;
    const __half2* p = x + (size_t)(n * (NCH / 2) + pl) * NPIX;
    __shared__ float rA[256], rB[256], rC[256], rD[256], rE[256], rF[256];
    const int tid = threadIdx.x;

    float m0 = -1e30f, m1 = -1e30f;
    for (int i = tid; i < NPIX; i += 256) {
        __half2 v = p[i];
        m0 = fmaxf(m0, __low2float(v));
        m1 = fmaxf(m1, __high2float(v));
    }
    rA[tid] = m0; rB[tid] = m1; __syncthreads();
    for (int s = 128; s > 0; s >>= 1) {
        if (tid < s) {
            rA[tid] = fmaxf(rA[tid], rA[tid + s]);
            rB[tid] = fmaxf(rB[tid], rB[tid + s]);
        }
        __syncthreads();
    }
    m0 = rA[0]; m1 = rB[0];
    __syncthreads();

    float s0 = 0.f, sx0 = 0.f, sy0 = 0.f;
    float s1 = 0.f, sx1 = 0.f, sy1 = 0.f;
    for (int i = tid; i < NPIX; i += 256) {
        __half2 v = p[i];
        float e0 = __expf(__low2float(v)  - m0);
        float e1 = __expf(__high2float(v) - m1);
        int yy = i >> 7, xx = i & 127;
        float px = -1.f + (2.f / 127.f) * (float)xx;
        float py = -1.f + (2.f / 127.f) * (float)yy;
        s0 += e0; sx0 += e0 * px; sy0 += e0 * py;
        s1 += e1; sx1 += e1 * px; sy1 += e1 * py;
    }
    rA[tid] = s0; rB[tid] = sx0; rC[tid] = sy0;
    rD[tid] = s1; rE[tid] = sx1; rF[tid] = sy1;
    __syncthreads();
    for (int st = 128; st > 0; st >>= 1) {
        if (tid < st) {
            rA[tid] += rA[tid + st]; rB[tid] += rB[tid + st]; rC[tid] += rC[tid + st];
            rD[tid] += rD[tid + st]; rE[tid] += rE[tid + st]; rF[tid] += rF[tid + st];
        }
        __syncthreads();
    }
    if (tid == 0) {
        float inv0 = 1.f / rA[0];
        float inv1 = 1.f / rD[0];
        int ch0 = 2 * pl, ch1 = 2 * pl + 1;
        img[n * 64 + base + 2 * ch0]     = rB[0] * inv0;
        img[n * 64 + base + 2 * ch0 + 1] = rC[0] * inv0;
        img[n * 64 + base + 2 * ch1]     = rE[0] * inv1;
        img[n * 64 + base + 2 * ch1 + 1] = rF[0] * inv1;
    }
}

// ---------------- fused LSTM cell (wide, compile-time input width) ----------------
// D1 = width of x1 (6 for layer 0, 512 for layers 1..5); d = D1 + 64 known at compile time.
template<int D1>
__global__ void __launch_bounds__(256)
lstm_cell_kernel(const float* __restrict__ x1, int x1_bs,
                 const float* __restrict__ x2,
                 const float* __restrict__ hprev,
                 const float* __restrict__ cprev,
                 const float* __restrict__ wih,
                 const float* __restrict__ whh,
                 const float* __restrict__ bih,
                 const float* __restrict__ bhh,
                 float* __restrict__ hout,
                 float* __restrict__ cout) {
    constexpr int D = D1 + 64;
    __shared__ __align__(16) float sx[BB * D];
    __shared__ __align__(16) float sh[BB * HID];
    __shared__ float gate[8][4];
    const int tid = threadIdx.x;

    for (int i = tid; i < BB * D; i += 256) {
        int b = i / D, k = i - b * D;
        sx[i] = (k < D1) ? x1[b * x1_bs + k] : x2[b * (TT * 64) + (k - D1)];
    }
    for (int i = tid; i < BB * HID; i += 256) sh[i] = hprev[i];
    __syncthreads();

    const int lane = tid & 31;
    const int w    = tid >> 5;
    const int jl   = w >> 2;
    const int g    = w & 3;
    const int j    = blockIdx.x * 2 + jl;

    float acc[4] = {0.f, 0.f, 0.f, 0.f};

    const float* wr = wih + (size_t)(g * HID + j) * D;
    if (D == 576) {
        // 4 full float4 blocks + half block: all loads independent (MLP high)
        #pragma unroll
        for (int kb = 0; kb < 4; kb++) {
            int k = lane * 4 + kb * 128;
            float4 wv = *reinterpret_cast<const float4*>(wr + k);
            #pragma unroll
            for (int b = 0; b < 4; b++) {
                float4 xv = *reinterpret_cast<const float4*>(sx + b * D + k);
                acc[b] = fmaf(wv.x, xv.x, acc[b]);
                acc[b] = fmaf(wv.y, xv.y, acc[b]);
                acc[b] = fmaf(wv.z, xv.z, acc[b]);
                acc[b] = fmaf(wv.w, xv.w, acc[b]);
            }
        }
        if (lane < 16) {
            int k = 512 + lane * 4;
            float4 wv = *reinterpret_cast<const float4*>(wr + k);
            #pragma unroll
            for (int b = 0; b < 4; b++) {
                float4 xv = *reinterpret_cast<const float4*>(sx + b * D + k);
                acc[b] = fmaf(wv.x, xv.x, acc[b]);
                acc[b] = fmaf(wv.y, xv.y, acc[b]);
                acc[b] = fmaf(wv.z, xv.z, acc[b]);
                acc[b] = fmaf(wv.w, xv.w, acc[b]);
            }
        }
    } else {
        #pragma unroll
        for (int kb = 0; kb < (D + 31) / 32; kb++) {
            int k = lane + kb * 32;
            if (k < D) {
                float wv = wr[k];
                #pragma unroll
                for (int b = 0; b < 4; b++)
                    acc[b] = fmaf(sx[b * D + k], wv, acc[b]);
            }
        }
    }

    const float* w2 = whh + (size_t)(g * HID + j) * HID;
    #pragma unroll
    for (int k4 = 0; k4 < 4; k4++) {
        int k = lane * 4 + k4 * 128;
        float4 wv = *reinterpret_cast<const float4*>(w2 + k);
        #pragma unroll
        for (int b = 0; b < 4; b++) {
            float4 hv = *reinterpret_cast<const float4*>(sh + b * HID + k);
            acc[b] = fmaf(wv.x, hv.x, acc[b]);
            acc[b] = fmaf(wv.y, hv.y, acc[b]);
            acc[b] = fmaf(wv.z, hv.z, acc[b]);
            acc[b] = fmaf(wv.w, hv.w, acc[b]);
        }
    }

    #pragma unroll
    for (int b = 0; b < 4; b++) {
        #pragma unroll
        for (int off = 16; off > 0; off >>= 1)
            acc[b] += __shfl_xor_sync(0xffffffffu, acc[b], off);
    }
    if (lane == 0) {
        gate[w][0] = acc[0]; gate[w][1] = acc[1];
        gate[w][2] = acc[2]; gate[w][3] = acc[3];
    }
    __syncthreads();

    if (tid < 8) {
        int jj = tid >> 2, b = tid & 3;
        int jg = blockIdx.x * 2 + jj;
        float gi = gate[jj * 4 + 0][b] + bih[jg]           + bhh[jg];
        float gf = gate[jj * 4 + 1][b] + bih[HID + jg]     + bhh[HID + jg];
        float gg = gate[jj * 4 + 2][b] + bih[2 * HID + jg] + bhh[2 * HID + jg];
        float go = gate[jj * 4 + 3][b] + bih[3 * HID + jg] + bhh[3 * HID + jg];
        float si = 1.f / (1.f + expf(-gi));
        float sf = 1.f / (1.f + expf(-gf));
        float tg = tanhf(gg);
        float so = 1.f / (1.f + expf(-go));
        float c2 = sf * cprev[b * HID + jg] + si * tg;
        float h2 = so * tanhf(c2);
        hout[b * HID + jg] = h2;
        cout[b * HID + jg] = c2;
    }
}

// ---------------- output projection ----------------
__global__ void out_proj_kernel(const float* __restrict__ h,
                                const float* __restrict__ imgf,
                                const float* __restrict__ out_w,
                                const float* __restrict__ out_b,
                                float* __restrict__ out, int t) {
    const int wid  = threadIdx.x >> 5;
    const int lane = threadIdx.x & 31;
    if (wid >= BB * AA) return;
    const int b = wid / AA, a = wid % AA;
    const float* row = out_w + a * 576;
    float acc = 0.f;
    for (int k = lane; k < 576; k += 32) {
        float x = (k < HID) ? h[b * HID + k] : imgf[(b * TT + t) * 64 + (k - HID)];
        acc = fmaf(row[k], x, acc);
    }
    #pragma unroll
    for (int off = 16; off > 0; off >>= 1)
        acc += __shfl_xor_sync(0xffffffffu, acc, off);
    if (lane == 0) out[(b * TT + t) * AA + a] = acc + out_b[a];
}

// ---------------- host orchestration ----------------
extern "C" void kernel_launch(void* const* d_in, const int* in_sizes, int n_in,
                              void* d_out, int out_size) {
    (void)in_sizes; (void)n_in; (void)out_size;

    const float* im_m   = (const float*)d_in[0];
    const float* im_s   = (const float*)d_in[1];
    const float* states = (const float*)d_in[2];
    const float* cw[2][4] = {
        {(const float*)d_in[3],  (const float*)d_in[5],  (const float*)d_in[7],  (const float*)d_in[9]},
        {(const float*)d_in[11], (const float*)d_in[13], (const float*)d_in[15], (const float*)d_in[17]}};
    const float* cb[2][4] = {
        {(const float*)d_in[4],  (const float*)d_in[6],  (const float*)d_in[8],  (const float*)d_in[10]},
        {(const float*)d_in[12], (const float*)d_in[14], (const float*)d_in[16], (const float*)d_in[18]}};
    const float* wih0  = (const float*)d_in[19];
    const float* whh0  = (const float*)d_in[20];
    const float* bih0  = (const float*)d_in[21];
    const float* bhh0  = (const float*)d_in[22];
    const float* wih_r = (const float*)d_in[23];
    const float* whh_r = (const float*)d_in[24];
    const float* bih_r = (const float*)d_in[25];
    const float* bhh_r = (const float*)d_in[26];
    const float* out_w = (const float*)d_in[27];
    const float* out_b = (const float*)d_in[28];
    float* out = (float*)d_out;

    __half2 *bufA, *bufB, *wt;
    float *imgf, *h0, *h1, *c0, *c1;
    cudaGetSymbolAddress((void**)&bufA, g_bufA);
    cudaGetSymbolAddress((void**)&bufB, g_bufB);
    cudaGetSymbolAddress((void**)&imgf, g_img);
    cudaGetSymbolAddress((void**)&h0,   g_h0);
    cudaGetSymbolAddress((void**)&h1,   g_h1);
    cudaGetSymbolAddress((void**)&c0,   g_c0);
    cudaGetSymbolAddress((void**)&c1,   g_c1);
    cudaGetSymbolAddress((void**)&wt,   g_wt);

    const size_t szL2 = 144 * 64, szL3 = 288 * 128, szL4 = 576 * 16;
    const size_t camw = szL2 + szL3 + szL4;

    // smem: slab (8*plane words) + sB (36*strideB uint2)
    const int SMEM_L23 = (8 * 568) * 4 + 36 * 68 * 8;   // 18176 + 19584 = 37760 B
    const int SMEM_L4  = (8 * 824) * 4 + 36 * 20 * 8;   // 26368 + 5760  = 32128 B

    for (int cam = 0; cam < 2; cam++) {
        const float* src = cam ? im_s : im_m;
        __half2* wt2 = wt + cam * camw;
        __half2* wt3 = wt2 + szL2;
        __half2* wt4 = wt3 + szL3;

        // keep conv_mma (L2) as the 4th launch overall for ncu's capture slot
        conv3x3_relu_kernel<<<dim3(32, 4, NIMG), 128, 3 * 72 * 4>>>(src, cw[cam][0], cb[cam][0], bufA, 3, 32);
        wt_transform_kernel<<<(int)((szL2 + 255) / 256), 256>>>(cw[cam][1], wt2, 32,  64);
        wt_transform_kernel<<<(int)((szL3 + 255) / 256), 256>>>(cw[cam][2], wt3, 64,  128);

        // L2: Cin=32 -> Cout=64. MF=2, NF=8: CTA 256px x 64oc (2 rows)
        conv_mma_kernel<2, 8><<<dim3(64, 1, NIMG), 256, SMEM_L23>>>(bufA, wt2, cb[cam][1], bufB, 32, 64);

        wt_transform_kernel<<<(int)((szL4 + 255) / 256), 256>>>(cw[cam][3], wt4, 128, 16);

        // L3: Cin=64 -> Cout=128 (two 64-oc slices)
        conv_mma_kernel<2, 8><<<dim3(64, 2, NIMG), 256, SMEM_L23>>>(bufB, wt3, cb[cam][2], bufA, 64, 128);
        // L4: Cin=128 -> Cout=16. MF=4, NF=2: CTA 512px x 16oc (4 rows)
        conv_mma_kernel<4, 2><<<dim3(32, 1, NIMG), 256, SMEM_L4>>>(bufA, wt4, cb[cam][3], bufB, 128, 16);

        spatial_softmax_kernel<<<dim3(NCH / 2, NIMG), 256>>>(bufB, imgf, cam ? 32 : 0);
    }

    // ---- LSTM ----
    cudaMemsetAsync(h0, 0, (size_t)LL * BB * HID * sizeof(float));
    cudaMemsetAsync(c0, 0, (size_t)LL * BB * HID * sizeof(float));

    for (int t = 0; t < TT; t++) {
        float* hp = (t & 1) ? h1 : h0;
        float* hc = (t & 1) ? h0 : h1;
        float* cp = (t & 1) ? c1 : c0;
        float* cc = (t & 1) ? c0 : c1;
        for (int l = 0; l < LL; l++) {
            if (l == 0) {
                lstm_cell_kernel<SS><<<256, 256>>>(
                    states + t * SS, TT * SS, imgf + t * 64,
                    hp, cp, wih0, whh0, bih0, bhh0, hc, cc);
            } else {
                lstm_cell_kernel<HID><<<256, 256>>>(
                    hc + (size_t)(l - 1) * BB * HID, HID, imgf + t * 64,
                    hp + (size_t)l * BB * HID, cp + (size_t)l * BB * HID,
                    wih_r + (size_t)(l - 1) * 4 * HID * 576,
                    whh_r + (size_t)(l - 1) * 4 * HID * HID,
                    bih_r + (size_t)(l - 1) * 4 * HID,
                    bhh_r + (size_t)(l - 1) * 4 * HID,
                    hc + (size_t)l * BB * HID, cc + (size_t)l * BB * HID);
            }
        }
        out_proj_kernel<<<1, 768>>>(hc + (size_t)5 * BB * HID, imgf, out_w, out_b, out, t);
    }
}

// round 11
// speedup vs baseline: 4.2299x; 1.1255x over previous
#include <cuda_runtime.h>
#include <cuda_fp16.h>
#include <math.h>
#include <stdint.h>

#define IMG   128
#define NPIX  16384
#define NIMG  40
#define BB    4
#define TT    10
#define SS    6
#define AA    6
#define HID   512
#define LL    6
#define NCH   16
#define SROW2 136   // half2 elements per slab row (data at [4..131], halo [3],[132])

// ---------------- scratch ----------------
__device__ __half2 g_bufA[(size_t)NIMG * 64 * NPIX];
__device__ __half2 g_bufB[(size_t)NIMG * 32 * NPIX];
__device__ float   g_img [BB * TT * 64];
__device__ float   g_h0[LL * BB * HID];
__device__ float   g_h1[LL * BB * HID];
__device__ float   g_c0[LL * BB * HID];
__device__ float   g_c1[LL * BB * HID];
// paired-B half2 weights per cam: [c][icb][kk][oc][p]
__device__ __half2 g_wt[2 * (144 * 64 + 288 * 128 + 576 * 16)];
// grid barrier state (zero-initialized; cnt returns to 0 after each barrier)
__device__ unsigned g_bar_cnt;
__device__ unsigned g_bar_gen;

__device__ __forceinline__ void mma_f16(float* d,
                                        uint32_t a0, uint32_t a1, uint32_t a2, uint32_t a3,
                                        uint32_t b0, uint32_t b1) {
    asm volatile(
        "mma.sync.aligned.m16n8k16.row.col.f32.f16.f16.f32 "
        "{%0,%1,%2,%3}, {%4,%5,%6,%7}, {%8,%9}, {%0,%1,%2,%3};"
        : "+f"(d[0]), "+f"(d[1]), "+f"(d[2]), "+f"(d[3])
        : "r"(a0), "r"(a1), "r"(a2), "r"(a3), "r"(b0), "r"(b1));
}

// ================ weight transform: [oc][ic][3][3] -> paired-B layout ================
__global__ void wt_transform_kernel(const float* __restrict__ w, __half2* __restrict__ wt2,
                                    int Cin, int Cout) {
    int idx = blockIdx.x * 256 + threadIdx.x;
    int tot = (9 * Cin / 2) * Cout;
    if (idx >= tot) return;
    int nicb = Cin >> 4;
    int p  = idx & 1;
    int t  = idx >> 1;
    int oc = t % Cout;  t /= Cout;
    int kk = t & 3;     t >>= 2;
    int icb = t % nicb;
    int c   = t / nicb;
    int ic0 = icb * 16 + 2 * (kk + 4 * p);
    float w0 = w[(oc * Cin + ic0) * 9 + c];
    float w1 = w[(oc * Cin + ic0 + 1) * 9 + c];
    wt2[idx] = __floats2half2_rn(w0, w1);
}

// ================ fp16 mma.sync implicit-GEMM conv, cp.async double-buffered ================
template<int MF, int NF>
__global__ void __launch_bounds__(256)
conv_mma_kernel(const __half2* __restrict__ in, const __half2* __restrict__ wt2,
                const float* __restrict__ bias, __half2* __restrict__ out,
                int Cin, int Cout) {
    extern __shared__ __align__(16) uint32_t smu[];
    const int tid  = threadIdx.x;
    const int lane = tid & 31;
    const int wid  = tid >> 5;

    constexpr int rows   = MF;
    constexpr int slabR  = rows + 2;
    constexpr int plane0 = slabR * SROW2;
    constexpr int plane  = plane0 + ((24 - (plane0 & 31)) & 31);  // plane%32==24
    constexpr int slabW  = 8 * plane;          // words per slab buffer
    constexpr int ocT    = NF * 8;
    constexpr int strideB = ocT + 4;           // uint2 units, conflict-free
    constexpr int sBW    = 36 * strideB;       // uint2 per B buffer

    uint32_t* slabBuf[2] = { smu, smu + slabW };
    uint2*    sBbase     = reinterpret_cast<uint2*>(smu + 2 * slabW);

    const int n   = blockIdx.z;
    const int y0  = blockIdx.x * rows;
    const int oc0 = blockIdx.y * ocT;

    const int pxbase = wid * (MF * 16);
    const int kk = lane & 3;
    const int qr = lane >> 2;

    float d[MF][NF][4];
    #pragma unroll
    for (int mf = 0; mf < MF; mf++)
        #pragma unroll
        for (int j = 0; j < NF; j++)
            #pragma unroll
            for (int r = 0; r < 4; r++) d[mf][j][r] = 0.f;

    const int nicb = Cin >> 4;
    const int np   = Cin >> 1;

    // zero halo words in both slab buffers (staging never writes [3],[132])
    for (int i = tid; i < 2 * 8 * slabR; i += 256) {
        int b  = i / (8 * slabR);
        int r2 = i - b * 8 * slabR;
        int q = r2 / slabR, r = r2 - q * slabR;
        slabBuf[b][q * plane + r * SROW2 + 3]   = 0u;
        slabBuf[b][q * plane + r * SROW2 + 132] = 0u;
    }

    auto stage = [&](int icb, int buf) {
        uint32_t* sl = slabBuf[buf];
        constexpr int perp = slabR * 32;
        for (int i = tid; i < 8 * perp; i += 256) {
            int q   = i / perp;
            int rem = i - q * perp;
            int r   = rem >> 5;
            int x0  = (rem & 31) << 2;
            int y   = y0 + r - 1;
            bool v  = (y >= 0 && y < IMG);
            int yc  = v ? y : 0;
            const void* g = in + ((size_t)(n * np + icb * 8 + q)) * NPIX + yc * IMG + x0;
            uint32_t sa = (uint32_t)__cvta_generic_to_shared(sl + q * plane + r * SROW2 + 4 + x0);
            asm volatile("cp.async.cg.shared.global [%0], [%1], 16, %2;"
                         :: "r"(sa), "l"(g), "r"(v ? 16 : 0) : "memory");
        }
        uint2* sB = sBbase + buf * sBW;
        const uint2* gB = reinterpret_cast<const uint2*>(wt2) + (size_t)icb * 4 * Cout + oc0;
        const size_t gcs = (size_t)nicb * 4 * Cout;
        for (int i = tid; i < 36 * ocT; i += 256) {
            int c   = i / (4 * ocT);
            int r   = i - c * 4 * ocT;
            int kkr = r / ocT, oc = r - kkr * ocT;
            uint32_t sa = (uint32_t)__cvta_generic_to_shared(sB + (c * 4 + kkr) * strideB + oc);
            const void* g = gB + c * gcs + kkr * Cout + oc;
            asm volatile("cp.async.ca.shared.global [%0], [%1], 8;"
                         :: "r"(sa), "l"(g) : "memory");
        }
        asm volatile("cp.async.commit_group;" ::: "memory");
    };

    stage(0, 0);

    for (int icb = 0; icb < nicb; icb++) {
        const int buf = icb & 1;
        if (icb + 1 < nicb) {
            stage(icb + 1, buf ^ 1);
            asm volatile("cp.async.wait_group 1;" ::: "memory");
        } else {
            asm volatile("cp.async.wait_group 0;" ::: "memory");
        }
        __syncthreads();

        uint32_t* sl = slabBuf[buf];
        uint2*    sB = sBbase + buf * sBW;

        #pragma unroll
        for (int c = 0; c < 9; c++) {
            const int ky = c / 3, kx = c - (c / 3) * 3;

            uint2 bf[NF];
            #pragma unroll
            for (int j = 0; j < NF; j++)
                bf[j] = sB[(c * 4 + kk) * strideB + j * 8 + qr];

            #pragma unroll
            for (int mf = 0; mf < MF; mf++) {
                int px = pxbase + mf * 16 + qr;
                int pr = px >> 7, x = px & 127;
                int base = (pr + ky) * SROW2 + 3 + x + kx;
                uint32_t a0 = sl[kk * plane + base];
                uint32_t a1 = sl[kk * plane + base + 8];
                uint32_t a2 = sl[(kk + 4) * plane + base];
                uint32_t a3 = sl[(kk + 4) * plane + base + 8];
                #pragma unroll
                for (int j = 0; j < NF; j++)
                    mma_f16(d[mf][j], a0, a1, a2, a3, bf[j].x, bf[j].y);
            }
        }
        __syncthreads();
    }

    // ---- epilogue: bias + relu + half2 store ----
    #pragma unroll
    for (int j = 0; j < NF; j++) {
        int oc = oc0 + j * 8 + 2 * kk;
        float bv0 = bias[oc], bv1 = bias[oc + 1];
        #pragma unroll
        for (int mf = 0; mf < MF; mf++) {
            int px = pxbase + mf * 16 + qr;
            int pr = px >> 7, x = px & 127;
            __half2* o0 = out + ((size_t)(n * (Cout >> 1) + (oc >> 1))) * NPIX
                          + (y0 + pr) * IMG + x;
            o0[0] = __floats2half2_rn(fmaxf(d[mf][j][0] + bv0, 0.f),
                                      fmaxf(d[mf][j][1] + bv1, 0.f));
            o0[8] = __floats2half2_rn(fmaxf(d[mf][j][2] + bv0, 0.f),
                                      fmaxf(d[mf][j][3] + bv1, 0.f));
        }
    }
}

// ---------------- fp32 direct conv (layer 1, Cin=3) -> half2 output ----------------
__global__ void conv3x3_relu_kernel(const float* __restrict__ in,
                                    const float* __restrict__ w,
                                    const float* __restrict__ bias,
                                    __half2* __restrict__ out,
                                    int Cin, int Cout) {
    extern __shared__ float sw[];
    const int tid  = threadIdx.x;
    const int lane = tid & 31;
    const int warp = tid >> 5;
    const int ocg  = blockIdx.y;
    const int n    = blockIdx.z;

    const int nw = Cin * 72;
    const float* wbase = w + (size_t)ocg * 8 * Cin * 9;
    for (int i = tid; i < nw; i += blockDim.x) {
        int o = i & 7, rest = i >> 3;
        sw[i] = wbase[(size_t)o * Cin * 9 + rest];
    }
    __syncthreads();

    const int y  = blockIdx.x * 4 + warp;
    const int x0 = lane * 4;

    float acc[8][4];
    #pragma unroll
    for (int o = 0; o < 8; o++) {
        float bv = bias[ocg * 8 + o];
        #pragma unroll
        for (int p = 0; p < 4; p++) acc[o][p] = bv;
    }

    for (int ic = 0; ic < Cin; ic++) {
        const float* ip = in + (size_t)(n * Cin + ic) * NPIX;
        float v[3][6];
        #pragma unroll
        for (int r = 0; r < 3; r++) {
            int yy = y - 1 + r;
            float4 m = make_float4(0.f, 0.f, 0.f, 0.f);
            if (yy >= 0 && yy < IMG)
                m = *reinterpret_cast<const float4*>(ip + yy * IMG + x0);
            float left  = __shfl_up_sync(0xffffffffu, m.w, 1);
            float right = __shfl_down_sync(0xffffffffu, m.x, 1);
            if (lane == 0)  left  = 0.f;
            if (lane == 31) right = 0.f;
            v[r][0] = left; v[r][1] = m.x; v[r][2] = m.y;
            v[r][3] = m.z;  v[r][4] = m.w; v[r][5] = right;
        }
        const float* wp = sw + ic * 72;
        #pragma unroll
        for (int ky = 0; ky < 3; ky++)
        #pragma unroll
        for (int kx = 0; kx < 3; kx++) {
            const float* wq = wp + (ky * 3 + kx) * 8;
            #pragma unroll
            for (int o = 0; o < 8; o++) {
                float wv = wq[o];
                #pragma unroll
                for (int p = 0; p < 4; p++)
                    acc[o][p] = fmaf(v[ky][kx + p], wv, acc[o][p]);
            }
        }
    }

    #pragma unroll
    for (int o = 0; o < 8; o += 2) {
        __half2 h[4];
        #pragma unroll
        for (int p = 0; p < 4; p++)
            h[p] = __floats2half2_rn(fmaxf(acc[o][p], 0.f), fmaxf(acc[o + 1][p], 0.f));
        int pl = (ocg * 8 + o) >> 1;
        *reinterpret_cast<uint4*>(
            out + ((size_t)(n * (Cout >> 1) + pl)) * NPIX + y * IMG + x0) =
            *reinterpret_cast<uint4*>(h);
    }
}

// ---------------- spatial softmax: one block per half2 plane (2 channels) ----------------
__global__ void spatial_softmax_kernel(const __half2* __restrict__ x,
                                       float* __restrict__ img, int base) {
    const int pl = blockIdx.x;
    const int n  = blockIdx.y;
    const __half2* p = x + (size_t)(n * (NCH / 2) + pl) * NPIX;
    __shared__ float rA[256], rB[256], rC[256], rD[256], rE[256], rF[256];
    const int tid = threadIdx.x;

    float m0 = -1e30f, m1 = -1e30f;
    for (int i = tid; i < NPIX; i += 256) {
        __half2 v = p[i];
        m0 = fmaxf(m0, __low2float(v));
        m1 = fmaxf(m1, __high2float(v));
    }
    rA[tid] = m0; rB[tid] = m1; __syncthreads();
    for (int s = 128; s > 0; s >>= 1) {
        if (tid < s) {
            rA[tid] = fmaxf(rA[tid], rA[tid + s]);
            rB[tid] = fmaxf(rB[tid], rB[tid + s]);
        }
        __syncthreads();
    }
    m0 = rA[0]; m1 = rB[0];
    __syncthreads();

    float s0 = 0.f, sx0 = 0.f, sy0 = 0.f;
    float s1 = 0.f, sx1 = 0.f, sy1 = 0.f;
    for (int i = tid; i < NPIX; i += 256) {
        __half2 v = p[i];
        float e0 = __expf(__low2float(v)  - m0);
        float e1 = __expf(__high2float(v) - m1);
        int yy = i >> 7, xx = i & 127;
        float px = -1.f + (2.f / 127.f) * (float)xx;
        float py = -1.f + (2.f / 127.f) * (float)yy;
        s0 += e0; sx0 += e0 * px; sy0 += e0 * py;
        s1 += e1; sx1 += e1 * px; sy1 += e1 * py;
    }
    rA[tid] = s0; rB[tid] = sx0; rC[tid] = sy0;
    rD[tid] = s1; rE[tid] = sx1; rF[tid] = sy1;
    __syncthreads();
    for (int st = 128; st > 0; st >>= 1) {
        if (tid < st) {
            rA[tid] += rA[tid + st]; rB[tid] += rB[tid + st]; rC[tid] += rC[tid + st];
            rD[tid] += rD[tid + st]; rE[tid] += rE[tid + st]; rF[tid] += rF[tid + st];
        }
        __syncthreads();
    }
    if (tid == 0) {
        float inv0 = 1.f / rA[0];
        float inv1 = 1.f / rD[0];
        int ch0 = 2 * pl, ch1 = 2 * pl + 1;
        img[n * 64 + base + 2 * ch0]     = rB[0] * inv0;
        img[n * 64 + base + 2 * ch0 + 1] = rC[0] * inv0;
        img[n * 64 + base + 2 * ch1]     = rE[0] * inv1;
        img[n * 64 + base + 2 * ch1 + 1] = rF[0] * inv1;
    }
}

// ---------------- grid barrier (256 co-resident blocks) ----------------
__device__ __forceinline__ void grid_bar() {
    __syncthreads();
    if (threadIdx.x == 0) {
        __threadfence();
        unsigned gen = atomicAdd(&g_bar_gen, 0u);
        if (atomicAdd(&g_bar_cnt, 1u) == 255u) {
            g_bar_cnt = 0u;                 // safe: all blocks have arrived
            __threadfence();
            atomicAdd(&g_bar_gen, 1u);
        } else {
            while (atomicAdd(&g_bar_gen, 0u) == gen) __nanosleep(64);
        }
        __threadfence();
    }
    __syncthreads();
}

// ---------------- LSTM cell body (in persistent kernel) ----------------
template<int D1>
__device__ __forceinline__ void lstm_cell_body(
    const float* __restrict__ x1, int x1_bs,
    const float* __restrict__ x2,
    const float* __restrict__ hprev, const float* __restrict__ cprev,
    const float* __restrict__ wih, const float* __restrict__ whh,
    const float* __restrict__ bih, const float* __restrict__ bhh,
    float* __restrict__ hout, float* __restrict__ cout,
    float* sx, float* sh, float (*gate)[4])
{
    constexpr int D = D1 + 64;
    const int tid = threadIdx.x;

    for (int i = tid; i < BB * D; i += 256) {
        int b = i / D, k = i - b * D;
        sx[i] = (k < D1) ? x1[b * x1_bs + k] : x2[b * (TT * 64) + (k - D1)];
    }
    for (int i = tid; i < BB * HID; i += 256) sh[i] = hprev[i];
    __syncthreads();

    const int lane = tid & 31;
    const int w    = tid >> 5;
    const int jl   = w >> 2;
    const int g    = w & 3;
    const int j    = blockIdx.x * 2 + jl;

    float acc[4] = {0.f, 0.f, 0.f, 0.f};

    const float* wr = wih + (size_t)(g * HID + j) * D;
    if (D == 576) {
        #pragma unroll
        for (int kb = 0; kb < 4; kb++) {
            int k = lane * 4 + kb * 128;
            float4 wv = *reinterpret_cast<const float4*>(wr + k);
            #pragma unroll
            for (int b = 0; b < 4; b++) {
                float4 xv = *reinterpret_cast<const float4*>(sx + b * D + k);
                acc[b] = fmaf(wv.x, xv.x, acc[b]);
                acc[b] = fmaf(wv.y, xv.y, acc[b]);
                acc[b] = fmaf(wv.z, xv.z, acc[b]);
                acc[b] = fmaf(wv.w, xv.w, acc[b]);
            }
        }
        if (lane < 16) {
            int k = 512 + lane * 4;
            float4 wv = *reinterpret_cast<const float4*>(wr + k);
            #pragma unroll
            for (int b = 0; b < 4; b++) {
                float4 xv = *reinterpret_cast<const float4*>(sx + b * D + k);
                acc[b] = fmaf(wv.x, xv.x, acc[b]);
                acc[b] = fmaf(wv.y, xv.y, acc[b]);
                acc[b] = fmaf(wv.z, xv.z, acc[b]);
                acc[b] = fmaf(wv.w, xv.w, acc[b]);
            }
        }
    } else {
        #pragma unroll
        for (int kb = 0; kb < (D + 31) / 32; kb++) {
            int k = lane + kb * 32;
            if (k < D) {
                float wv = wr[k];
                #pragma unroll
                for (int b = 0; b < 4; b++)
                    acc[b] = fmaf(sx[b * D + k], wv, acc[b]);
            }
        }
    }

    const float* w2 = whh + (size_t)(g * HID + j) * HID;
    #pragma unroll
    for (int k4 = 0; k4 < 4; k4++) {
        int k = lane * 4 + k4 * 128;
        float4 wv = *reinterpret_cast<const float4*>(w2 + k);
        #pragma unroll
        for (int b = 0; b < 4; b++) {
            float4 hv = *reinterpret_cast<const float4*>(sh + b * HID + k);
            acc[b] = fmaf(wv.x, hv.x, acc[b]);
            acc[b] = fmaf(wv.y, hv.y, acc[b]);
            acc[b] = fmaf(wv.z, hv.z, acc[b]);
            acc[b] = fmaf(wv.w, hv.w, acc[b]);
        }
    }

    #pragma unroll
    for (int b = 0; b < 4; b++) {
        #pragma unroll
        for (int off = 16; off > 0; off >>= 1)
            acc[b] += __shfl_xor_sync(0xffffffffu, acc[b], off);
    }
    if (lane == 0) {
        gate[w][0] = acc[0]; gate[w][1] = acc[1];
        gate[w][2] = acc[2]; gate[w][3] = acc[3];
    }
    __syncthreads();

    if (tid < 8) {
        int jj = tid >> 2, b = tid & 3;
        int jg = blockIdx.x * 2 + jj;
        float gi = gate[jj * 4 + 0][b] + bih[jg]           + bhh[jg];
        float gf = gate[jj * 4 + 1][b] + bih[HID + jg]     + bhh[HID + jg];
        float gg = gate[jj * 4 + 2][b] + bih[2 * HID + jg] + bhh[2 * HID + jg];
        float go = gate[jj * 4 + 3][b] + bih[3 * HID + jg] + bhh[3 * HID + jg];
        float si = 1.f / (1.f + expf(-gi));
        float sf = 1.f / (1.f + expf(-gf));
        float tg = tanhf(gg);
        float so = 1.f / (1.f + expf(-go));
        float c2 = sf * cprev[b * HID + jg] + si * tg;
        float h2 = so * tanhf(c2);
        hout[b * HID + jg] = h2;
        cout[b * HID + jg] = c2;
    }
}

// ---------------- persistent LSTM: all 60 cells + 10 out_proj, one launch ----------------
__global__ void __launch_bounds__(256, 2)
lstm_persist_kernel(const float* __restrict__ states, const float* __restrict__ imgf,
                    const float* __restrict__ wih0, const float* __restrict__ whh0,
                    const float* __restrict__ bih0, const float* __restrict__ bhh0,
                    const float* __restrict__ wih_r, const float* __restrict__ whh_r,
                    const float* __restrict__ bih_r, const float* __restrict__ bhh_r,
                    const float* __restrict__ out_w, const float* __restrict__ out_b,
                    float* __restrict__ out,
                    float* __restrict__ h0, float* __restrict__ h1,
                    float* __restrict__ c0, float* __restrict__ c1)
{
    __shared__ __align__(16) float sx[BB * 576];
    __shared__ __align__(16) float sh[BB * HID];
    __shared__ float gate[8][4];

    // zero-init t=0 state (h0/c0); 12288 floats each / 256 blocks = 48 per block
    {
        int base = blockIdx.x * 48;
        for (int i = threadIdx.x; i < 48; i += 256) {
            h0[base + i] = 0.f;
            c0[base + i] = 0.f;
        }
    }
    grid_bar();

    for (int t = 0; t < TT; t++) {
        float* hp = (t & 1) ? h1 : h0;
        float* hc = (t & 1) ? h0 : h1;
        float* cp = (t & 1) ? c1 : c0;
        float* cc = (t & 1) ? c0 : c1;

        lstm_cell_body<SS>(states + t * SS, TT * SS, imgf + t * 64,
                           hp, cp, wih0, whh0, bih0, bhh0, hc, cc, sx, sh, gate);
        grid_bar();

        for (int l = 1; l < LL; l++) {
            lstm_cell_body<HID>(hc + (size_t)(l - 1) * BB * HID, HID, imgf + t * 64,
                                hp + (size_t)l * BB * HID, cp + (size_t)l * BB * HID,
                                wih_r + (size_t)(l - 1) * 4 * HID * 576,
                                whh_r + (size_t)(l - 1) * 4 * HID * HID,
                                bih_r + (size_t)(l - 1) * 4 * HID,
                                bhh_r + (size_t)(l - 1) * 4 * HID,
                                hc + (size_t)l * BB * HID, cc + (size_t)l * BB * HID,
                                sx, sh, gate);
            grid_bar();
        }

        // out_proj: blocks 0..23, warp 0; runs concurrently with next timestep's
        // early layers (reads hc[5], written this t; next write is t+2 layer5).
        if (blockIdx.x < BB * AA && threadIdx.x < 32) {
            const int b = blockIdx.x / AA, a = blockIdx.x % AA;
            const int lane = threadIdx.x;
            const float* row = out_w + a * 576;
            const float* h5  = hc + (size_t)5 * BB * HID;
            float acc = 0.f;
            for (int k = lane; k < 576; k += 32) {
                float xv = (k < HID) ? h5[b * HID + k]
                                     : imgf[b * (TT * 64) + t * 64 + (k - HID)];
                acc = fmaf(row[k], xv, acc);
            }
            #pragma unroll
            for (int off = 16; off > 0; off >>= 1)
                acc += __shfl_xor_sync(0xffffffffu, acc, off);
            if (lane == 0) out[(b * TT + t) * AA + a] = acc + out_b[a];
        }
    }
}

// ---------------- host orchestration ----------------
extern "C" void kernel_launch(void* const* d_in, const int* in_sizes, int n_in,
                              void* d_out, int out_size) {
    (void)in_sizes; (void)n_in; (void)out_size;

    const float* im_m   = (const float*)d_in[0];
    const float* im_s   = (const float*)d_in[1];
    const float* states = (const float*)d_in[2];
    const float* cw[2][4] = {
        {(const float*)d_in[3],  (const float*)d_in[5],  (const float*)d_in[7],  (const float*)d_in[9]},
        {(const float*)d_in[11], (const float*)d_in[13], (const float*)d_in[15], (const float*)d_in[17]}};
    const float* cb[2][4] = {
        {(const float*)d_in[4],  (const float*)d_in[6],  (const float*)d_in[8],  (const float*)d_in[10]},
        {(const float*)d_in[12], (const float*)d_in[14], (const float*)d_in[16], (const float*)d_in[18]}};
    const float* wih0  = (const float*)d_in[19];
    const float* whh0  = (const float*)d_in[20];
    const float* bih0  = (const float*)d_in[21];
    const float* bhh0  = (const float*)d_in[22];
    const float* wih_r = (const float*)d_in[23];
    const float* whh_r = (const float*)d_in[24];
    const float* bih_r = (const float*)d_in[25];
    const float* bhh_r = (const float*)d_in[26];
    const float* out_w = (const float*)d_in[27];
    const float* out_b = (const float*)d_in[28];
    float* out = (float*)d_out;

    __half2 *bufA, *bufB, *wt;
    float *imgf, *h0, *h1, *c0, *c1;
    cudaGetSymbolAddress((void**)&bufA, g_bufA);
    cudaGetSymbolAddress((void**)&bufB, g_bufB);
    cudaGetSymbolAddress((void**)&imgf, g_img);
    cudaGetSymbolAddress((void**)&h0,   g_h0);
    cudaGetSymbolAddress((void**)&h1,   g_h1);
    cudaGetSymbolAddress((void**)&c0,   g_c0);
    cudaGetSymbolAddress((void**)&c1,   g_c1);
    cudaGetSymbolAddress((void**)&wt,   g_wt);

    const size_t szL2 = 144 * 64, szL3 = 288 * 128, szL4 = 576 * 16;
    const size_t camw = szL2 + szL3 + szL4;

    // double-buffered smem: 2*slab + 2*sB
    const int SMEM_L23 = 2 * (8 * 568) * 4 + 2 * (36 * 68) * 8;  // 36352 + 39168 = 75520
    const int SMEM_L4  = 2 * (8 * 824) * 4 + 2 * (36 * 20) * 8;  // 52736 + 11520 = 64256

    cudaFuncSetAttribute(conv_mma_kernel<2, 8>,
                         cudaFuncAttributeMaxDynamicSharedMemorySize, SMEM_L23);
    cudaFuncSetAttribute(conv_mma_kernel<4, 2>,
                         cudaFuncAttributeMaxDynamicSharedMemorySize, SMEM_L4);

    for (int cam = 0; cam < 2; cam++) {
        const float* src = cam ? im_s : im_m;
        __half2* wt2 = wt + cam * camw;
        __half2* wt3 = wt2 + szL2;
        __half2* wt4 = wt3 + szL3;

        // keep conv_mma (L2) as the 4th kernel launch for ncu's capture slot
        conv3x3_relu_kernel<<<dim3(32, 4, NIMG), 128, 3 * 72 * 4>>>(src, cw[cam][0], cb[cam][0], bufA, 3, 32);
        wt_transform_kernel<<<(int)((szL2 + 255) / 256), 256>>>(cw[cam][1], wt2, 32,  64);
        wt_transform_kernel<<<(int)((szL3 + 255) / 256), 256>>>(cw[cam][2], wt3, 64,  128);

        conv_mma_kernel<2, 8><<<dim3(64, 1, NIMG), 256, SMEM_L23>>>(bufA, wt2, cb[cam][1], bufB, 32, 64);

        wt_transform_kernel<<<(int)((szL4 + 255) / 256), 256>>>(cw[cam][3], wt4, 128, 16);

        conv_mma_kernel<2, 8><<<dim3(64, 2, NIMG), 256, SMEM_L23>>>(bufB, wt3, cb[cam][2], bufA, 64, 128);
        conv_mma_kernel<4, 2><<<dim3(32, 1, NIMG), 256, SMEM_L4>>>(bufA, wt4, cb[cam][3], bufB, 128, 16);

        spatial_softmax_kernel<<<dim3(NCH / 2, NIMG), 256>>>(bufB, imgf, cam ? 32 : 0);
    }

    // ---- LSTM: one persistent launch (256 blocks, all co-resident) ----
    lstm_persist_kernel<<<256, 256>>>(
        states, imgf,
        wih0, whh0, bih0, bhh0,
        wih_r, whh_r, bih_r, bhh_r,
        out_w, out_b, out,
        h0, h1, c0, c1);
}

// round 12
// speedup vs baseline: 4.6411x; 1.0972x over previous
#include <cuda_runtime.h>
#include <cuda_fp16.h>
#include <math.h>
#include <stdint.h>

#define IMG   128
#define NPIX  16384
#define NIMG  40
#define BB    4
#define TT    10
#define SS    6
#define AA    6
#define HID   512
#define LL    6
#define NCH   16
#define SROW2 136   // half2 elements per slab row (data at [4..131], halo [3],[132])

// ---------------- scratch ----------------
__device__ __half2 g_bufA[(size_t)NIMG * 64 * NPIX];
__device__ __half2 g_bufB[(size_t)NIMG * 32 * NPIX];
__device__ float   g_img [BB * TT * 64];
__device__ float   g_h0[LL * BB * HID];
__device__ float   g_h1[LL * BB * HID];
__device__ float   g_c0[LL * BB * HID];
__device__ float   g_c1[LL * BB * HID];
// paired-B half2 weights per cam: [c][icb][kk][oc][p]
__device__ __half2 g_wt[2 * (144 * 64 + 288 * 128 + 576 * 16)];
// grid barrier state (zero-initialized; cnt returns to 0 after each barrier)
__device__ unsigned g_bar_cnt;
__device__ unsigned g_bar_gen;

__device__ __forceinline__ void mma_f16(float* d,
                                        uint32_t a0, uint32_t a1, uint32_t a2, uint32_t a3,
                                        uint32_t b0, uint32_t b1) {
    asm volatile(
        "mma.sync.aligned.m16n8k16.row.col.f32.f16.f16.f32 "
        "{%0,%1,%2,%3}, {%4,%5,%6,%7}, {%8,%9}, {%0,%1,%2,%3};"
        : "+f"(d[0]), "+f"(d[1]), "+f"(d[2]), "+f"(d[3])
        : "r"(a0), "r"(a1), "r"(a2), "r"(a3), "r"(b0), "r"(b1));
}

// ================ weight transform: [oc][ic][3][3] -> paired-B layout ================
__global__ void wt_transform_kernel(const float* __restrict__ w, __half2* __restrict__ wt2,
                                    int Cin, int Cout) {
    int idx = blockIdx.x * 256 + threadIdx.x;
    int tot = (9 * Cin / 2) * Cout;
    if (idx >= tot) return;
    int nicb = Cin >> 4;
    int p  = idx & 1;
    int t  = idx >> 1;
    int oc = t % Cout;  t /= Cout;
    int kk = t & 3;     t >>= 2;
    int icb = t % nicb;
    int c   = t / nicb;
    int ic0 = icb * 16 + 2 * (kk + 4 * p);
    float w0 = w[(oc * Cin + ic0) * 9 + c];
    float w1 = w[(oc * Cin + ic0 + 1) * 9 + c];
    wt2[idx] = __floats2half2_rn(w0, w1);
}

// ================ fp16 mma.sync implicit-GEMM conv, cp.async double-buffered ================
// __launch_bounds__(256, 2): cap regs at 128 so 2 CTAs/SM co-reside (regfile 2*128*256 = 64K).
template<int MF, int NF>
__global__ void __launch_bounds__(256, 2)
conv_mma_kernel(const __half2* __restrict__ in, const __half2* __restrict__ wt2,
                const float* __restrict__ bias, __half2* __restrict__ out,
                int Cin, int Cout) {
    extern __shared__ __align__(16) uint32_t smu[];
    const int tid  = threadIdx.x;
    const int lane = tid & 31;
    const int wid  = tid >> 5;

    constexpr int rows   = MF;
    constexpr int slabR  = rows + 2;
    constexpr int plane0 = slabR * SROW2;
    constexpr int plane  = plane0 + ((24 - (plane0 & 31)) & 31);  // plane%32==24
    constexpr int slabW  = 8 * plane;          // words per slab buffer
    constexpr int ocT    = NF * 8;
    constexpr int strideB = ocT + 4;           // uint2 units, conflict-free
    constexpr int sBW    = 36 * strideB;       // uint2 per B buffer

    uint32_t* slabBuf[2] = { smu, smu + slabW };
    uint2*    sBbase     = reinterpret_cast<uint2*>(smu + 2 * slabW);

    const int n   = blockIdx.z;
    const int y0  = blockIdx.x * rows;
    const int oc0 = blockIdx.y * ocT;

    const int pxbase = wid * (MF * 16);
    const int kk = lane & 3;
    const int qr = lane >> 2;

    float d[MF][NF][4];
    #pragma unroll
    for (int mf = 0; mf < MF; mf++)
        #pragma unroll
        for (int j = 0; j < NF; j++)
            #pragma unroll
            for (int r = 0; r < 4; r++) d[mf][j][r] = 0.f;

    const int nicb = Cin >> 4;
    const int np   = Cin >> 1;

    // zero halo words in both slab buffers (staging never writes [3],[132])
    for (int i = tid; i < 2 * 8 * slabR; i += 256) {
        int b  = i / (8 * slabR);
        int r2 = i - b * 8 * slabR;
        int q = r2 / slabR, r = r2 - q * slabR;
        slabBuf[b][q * plane + r * SROW2 + 3]   = 0u;
        slabBuf[b][q * plane + r * SROW2 + 132] = 0u;
    }

    auto stage = [&](int icb, int buf) {
        uint32_t* sl = slabBuf[buf];
        constexpr int perp = slabR * 32;
        for (int i = tid; i < 8 * perp; i += 256) {
            int q   = i / perp;
            int rem = i - q * perp;
            int r   = rem >> 5;
            int x0  = (rem & 31) << 2;
            int y   = y0 + r - 1;
            bool v  = (y >= 0 && y < IMG);
            int yc  = v ? y : 0;
            const void* g = in + ((size_t)(n * np + icb * 8 + q)) * NPIX + yc * IMG + x0;
            uint32_t sa = (uint32_t)__cvta_generic_to_shared(sl + q * plane + r * SROW2 + 4 + x0);
            asm volatile("cp.async.cg.shared.global [%0], [%1], 16, %2;"
                         :: "r"(sa), "l"(g), "r"(v ? 16 : 0) : "memory");
        }
        uint2* sB = sBbase + buf * sBW;
        const uint2* gB = reinterpret_cast<const uint2*>(wt2) + (size_t)icb * 4 * Cout + oc0;
        const size_t gcs = (size_t)nicb * 4 * Cout;
        for (int i = tid; i < 36 * ocT; i += 256) {
            int c   = i / (4 * ocT);
            int r   = i - c * 4 * ocT;
            int kkr = r / ocT, oc = r - kkr * ocT;
            uint32_t sa = (uint32_t)__cvta_generic_to_shared(sB + (c * 4 + kkr) * strideB + oc);
            const void* g = gB + c * gcs + kkr * Cout + oc;
            asm volatile("cp.async.ca.shared.global [%0], [%1], 8;"
                         :: "r"(sa), "l"(g) : "memory");
        }
        asm volatile("cp.async.commit_group;" ::: "memory");
    };

    stage(0, 0);

    for (int icb = 0; icb < nicb; icb++) {
        const int buf = icb & 1;
        if (icb + 1 < nicb) {
            stage(icb + 1, buf ^ 1);
            asm volatile("cp.async.wait_group 1;" ::: "memory");
        } else {
            asm volatile("cp.async.wait_group 0;" ::: "memory");
        }
        __syncthreads();

        uint32_t* sl = slabBuf[buf];
        uint2*    sB = sBbase + buf * sBW;

        #pragma unroll
        for (int c = 0; c < 9; c++) {
            const int ky = c / 3, kx = c - (c / 3) * 3;

            // B fragments first: 8 independent LDS.64 issue back-to-back
            uint2 bf[NF];
            #pragma unroll
            for (int j = 0; j < NF; j++)
                bf[j] = sB[(c * 4 + kk) * strideB + j * 8 + qr];

            #pragma unroll
            for (int mf = 0; mf < MF; mf++) {
                int px = pxbase + mf * 16 + qr;
                int pr = px >> 7, x = px & 127;
                int base = (pr + ky) * SROW2 + 3 + x + kx;
                uint32_t a0 = sl[kk * plane + base];
                uint32_t a1 = sl[kk * plane + base + 8];
                uint32_t a2 = sl[(kk + 4) * plane + base];
                uint32_t a3 = sl[(kk + 4) * plane + base + 8];
                #pragma unroll
                for (int j = 0; j < NF; j++)
                    mma_f16(d[mf][j], a0, a1, a2, a3, bf[j].x, bf[j].y);
            }
        }
        __syncthreads();
    }

    // ---- epilogue: bias + relu + half2 store ----
    #pragma unroll
    for (int j = 0; j < NF; j++) {
        int oc = oc0 + j * 8 + 2 * kk;
        float bv0 = bias[oc], bv1 = bias[oc + 1];
        #pragma unroll
        for (int mf = 0; mf < MF; mf++) {
            int px = pxbase + mf * 16 + qr;
            int pr = px >> 7, x = px & 127;
            __half2* o0 = out + ((size_t)(n * (Cout >> 1) + (oc >> 1))) * NPIX
                          + (y0 + pr) * IMG + x;
            o0[0] = __floats2half2_rn(fmaxf(d[mf][j][0] + bv0, 0.f),
                                      fmaxf(d[mf][j][1] + bv1, 0.f));
            o0[8] = __floats2half2_rn(fmaxf(d[mf][j][2] + bv0, 0.f),
                                      fmaxf(d[mf][j][3] + bv1, 0.f));
        }
    }
}

// ---------------- fp32 direct conv (layer 1, Cin=3) -> half2 output ----------------
__global__ void conv3x3_relu_kernel(const float* __restrict__ in,
                                    const float* __restrict__ w,
                                    const float* __restrict__ bias,
                                    __half2* __restrict__ out,
                                    int Cin, int Cout) {
    extern __shared__ float sw[];
    const int tid  = threadIdx.x;
    const int lane = tid & 31;
    const int warp = tid >> 5;
    const int ocg  = blockIdx.y;
    const int n    = blockIdx.z;

    const int nw = Cin * 72;
    const float* wbase = w + (size_t)ocg * 8 * Cin * 9;
    for (int i = tid; i < nw; i += blockDim.x) {
        int o = i & 7, rest = i >> 3;
        sw[i] = wbase[(size_t)o * Cin * 9 + rest];
    }
    __syncthreads();

    const int y  = blockIdx.x * 4 + warp;
    const int x0 = lane * 4;

    float acc[8][4];
    #pragma unroll
    for (int o = 0; o < 8; o++) {
        float bv = bias[ocg * 8 + o];
        #pragma unroll
        for (int p = 0; p < 4; p++) acc[o][p] = bv;
    }

    for (int ic = 0; ic < Cin; ic++) {
        const float* ip = in + (size_t)(n * Cin + ic) * NPIX;
        float v[3][6];
        #pragma unroll
        for (int r = 0; r < 3; r++) {
            int yy = y - 1 + r;
            float4 m = make_float4(0.f, 0.f, 0.f, 0.f);
            if (yy >= 0 && yy < IMG)
                m = *reinterpret_cast<const float4*>(ip + yy * IMG + x0);
            float left  = __shfl_up_sync(0xffffffffu, m.w, 1);
            float right = __shfl_down_sync(0xffffffffu, m.x, 1);
            if (lane == 0)  left  = 0.f;
            if (lane == 31) right = 0.f;
            v[r][0] = left; v[r][1] = m.x; v[r][2] = m.y;
            v[r][3] = m.z;  v[r][4] = m.w; v[r][5] = right;
        }
        const float* wp = sw + ic * 72;
        #pragma unroll
        for (int ky = 0; ky < 3; ky++)
        #pragma unroll
        for (int kx = 0; kx < 3; kx++) {
            const float* wq = wp + (ky * 3 + kx) * 8;
            #pragma unroll
            for (int o = 0; o < 8; o++) {
                float wv = wq[o];
                #pragma unroll
                for (int p = 0; p < 4; p++)
                    acc[o][p] = fmaf(v[ky][kx + p], wv, acc[o][p]);
            }
        }
    }

    #pragma unroll
    for (int o = 0; o < 8; o += 2) {
        __half2 h[4];
        #pragma unroll
        for (int p = 0; p < 4; p++)
            h[p] = __floats2half2_rn(fmaxf(acc[o][p], 0.f), fmaxf(acc[o + 1][p], 0.f));
        int pl = (ocg * 8 + o) >> 1;
        *reinterpret_cast<uint4*>(
            out + ((size_t)(n * (Cout >> 1) + pl)) * NPIX + y * IMG + x0) =
            *reinterpret_cast<uint4*>(h);
    }
}

// ---------------- spatial softmax: one block per half2 plane (2 channels) ----------------
__global__ void spatial_softmax_kernel(const __half2* __restrict__ x,
                                       float* __restrict__ img, int base) {
    const int pl = blockIdx.x;
    const int n  = blockIdx.y;
    const __half2* p = x + (size_t)(n * (NCH / 2) + pl) * NPIX;
    __shared__ float rA[256], rB[256], rC[256], rD[256], rE[256], rF[256];
    const int tid = threadIdx.x;

    float m0 = -1e30f, m1 = -1e30f;
    for (int i = tid; i < NPIX; i += 256) {
        __half2 v = p[i];
        m0 = fmaxf(m0, __low2float(v));
        m1 = fmaxf(m1, __high2float(v));
    }
    rA[tid] = m0; rB[tid] = m1; __syncthreads();
    for (int s = 128; s > 0; s >>= 1) {
        if (tid < s) {
            rA[tid] = fmaxf(rA[tid], rA[tid + s]);
            rB[tid] = fmaxf(rB[tid], rB[tid + s]);
        }
        __syncthreads();
    }
    m0 = rA[0]; m1 = rB[0];
    __syncthreads();

    float s0 = 0.f, sx0 = 0.f, sy0 = 0.f;
    float s1 = 0.f, sx1 = 0.f, sy1 = 0.f;
    for (int i = tid; i < NPIX; i += 256) {
        __half2 v = p[i];
        float e0 = __expf(__low2float(v)  - m0);
        float e1 = __expf(__high2float(v) - m1);
        int yy = i >> 7, xx = i & 127;
        float px = -1.f + (2.f / 127.f) * (float)xx;
        float py = -1.f + (2.f / 127.f) * (float)yy;
        s0 += e0; sx0 += e0 * px; sy0 += e0 * py;
        s1 += e1; sx1 += e1 * px; sy1 += e1 * py;
    }
    rA[tid] = s0; rB[tid] = sx0; rC[tid] = sy0;
    rD[tid] = s1; rE[tid] = sx1; rF[tid] = sy1;
    __syncthreads();
    for (int st = 128; st > 0; st >>= 1) {
        if (tid < st) {
            rA[tid] += rA[tid + st]; rB[tid] += rB[tid + st]; rC[tid] += rC[tid + st];
            rD[tid] += rD[tid + st]; rE[tid] += rE[tid + st]; rF[tid] += rF[tid + st];
        }
        __syncthreads();
    }
    if (tid == 0) {
        float inv0 = 1.f / rA[0];
        float inv1 = 1.f / rD[0];
        int ch0 = 2 * pl, ch1 = 2 * pl + 1;
        img[n * 64 + base + 2 * ch0]     = rB[0] * inv0;
        img[n * 64 + base + 2 * ch0 + 1] = rC[0] * inv0;
        img[n * 64 + base + 2 * ch1]     = rE[0] * inv1;
        img[n * 64 + base + 2 * ch1 + 1] = rF[0] * inv1;
    }
}

// ---------------- grid barrier (256 co-resident blocks) ----------------
__device__ __forceinline__ void grid_bar() {
    __syncthreads();
    if (threadIdx.x == 0) {
        __threadfence();
        unsigned gen = atomicAdd(&g_bar_gen, 0u);
        if (atomicAdd(&g_bar_cnt, 1u) == 255u) {
            g_bar_cnt = 0u;                 // safe: all blocks have arrived
            __threadfence();
            atomicAdd(&g_bar_gen, 1u);
        } else {
            while (atomicAdd(&g_bar_gen, 0u) == gen) __nanosleep(64);
        }
        __threadfence();
    }
    __syncthreads();
}

// ---------------- LSTM cell body (in persistent kernel) ----------------
template<int D1>
__device__ __forceinline__ void lstm_cell_body(
    const float* __restrict__ x1, int x1_bs,
    const float* __restrict__ x2,
    const float* __restrict__ hprev, const float* __restrict__ cprev,
    const float* __restrict__ wih, const float* __restrict__ whh,
    const float* __restrict__ bih, const float* __restrict__ bhh,
    float* __restrict__ hout, float* __restrict__ cout,
    float* sx, float* sh, float (*gate)[4])
{
    constexpr int D = D1 + 64;
    const int tid = threadIdx.x;

    for (int i = tid; i < BB * D; i += 256) {
        int b = i / D, k = i - b * D;
        sx[i] = (k < D1) ? x1[b * x1_bs + k] : x2[b * (TT * 64) + (k - D1)];
    }
    for (int i = tid; i < BB * HID; i += 256) sh[i] = hprev[i];
    __syncthreads();

    const int lane = tid & 31;
    const int w    = tid >> 5;
    const int jl   = w >> 2;
    const int g    = w & 3;
    const int j    = blockIdx.x * 2 + jl;

    float acc[4] = {0.f, 0.f, 0.f, 0.f};

    const float* wr = wih + (size_t)(g * HID + j) * D;
    if (D == 576) {
        #pragma unroll
        for (int kb = 0; kb < 4; kb++) {
            int k = lane * 4 + kb * 128;
            float4 wv = *reinterpret_cast<const float4*>(wr + k);
            #pragma unroll
            for (int b = 0; b < 4; b++) {
                float4 xv = *reinterpret_cast<const float4*>(sx + b * D + k);
                acc[b] = fmaf(wv.x, xv.x, acc[b]);
                acc[b] = fmaf(wv.y, xv.y, acc[b]);
                acc[b] = fmaf(wv.z, xv.z, acc[b]);
                acc[b] = fmaf(wv.w, xv.w, acc[b]);
            }
        }
        if (lane < 16) {
            int k = 512 + lane * 4;
            float4 wv = *reinterpret_cast<const float4*>(wr + k);
            #pragma unroll
            for (int b = 0; b < 4; b++) {
                float4 xv = *reinterpret_cast<const float4*>(sx + b * D + k);
                acc[b] = fmaf(wv.x, xv.x, acc[b]);
                acc[b] = fmaf(wv.y, xv.y, acc[b]);
                acc[b] = fmaf(wv.z, xv.z, acc[b]);
                acc[b] = fmaf(wv.w, xv.w, acc[b]);
            }
        }
    } else {
        #pragma unroll
        for (int kb = 0; kb < (D + 31) / 32; kb++) {
            int k = lane + kb * 32;
            if (k < D) {
                float wv = wr[k];
                #pragma unroll
                for (int b = 0; b < 4; b++)
                    acc[b] = fmaf(sx[b * D + k], wv, acc[b]);
            }
        }
    }

    const float* w2 = whh + (size_t)(g * HID + j) * HID;
    #pragma unroll
    for (int k4 = 0; k4 < 4; k4++) {
        int k = lane * 4 + k4 * 128;
        float4 wv = *reinterpret_cast<const float4*>(w2 + k);
        #pragma unroll
        for (int b = 0; b < 4; b++) {
            float4 hv = *reinterpret_cast<const float4*>(sh + b * HID + k);
            acc[b] = fmaf(wv.x, hv.x, acc[b]);
            acc[b] = fmaf(wv.y, hv.y, acc[b]);
            acc[b] = fmaf(wv.z, hv.z, acc[b]);
            acc[b] = fmaf(wv.w, hv.w, acc[b]);
        }
    }

    #pragma unroll
    for (int b = 0; b < 4; b++) {
        #pragma unroll
        for (int off = 16; off > 0; off >>= 1)
            acc[b] += __shfl_xor_sync(0xffffffffu, acc[b], off);
    }
    if (lane == 0) {
        gate[w][0] = acc[0]; gate[w][1] = acc[1];
        gate[w][2] = acc[2]; gate[w][3] = acc[3];
    }
    __syncthreads();

    if (tid < 8) {
        int jj = tid >> 2, b = tid & 3;
        int jg = blockIdx.x * 2 + jj;
        float gi = gate[jj * 4 + 0][b] + bih[jg]           + bhh[jg];
        float gf = gate[jj * 4 + 1][b] + bih[HID + jg]     + bhh[HID + jg];
        float gg = gate[jj * 4 + 2][b] + bih[2 * HID + jg] + bhh[2 * HID + jg];
        float go = gate[jj * 4 + 3][b] + bih[3 * HID + jg] + bhh[3 * HID + jg];
        float si = 1.f / (1.f + expf(-gi));
        float sf = 1.f / (1.f + expf(-gf));
        float tg = tanhf(gg);
        float so = 1.f / (1.f + expf(-go));
        float c2 = sf * cprev[b * HID + jg] + si * tg;
        float h2 = so * tanhf(c2);
        hout[b * HID + jg] = h2;
        cout[b * HID + jg] = c2;
    }
}

// ---------------- persistent LSTM: all 60 cells + 10 out_proj, one launch ----------------
__global__ void __launch_bounds__(256, 2)
lstm_persist_kernel(const float* __restrict__ states, const float* __restrict__ imgf,
                    const float* __restrict__ wih0, const float* __restrict__ whh0,
                    const float* __restrict__ bih0, const float* __restrict__ bhh0,
                    const float* __restrict__ wih_r, const float* __restrict__ whh_r,
                    const float* __restrict__ bih_r, const float* __restrict__ bhh_r,
                    const float* __restrict__ out_w, const float* __restrict__ out_b,
                    float* __restrict__ out,
                    float* __restrict__ h0, float* __restrict__ h1,
                    float* __restrict__ c0, float* __restrict__ c1)
{
    __shared__ __align__(16) float sx[BB * 576];
    __shared__ __align__(16) float sh[BB * HID];
    __shared__ float gate[8][4];

    // zero-init t=0 state (h0/c0); 12288 floats each / 256 blocks = 48 per block
    {
        int base = blockIdx.x * 48;
        for (int i = threadIdx.x; i < 48; i += 256) {
            h0[base + i] = 0.f;
            c0[base + i] = 0.f;
        }
    }
    grid_bar();

    for (int t = 0; t < TT; t++) {
        float* hp = (t & 1) ? h1 : h0;
        float* hc = (t & 1) ? h0 : h1;
        float* cp = (t & 1) ? c1 : c0;
        float* cc = (t & 1) ? c0 : c1;

        lstm_cell_body<SS>(states + t * SS, TT * SS, imgf + t * 64,
                           hp, cp, wih0, whh0, bih0, bhh0, hc, cc, sx, sh, gate);
        grid_bar();

        for (int l = 1; l < LL; l++) {
            lstm_cell_body<HID>(hc + (size_t)(l - 1) * BB * HID, HID, imgf + t * 64,
                                hp + (size_t)l * BB * HID, cp + (size_t)l * BB * HID,
                                wih_r + (size_t)(l - 1) * 4 * HID * 576,
                                whh_r + (size_t)(l - 1) * 4 * HID * HID,
                                bih_r + (size_t)(l - 1) * 4 * HID,
                                bhh_r + (size_t)(l - 1) * 4 * HID,
                                hc + (size_t)l * BB * HID, cc + (size_t)l * BB * HID,
                                sx, sh, gate);
            grid_bar();
        }

        // out_proj: blocks 0..23, warp 0; runs concurrently with next timestep's
        // early layers (reads hc[5], written this t; next write is t+2 layer5).
        if (blockIdx.x < BB * AA && threadIdx.x < 32) {
            const int b = blockIdx.x / AA, a = blockIdx.x % AA;
            const int lane = threadIdx.x;
            const float* row = out_w + a * 576;
            const float* h5  = hc + (size_t)5 * BB * HID;
            float acc = 0.f;
            for (int k = lane; k < 576; k += 32) {
                float xv = (k < HID) ? h5[b * HID + k]
                                     : imgf[b * (TT * 64) + t * 64 + (k - HID)];
                acc = fmaf(row[k], xv, acc);
            }
            #pragma unroll
            for (int off = 16; off > 0; off >>= 1)
                acc += __shfl_xor_sync(0xffffffffu, acc, off);
            if (lane == 0) out[(b * TT + t) * AA + a] = acc + out_b[a];
        }
    }
}

// ---------------- host orchestration ----------------
extern "C" void kernel_launch(void* const* d_in, const int* in_sizes, int n_in,
                              void* d_out, int out_size) {
    (void)in_sizes; (void)n_in; (void)out_size;

    const float* im_m   = (const float*)d_in[0];
    const float* im_s   = (const float*)d_in[1];
    const float* states = (const float*)d_in[2];
    const float* cw[2][4] = {
        {(const float*)d_in[3],  (const float*)d_in[5],  (const float*)d_in[7],  (const float*)d_in[9]},
        {(const float*)d_in[11], (const float*)d_in[13], (const float*)d_in[15], (const float*)d_in[17]}};
    const float* cb[2][4] = {
        {(const float*)d_in[4],  (const float*)d_in[6],  (const float*)d_in[8],  (const float*)d_in[10]},
        {(const float*)d_in[12], (const float*)d_in[14], (const float*)d_in[16], (const float*)d_in[18]}};
    const float* wih0  = (const float*)d_in[19];
    const float* whh0  = (const float*)d_in[20];
    const float* bih0  = (const float*)d_in[21];
    const float* bhh0  = (const float*)d_in[22];
    const float* wih_r = (const float*)d_in[23];
    const float* whh_r = (const float*)d_in[24];
    const float* bih_r = (const float*)d_in[25];
    const float* bhh_r = (const float*)d_in[26];
    const float* out_w = (const float*)d_in[27];
    const float* out_b = (const float*)d_in[28];
    float* out = (float*)d_out;

    __half2 *bufA, *bufB, *wt;
    float *imgf, *h0, *h1, *c0, *c1;
    cudaGetSymbolAddress((void**)&bufA, g_bufA);
    cudaGetSymbolAddress((void**)&bufB, g_bufB);
    cudaGetSymbolAddress((void**)&imgf, g_img);
    cudaGetSymbolAddress((void**)&h0,   g_h0);
    cudaGetSymbolAddress((void**)&h1,   g_h1);
    cudaGetSymbolAddress((void**)&c0,   g_c0);
    cudaGetSymbolAddress((void**)&c1,   g_c1);
    cudaGetSymbolAddress((void**)&wt,   g_wt);

    const size_t szL2 = 144 * 64, szL3 = 288 * 128, szL4 = 576 * 16;
    const size_t camw = szL2 + szL3 + szL4;

    // double-buffered smem: 2*slab + 2*sB
    const int SMEM_L23 = 2 * (8 * 568) * 4 + 2 * (36 * 68) * 8;  // 36352 + 39168 = 75520
    const int SMEM_L4  = 2 * (8 * 824) * 4 + 2 * (36 * 20) * 8;  // 52736 + 11520 = 64256

    cudaFuncSetAttribute(conv_mma_kernel<2, 8>,
                         cudaFuncAttributeMaxDynamicSharedMemorySize, SMEM_L23);
    cudaFuncSetAttribute(conv_mma_kernel<4, 2>,
                         cudaFuncAttributeMaxDynamicSharedMemorySize, SMEM_L4);

    for (int cam = 0; cam < 2; cam++) {
        const float* src = cam ? im_s : im_m;
        __half2* wt2 = wt + cam * camw;
        __half2* wt3 = wt2 + szL2;
        __half2* wt4 = wt3 + szL3;

        // keep conv_mma (L2) as the 4th kernel launch for ncu's capture slot
        conv3x3_relu_kernel<<<dim3(32, 4, NIMG), 128, 3 * 72 * 4>>>(src, cw[cam][0], cb[cam][0], bufA, 3, 32);
        wt_transform_kernel<<<(int)((szL2 + 255) / 256), 256>>>(cw[cam][1], wt2, 32,  64);
        wt_transform_kernel<<<(int)((szL3 + 255) / 256), 256>>>(cw[cam][2], wt3, 64,  128);

        conv_mma_kernel<2, 8><<<dim3(64, 1, NIMG), 256, SMEM_L23>>>(bufA, wt2, cb[cam][1], bufB, 32, 64);

        wt_transform_kernel<<<(int)((szL4 + 255) / 256), 256>>>(cw[cam][3], wt4, 128, 16);

        conv_mma_kernel<2, 8><<<dim3(64, 2, NIMG), 256, SMEM_L23>>>(bufB, wt3, cb[cam][2], bufA, 64, 128);
        conv_mma_kernel<4, 2><<<dim3(32, 1, NIMG), 256, SMEM_L4>>>(bufA, wt4, cb[cam][3], bufB, 128, 16);

        spatial_softmax_kernel<<<dim3(NCH / 2, NIMG), 256>>>(bufB, imgf, cam ? 32 : 0);
    }

    // ---- LSTM: one persistent launch (256 blocks, all co-resident) ----
    lstm_persist_kernel<<<256, 256>>>(
        states, imgf,
        wih0, whh0, bih0, bhh0,
        wih_r, whh_r, bih_r, bhh_r,
        out_w, out_b, out,
        h0, h1, c0, c1);
}